// round 2
// baseline (speedup 1.0000x reference)
#include <cuda_runtime.h>
#include <math.h>

#define CN0 30000
#define CN1 90000
#define CN2 60000
#define D_IN 256
#define D_OUT 128
#define HEADS 4
#define NNZ0 960000
#define NNZ1 180000
#define NNZ2 180000
#define CAP 256

// ---------------- scratch ----------------
__device__ float g_y1[HEADS * CN1 * D_OUT];
__device__ float g_y2[HEADS * CN2 * D_OUT];
__device__ float g_cat[HEADS * CN0 * 4 * D_OUT];   // [h][row][ xi0 | agg0 | agg1 | agg2 ]
__device__ float g_a1[HEADS * CN0];
__device__ float g_a20[HEADS * CN0];
__device__ float g_a21[HEADS * CN1];
__device__ float g_a22[HEADS * CN2];
__device__ int   g_cnt[3 * CN0];
__device__ int   g_list[3 * CN0 * CAP];

__global__ void zero_cnt_kernel() {
    int i = blockIdx.x * blockDim.x + threadIdx.x;
    if (i < 3 * CN0) g_cnt[i] = 0;
}

// ============================================================================
// GEMM1: 128x128 tile, BK=16, 256 threads, 8x8 microtile, double-buffered
// y = relu(X @ W1h + b1h), fused a1/a2 attention dots
// ============================================================================
__global__ __launch_bounds__(256) void gemm1_kernel(
    const float* __restrict__ x0, const float* __restrict__ x1, const float* __restrict__ x2,
    const float* __restrict__ W1, const float* __restrict__ b1,
    const float* __restrict__ a1w, const float* __restrict__ a1b,
    const float* __restrict__ a2w, const float* __restrict__ a2b)
{
    const int lvl = blockIdx.y;
    const int h   = blockIdx.z;
    const int Nl  = (lvl == 0) ? CN0 : (lvl == 1) ? CN1 : CN2;
    const int row0 = blockIdx.x * 128;
    if (row0 >= Nl) return;

    const float* X = (lvl == 0) ? x0 : (lvl == 1) ? x1 : x2;
    float* out; int ldo;
    if (lvl == 0)      { out = g_cat + (size_t)h * CN0 * 512; ldo = 512; }
    else if (lvl == 1) { out = g_y1  + (size_t)h * CN1 * 128; ldo = 128; }
    else               { out = g_y2  + (size_t)h * CN2 * 128; ldo = 128; }
    const float* Wh = W1 + (size_t)h * D_IN * D_OUT;

    __shared__ float As[2][16][128];   // [k][m] transposed
    __shared__ float Bs[2][16][128];   // [k][n]

    const int tid = threadIdx.x;
    const int tx  = tid & 15;          // 0..15 (cols)
    const int ty  = tid >> 4;          // 0..15 (rows)

    // load-slot mapping
    const int fa0 = tid, fa1 = tid + 256;          // A slots: r=f>>2, kk=(f&3)*4
    const int ra0 = fa0 >> 2, ka0 = (fa0 & 3) * 4;
    const int ra1 = fa1 >> 2, ka1 = (fa1 & 3) * 4;
    const int kb0 = fa0 >> 5, cb0 = (fa0 & 31) * 4; // B slots
    const int kb1 = fa1 >> 5, cb1 = (fa1 & 31) * 4;

    const int gra0 = min(row0 + ra0, Nl - 1);
    const int gra1 = min(row0 + ra1, Nl - 1);

    float acc[8][8];
#pragma unroll
    for (int i = 0; i < 8; i++)
#pragma unroll
        for (int j = 0; j < 8; j++) acc[i][j] = 0.f;

    float4 ar0, ar1, br0, br1;
    // prefetch tile 0
    ar0 = *(const float4*)(X + (size_t)gra0 * D_IN + ka0);
    ar1 = *(const float4*)(X + (size_t)gra1 * D_IN + ka1);
    br0 = *(const float4*)(Wh + (size_t)kb0 * 128 + cb0);
    br1 = *(const float4*)(Wh + (size_t)kb1 * 128 + cb1);
    {
        As[0][ka0+0][ra0]=ar0.x; As[0][ka0+1][ra0]=ar0.y; As[0][ka0+2][ra0]=ar0.z; As[0][ka0+3][ra0]=ar0.w;
        As[0][ka1+0][ra1]=ar1.x; As[0][ka1+1][ra1]=ar1.y; As[0][ka1+2][ra1]=ar1.z; As[0][ka1+3][ra1]=ar1.w;
        *(float4*)&Bs[0][kb0][cb0] = br0;
        *(float4*)&Bs[0][kb1][cb1] = br1;
    }
    __syncthreads();

    const int NT = D_IN / 16;  // 16
    int buf = 0;
    for (int kt = 0; kt < NT; kt++) {
        if (kt + 1 < NT) {
            int k0 = (kt + 1) * 16;
            ar0 = *(const float4*)(X + (size_t)gra0 * D_IN + k0 + ka0);
            ar1 = *(const float4*)(X + (size_t)gra1 * D_IN + k0 + ka1);
            br0 = *(const float4*)(Wh + (size_t)(k0 + kb0) * 128 + cb0);
            br1 = *(const float4*)(Wh + (size_t)(k0 + kb1) * 128 + cb1);
        }
#pragma unroll
        for (int k = 0; k < 16; k++) {
            float4 a0 = *(float4*)&As[buf][k][ty * 8];
            float4 a1 = *(float4*)&As[buf][k][ty * 8 + 4];
            float4 b0 = *(float4*)&Bs[buf][k][tx * 8];
            float4 b1 = *(float4*)&Bs[buf][k][tx * 8 + 4];
            float av[8] = {a0.x,a0.y,a0.z,a0.w,a1.x,a1.y,a1.z,a1.w};
            float bv[8] = {b0.x,b0.y,b0.z,b0.w,b1.x,b1.y,b1.z,b1.w};
#pragma unroll
            for (int i = 0; i < 8; i++)
#pragma unroll
                for (int j = 0; j < 8; j++)
                    acc[i][j] = fmaf(av[i], bv[j], acc[i][j]);
        }
        if (kt + 1 < NT) {
            int nb = buf ^ 1;
            As[nb][ka0+0][ra0]=ar0.x; As[nb][ka0+1][ra0]=ar0.y; As[nb][ka0+2][ra0]=ar0.z; As[nb][ka0+3][ra0]=ar0.w;
            As[nb][ka1+0][ra1]=ar1.x; As[nb][ka1+1][ra1]=ar1.y; As[nb][ka1+2][ra1]=ar1.z; As[nb][ka1+3][ra1]=ar1.w;
            *(float4*)&Bs[nb][kb0][cb0] = br0;
            *(float4*)&Bs[nb][kb1][cb1] = br1;
            __syncthreads();
            buf = nb;
        }
    }

    // epilogue: bias + relu + store + fused attention dots
    float4 bias0 = *(const float4*)(b1  + h * 128 + tx * 8);
    float4 bias1 = *(const float4*)(b1  + h * 128 + tx * 8 + 4);
    float4 w20   = *(const float4*)(a2w + h * 128 + tx * 8);
    float4 w21   = *(const float4*)(a2w + h * 128 + tx * 8 + 4);
    float4 w10 = make_float4(0,0,0,0), w11 = make_float4(0,0,0,0);
    if (lvl == 0) {
        w10 = *(const float4*)(a1w + h * 128 + tx * 8);
        w11 = *(const float4*)(a1w + h * 128 + tx * 8 + 4);
    }
    float* a2out = (lvl == 0) ? (g_a20 + h * CN0)
                 : (lvl == 1) ? (g_a21 + h * CN1)
                              : (g_a22 + h * CN2);
    const float a2bias = a2b[h];
    const float a1bias = a1b[h];

#pragma unroll
    for (int i = 0; i < 8; i++) {
        int gr = row0 + ty * 8 + i;
        float v[8];
        v[0]=fmaxf(acc[i][0]+bias0.x,0.f); v[1]=fmaxf(acc[i][1]+bias0.y,0.f);
        v[2]=fmaxf(acc[i][2]+bias0.z,0.f); v[3]=fmaxf(acc[i][3]+bias0.w,0.f);
        v[4]=fmaxf(acc[i][4]+bias1.x,0.f); v[5]=fmaxf(acc[i][5]+bias1.y,0.f);
        v[6]=fmaxf(acc[i][6]+bias1.z,0.f); v[7]=fmaxf(acc[i][7]+bias1.w,0.f);
        if (gr < Nl) {
            *(float4*)(out + (size_t)gr * ldo + tx * 8)     = make_float4(v[0],v[1],v[2],v[3]);
            *(float4*)(out + (size_t)gr * ldo + tx * 8 + 4) = make_float4(v[4],v[5],v[6],v[7]);
        }
        float s2 = v[0]*w20.x + v[1]*w20.y + v[2]*w20.z + v[3]*w20.w
                 + v[4]*w21.x + v[5]*w21.y + v[6]*w21.z + v[7]*w21.w;
#pragma unroll
        for (int o = 8; o; o >>= 1) s2 += __shfl_xor_sync(0xffffffffu, s2, o);
        if (tx == 0 && gr < Nl) a2out[gr] = s2 + a2bias;
        if (lvl == 0) {
            float s1 = v[0]*w10.x + v[1]*w10.y + v[2]*w10.z + v[3]*w10.w
                     + v[4]*w11.x + v[5]*w11.y + v[6]*w11.z + v[7]*w11.w;
#pragma unroll
            for (int o = 8; o; o >>= 1) s1 += __shfl_xor_sync(0xffffffffu, s1, o);
            if (tx == 0 && gr < Nl) g_a1[h * CN0 + gr] = s1 + a1bias;
        }
    }
}

// ---------------- bucket build ----------------
__global__ void bucket_kernel(
    const int* __restrict__ rows0, const int* __restrict__ cols0,
    const int* __restrict__ rows1, const int* __restrict__ cols1,
    const int* __restrict__ rows2, const int* __restrict__ cols2)
{
    int i = blockIdx.x * blockDim.x + threadIdx.x;
    int lvl, e;
    const int *rows, *cols;
    if (i < NNZ0)                    { lvl = 0; e = i;               rows = rows0; cols = cols0; }
    else if (i < NNZ0 + NNZ1)        { lvl = 1; e = i - NNZ0;        rows = rows1; cols = cols1; }
    else if (i < NNZ0 + NNZ1 + NNZ2) { lvl = 2; e = i - NNZ0 - NNZ1; rows = rows2; cols = cols2; }
    else return;
    int r = rows[e], c = cols[e];
    int pos = atomicAdd(&g_cnt[lvl * CN0 + r], 1);
    if (pos < CAP) g_list[(size_t)(lvl * CN0 + r) * CAP + pos] = c;
}

// ---------------- attention gather: warp per (row, head, level), 4x unrolled ----
__global__ __launch_bounds__(256) void agg_kernel()
{
    int w = (blockIdx.x * blockDim.x + threadIdx.x) >> 5;
    int lane = threadIdx.x & 31;
    if (w >= 3 * HEADS * CN0) return;
    int lvl = w / (HEADS * CN0);
    int rem = w - lvl * (HEADS * CN0);
    int h   = rem / CN0;
    int row = rem - h * CN0;

    int n = g_cnt[lvl * CN0 + row];
    if (n > CAP) n = CAP;
    float a1v = g_a1[h * CN0 + row];

    const float* a2p; const float* yb; int ldy;
    if (lvl == 0)      { a2p = g_a20 + h * CN0; yb = g_cat + (size_t)h * CN0 * 512; ldy = 512; }
    else if (lvl == 1) { a2p = g_a21 + h * CN1; yb = g_y1  + (size_t)h * CN1 * 128; ldy = 128; }
    else               { a2p = g_a22 + h * CN2; yb = g_y2  + (size_t)h * CN2 * 128; ldy = 128; }

    const int* lst = g_list + (size_t)(lvl * CN0 + row) * CAP;
    float4 acc0 = make_float4(0,0,0,0), acc1 = make_float4(0,0,0,0);
    float4 acc2 = make_float4(0,0,0,0), acc3 = make_float4(0,0,0,0);

    int j = 0;
    for (; j + 4 <= n; j += 4) {
        int c0 = lst[j], c1 = lst[j+1], c2 = lst[j+2], c3 = lst[j+3];
        float z0 = a1v + a2p[c0], z1 = a1v + a2p[c1];
        float z2 = a1v + a2p[c2], z3 = a1v + a2p[c3];
        const float4* p0 = (const float4*)(yb + (size_t)c0 * ldy) + lane;
        const float4* p1 = (const float4*)(yb + (size_t)c1 * ldy) + lane;
        const float4* p2 = (const float4*)(yb + (size_t)c2 * ldy) + lane;
        const float4* p3 = (const float4*)(yb + (size_t)c3 * ldy) + lane;
        float4 y0 = *p0, y1 = *p1, y2 = *p2, y3 = *p3;
        float t0 = 1.f / (1.f + __expf(-z0));
        float t1 = 1.f / (1.f + __expf(-z1));
        float t2 = 1.f / (1.f + __expf(-z2));
        float t3 = 1.f / (1.f + __expf(-z3));
        acc0.x = fmaf(t0, y0.x, acc0.x); acc0.y = fmaf(t0, y0.y, acc0.y);
        acc0.z = fmaf(t0, y0.z, acc0.z); acc0.w = fmaf(t0, y0.w, acc0.w);
        acc1.x = fmaf(t1, y1.x, acc1.x); acc1.y = fmaf(t1, y1.y, acc1.y);
        acc1.z = fmaf(t1, y1.z, acc1.z); acc1.w = fmaf(t1, y1.w, acc1.w);
        acc2.x = fmaf(t2, y2.x, acc2.x); acc2.y = fmaf(t2, y2.y, acc2.y);
        acc2.z = fmaf(t2, y2.z, acc2.z); acc2.w = fmaf(t2, y2.w, acc2.w);
        acc3.x = fmaf(t3, y3.x, acc3.x); acc3.y = fmaf(t3, y3.y, acc3.y);
        acc3.z = fmaf(t3, y3.z, acc3.z); acc3.w = fmaf(t3, y3.w, acc3.w);
    }
    for (; j < n; j++) {
        int c = lst[j];
        float z = a1v + a2p[c];
        float att = 1.f / (1.f + __expf(-z));
        float4 yv = *((const float4*)(yb + (size_t)c * ldy) + lane);
        acc0.x = fmaf(att, yv.x, acc0.x); acc0.y = fmaf(att, yv.y, acc0.y);
        acc0.z = fmaf(att, yv.z, acc0.z); acc0.w = fmaf(att, yv.w, acc0.w);
    }
    float4 acc;
    acc.x = (acc0.x + acc1.x) + (acc2.x + acc3.x);
    acc.y = (acc0.y + acc1.y) + (acc2.y + acc3.y);
    acc.z = (acc0.z + acc1.z) + (acc2.z + acc3.z);
    acc.w = (acc0.w + acc1.w) + (acc2.w + acc3.w);
    *(float4*)(g_cat + (size_t)h * CN0 * 512 + (size_t)row * 512 + 128 + lvl * 128 + lane * 4) = acc;
}

// ============================================================================
// GEMM2: out = mean_h(cat_h @ Wagg_h + bagg_h); 128x128 tile, same pipeline
// ============================================================================
__global__ __launch_bounds__(256) void gemm2_kernel(
    const float* __restrict__ Wagg, const float* __restrict__ bagg,
    float* __restrict__ out)
{
    const int row0 = blockIdx.x * 128;

    __shared__ float As[2][16][128];
    __shared__ float Bs[2][16][128];

    const int tid = threadIdx.x;
    const int tx  = tid & 15;
    const int ty  = tid >> 4;

    const int fa0 = tid, fa1 = tid + 256;
    const int ra0 = fa0 >> 2, ka0 = (fa0 & 3) * 4;
    const int ra1 = fa1 >> 2, ka1 = (fa1 & 3) * 4;
    const int kb0 = fa0 >> 5, cb0 = (fa0 & 31) * 4;
    const int kb1 = fa1 >> 5, cb1 = (fa1 & 31) * 4;

    const int gra0 = min(row0 + ra0, CN0 - 1);
    const int gra1 = min(row0 + ra1, CN0 - 1);

    float acc[8][8];
#pragma unroll
    for (int i = 0; i < 8; i++)
#pragma unroll
        for (int j = 0; j < 8; j++) acc[i][j] = 0.f;

    const int NT = 128;   // 4 heads * 512 / 16
    float4 ar0, ar1, br0, br1;

    // tile pointers for tile t: head = t>>5, k0 = (t&31)*16
    {
        const float* A  = g_cat;
        const float* Wh = Wagg;
        ar0 = *(const float4*)(A + (size_t)gra0 * 512 + ka0);
        ar1 = *(const float4*)(A + (size_t)gra1 * 512 + ka1);
        br0 = *(const float4*)(Wh + (size_t)kb0 * 128 + cb0);
        br1 = *(const float4*)(Wh + (size_t)kb1 * 128 + cb1);
        As[0][ka0+0][ra0]=ar0.x; As[0][ka0+1][ra0]=ar0.y; As[0][ka0+2][ra0]=ar0.z; As[0][ka0+3][ra0]=ar0.w;
        As[0][ka1+0][ra1]=ar1.x; As[0][ka1+1][ra1]=ar1.y; As[0][ka1+2][ra1]=ar1.z; As[0][ka1+3][ra1]=ar1.w;
        *(float4*)&Bs[0][kb0][cb0] = br0;
        *(float4*)&Bs[0][kb1][cb1] = br1;
    }
    __syncthreads();

    int buf = 0;
    for (int kt = 0; kt < NT; kt++) {
        if (kt + 1 < NT) {
            int t = kt + 1;
            int h = t >> 5, k0 = (t & 31) * 16;
            const float* A  = g_cat + (size_t)h * CN0 * 512;
            const float* Wh = Wagg + (size_t)h * 512 * 128;
            ar0 = *(const float4*)(A + (size_t)gra0 * 512 + k0 + ka0);
            ar1 = *(const float4*)(A + (size_t)gra1 * 512 + k0 + ka1);
            br0 = *(const float4*)(Wh + (size_t)(k0 + kb0) * 128 + cb0);
            br1 = *(const float4*)(Wh + (size_t)(k0 + kb1) * 128 + cb1);
        }
#pragma unroll
        for (int k = 0; k < 16; k++) {
            float4 a0 = *(float4*)&As[buf][k][ty * 8];
            float4 a1 = *(float4*)&As[buf][k][ty * 8 + 4];
            float4 b0 = *(float4*)&Bs[buf][k][tx * 8];
            float4 b1 = *(float4*)&Bs[buf][k][tx * 8 + 4];
            float av[8] = {a0.x,a0.y,a0.z,a0.w,a1.x,a1.y,a1.z,a1.w};
            float bv[8] = {b0.x,b0.y,b0.z,b0.w,b1.x,b1.y,b1.z,b1.w};
#pragma unroll
            for (int i = 0; i < 8; i++)
#pragma unroll
                for (int j = 0; j < 8; j++)
                    acc[i][j] = fmaf(av[i], bv[j], acc[i][j]);
        }
        if (kt + 1 < NT) {
            int nb = buf ^ 1;
            As[nb][ka0+0][ra0]=ar0.x; As[nb][ka0+1][ra0]=ar0.y; As[nb][ka0+2][ra0]=ar0.z; As[nb][ka0+3][ra0]=ar0.w;
            As[nb][ka1+0][ra1]=ar1.x; As[nb][ka1+1][ra1]=ar1.y; As[nb][ka1+2][ra1]=ar1.z; As[nb][ka1+3][ra1]=ar1.w;
            *(float4*)&Bs[nb][kb0][cb0] = br0;
            *(float4*)&Bs[nb][kb1][cb1] = br1;
            __syncthreads();
            buf = nb;
        }
    }

    float bsx[8];
#pragma unroll
    for (int j = 0; j < 8; j++) bsx[j] = 0.f;
#pragma unroll
    for (int h = 0; h < HEADS; h++) {
#pragma unroll
        for (int j = 0; j < 8; j++) bsx[j] += bagg[h * 128 + tx * 8 + j];
    }
#pragma unroll
    for (int i = 0; i < 8; i++) {
        int gr = row0 + ty * 8 + i;
        if (gr < CN0) {
            float4 v0, v1;
            v0.x = (acc[i][0] + bsx[0]) * 0.25f;
            v0.y = (acc[i][1] + bsx[1]) * 0.25f;
            v0.z = (acc[i][2] + bsx[2]) * 0.25f;
            v0.w = (acc[i][3] + bsx[3]) * 0.25f;
            v1.x = (acc[i][4] + bsx[4]) * 0.25f;
            v1.y = (acc[i][5] + bsx[5]) * 0.25f;
            v1.z = (acc[i][6] + bsx[6]) * 0.25f;
            v1.w = (acc[i][7] + bsx[7]) * 0.25f;
            *(float4*)(out + (size_t)gr * 128 + tx * 8)     = v0;
            *(float4*)(out + (size_t)gr * 128 + tx * 8 + 4) = v1;
        }
    }
}

// ---------------- launch ----------------
extern "C" void kernel_launch(void* const* d_in, const int* in_sizes, int n_in,
                              void* d_out, int out_size)
{
    const float* x0    = (const float*)d_in[0];
    const float* x1    = (const float*)d_in[1];
    const float* x2    = (const float*)d_in[2];
    const int*   rows0 = (const int*)d_in[3];
    const int*   cols0 = (const int*)d_in[4];
    const int*   rows1 = (const int*)d_in[5];
    const int*   cols1 = (const int*)d_in[6];
    const int*   rows2 = (const int*)d_in[7];
    const int*   cols2 = (const int*)d_in[8];
    const float* W1    = (const float*)d_in[9];
    const float* b1    = (const float*)d_in[10];
    const float* a1w   = (const float*)d_in[11];
    const float* a1b   = (const float*)d_in[12];
    const float* a2w   = (const float*)d_in[13];
    const float* a2b   = (const float*)d_in[14];
    const float* Wagg  = (const float*)d_in[15];
    const float* bagg  = (const float*)d_in[16];
    float* out = (float*)d_out;

    zero_cnt_kernel<<<(3 * CN0 + 255) / 256, 256>>>();
    bucket_kernel<<<(NNZ0 + NNZ1 + NNZ2 + 255) / 256, 256>>>(
        rows0, cols0, rows1, cols1, rows2, cols2);

    {
        dim3 grid((CN1 + 127) / 128, 3, HEADS);
        gemm1_kernel<<<grid, 256>>>(x0, x1, x2, W1, b1, a1w, a1b, a2w, a2b);
    }
    {
        int warps = 3 * HEADS * CN0;
        agg_kernel<<<(warps * 32 + 255) / 256, 256>>>();
    }
    gemm2_kernel<<<(CN0 + 127) / 128, 256>>>(Wagg, bagg, out);
}

// round 3
// speedup vs baseline: 2.1880x; 2.1880x over previous
#include <cuda_runtime.h>
#include <math.h>

#define CN0 30000
#define CN1 90000
#define CN2 60000
#define D_IN 256
#define D_OUT 128
#define HEADS 4
#define NNZ0 960000
#define NNZ1 180000
#define NNZ2 180000
#define CAP 256

// ---------------- scratch ----------------
__device__ float g_y1[HEADS * CN1 * D_OUT];
__device__ float g_y2[HEADS * CN2 * D_OUT];
__device__ float g_cat[HEADS * CN0 * 4 * D_OUT];   // [h][row][ xi0 | agg0 | agg1 | agg2 ]
__device__ float g_a1[HEADS * CN0];
__device__ float g_a20[HEADS * CN0];
__device__ float g_a21[HEADS * CN1];
__device__ float g_a22[HEADS * CN2];
__device__ int   g_cnt[3 * CN0];
__device__ int   g_list[3 * CN0 * CAP];

__global__ void zero_cnt_kernel() {
    int i = blockIdx.x * blockDim.x + threadIdx.x;
    if (i < 3 * CN0) g_cnt[i] = 0;
}

// ---------------- tf32 helpers ----------------
__device__ __forceinline__ unsigned f2tf(float f) {
    unsigned u;
    asm("cvt.rna.tf32.f32 %0, %1;" : "=r"(u) : "f"(f));
    return u;
}
__device__ __forceinline__ void mma_tf32(float d[4], const unsigned a[4], const unsigned b[2]) {
    asm volatile(
        "mma.sync.aligned.m16n8k8.row.col.f32.tf32.tf32.f32 "
        "{%0,%1,%2,%3}, {%4,%5,%6,%7}, {%8,%9}, {%0,%1,%2,%3};\n"
        : "+f"(d[0]), "+f"(d[1]), "+f"(d[2]), "+f"(d[3])
        : "r"(a[0]), "r"(a[1]), "r"(a[2]), "r"(a[3]), "r"(b[0]), "r"(b[1]));
}

// ============================================================================
// GEMM1 (tf32 tensor core): y = relu(X @ W1h + b1h), fused a1/a2 dots
// CTA tile 128x128, BK=16, 256 threads (8 warps, warp tile 64x32), dbl-buffered
// ============================================================================
__global__ __launch_bounds__(256, 2) void gemm1_kernel(
    const float* __restrict__ x0, const float* __restrict__ x1, const float* __restrict__ x2,
    const float* __restrict__ W1, const float* __restrict__ b1,
    const float* __restrict__ a1w, const float* __restrict__ a1b,
    const float* __restrict__ a2w, const float* __restrict__ a2b)
{
    const int lvl = blockIdx.y;
    const int h   = blockIdx.z;
    const int Nl  = (lvl == 0) ? CN0 : (lvl == 1) ? CN1 : CN2;
    const int row0 = blockIdx.x * 128;
    if (row0 >= Nl) return;

    const float* X = (lvl == 0) ? x0 : (lvl == 1) ? x1 : x2;
    float* out; int ldo;
    if (lvl == 0)      { out = g_cat + (size_t)h * CN0 * 512; ldo = 512; }
    else if (lvl == 1) { out = g_y1  + (size_t)h * CN1 * 128; ldo = 128; }
    else               { out = g_y2  + (size_t)h * CN2 * 128; ldo = 128; }
    const float* Wh = W1 + (size_t)h * D_IN * D_OUT;

    __shared__ unsigned As[2][128][20];   // [m][k], pad 20
    __shared__ unsigned Bs[2][16][132];   // [k][n], pad 132

    const int tid = threadIdx.x;
    const int lane = tid & 31;
    const int wid  = tid >> 5;
    const int wR = wid >> 2;          // 0..1 : row warp (64 rows)
    const int wC = wid & 3;           // 0..3 : col warp (32 cols)
    const int gid = lane >> 2;        // 0..7
    const int tg  = lane & 3;         // 0..3

    // load-slot mapping (2 float4 per thread for A and for B per panel)
    const int sA0 = tid, sA1 = tid + 256;
    const int mA0 = sA0 >> 2, kA0 = (sA0 & 3) * 4;
    const int mA1 = sA1 >> 2, kA1 = (sA1 & 3) * 4;
    const int kB0 = sA0 >> 5, nB0 = (sA0 & 31) * 4;
    const int kB1 = sA1 >> 5, nB1 = (sA1 & 31) * 4;
    const int grA0 = min(row0 + mA0, Nl - 1);
    const int grA1 = min(row0 + mA1, Nl - 1);

    float acc[4][4][4];
#pragma unroll
    for (int mt = 0; mt < 4; mt++)
#pragma unroll
        for (int nt = 0; nt < 4; nt++)
#pragma unroll
            for (int r = 0; r < 4; r++) acc[mt][nt][r] = 0.f;

    const int NT = D_IN / 16;   // 16 panels
    float4 a0v, a1v_, b0v, b1v;

    // prefetch panel 0
    a0v = *(const float4*)(X + (size_t)grA0 * D_IN + kA0);
    a1v_ = *(const float4*)(X + (size_t)grA1 * D_IN + kA1);
    b0v = *(const float4*)(Wh + (size_t)kB0 * 128 + nB0);
    b1v = *(const float4*)(Wh + (size_t)kB1 * 128 + nB1);
    {
        uint4 t;
        t.x = f2tf(a0v.x); t.y = f2tf(a0v.y); t.z = f2tf(a0v.z); t.w = f2tf(a0v.w);
        *(uint4*)&As[0][mA0][kA0] = t;
        t.x = f2tf(a1v_.x); t.y = f2tf(a1v_.y); t.z = f2tf(a1v_.z); t.w = f2tf(a1v_.w);
        *(uint4*)&As[0][mA1][kA1] = t;
        t.x = f2tf(b0v.x); t.y = f2tf(b0v.y); t.z = f2tf(b0v.z); t.w = f2tf(b0v.w);
        *(uint4*)&Bs[0][kB0][nB0] = t;
        t.x = f2tf(b1v.x); t.y = f2tf(b1v.y); t.z = f2tf(b1v.z); t.w = f2tf(b1v.w);
        *(uint4*)&Bs[0][kB1][nB1] = t;
    }
    __syncthreads();

    int buf = 0;
    for (int kt = 0; kt < NT; kt++) {
        if (kt + 1 < NT) {
            int k0 = (kt + 1) * 16;
            a0v = *(const float4*)(X + (size_t)grA0 * D_IN + k0 + kA0);
            a1v_ = *(const float4*)(X + (size_t)grA1 * D_IN + k0 + kA1);
            b0v = *(const float4*)(Wh + (size_t)(k0 + kB0) * 128 + nB0);
            b1v = *(const float4*)(Wh + (size_t)(k0 + kB1) * 128 + nB1);
        }
#pragma unroll
        for (int ks = 0; ks < 2; ks++) {
            const int kb = ks * 8;
            unsigned af[4][4], bf[4][2];
#pragma unroll
            for (int mt = 0; mt < 4; mt++) {
                int rb = wR * 64 + mt * 16;
                af[mt][0] = As[buf][rb + gid][kb + tg];
                af[mt][1] = As[buf][rb + gid + 8][kb + tg];
                af[mt][2] = As[buf][rb + gid][kb + tg + 4];
                af[mt][3] = As[buf][rb + gid + 8][kb + tg + 4];
            }
#pragma unroll
            for (int nt = 0; nt < 4; nt++) {
                int cb = wC * 32 + nt * 8;
                bf[nt][0] = Bs[buf][kb + tg][cb + gid];
                bf[nt][1] = Bs[buf][kb + tg + 4][cb + gid];
            }
#pragma unroll
            for (int mt = 0; mt < 4; mt++)
#pragma unroll
                for (int nt = 0; nt < 4; nt++)
                    mma_tf32(acc[mt][nt], af[mt], bf[nt]);
        }
        if (kt + 1 < NT) {
            int nb = buf ^ 1;
            uint4 t;
            t.x = f2tf(a0v.x); t.y = f2tf(a0v.y); t.z = f2tf(a0v.z); t.w = f2tf(a0v.w);
            *(uint4*)&As[nb][mA0][kA0] = t;
            t.x = f2tf(a1v_.x); t.y = f2tf(a1v_.y); t.z = f2tf(a1v_.z); t.w = f2tf(a1v_.w);
            *(uint4*)&As[nb][mA1][kA1] = t;
            t.x = f2tf(b0v.x); t.y = f2tf(b0v.y); t.z = f2tf(b0v.z); t.w = f2tf(b0v.w);
            *(uint4*)&Bs[nb][kB0][nB0] = t;
            t.x = f2tf(b1v.x); t.y = f2tf(b1v.y); t.z = f2tf(b1v.z); t.w = f2tf(b1v.w);
            *(uint4*)&Bs[nb][kB1][nB1] = t;
            __syncthreads();
            buf = nb;
        }
    }

    // ---- epilogue: bias + relu + store + fused attention dots ----
    float* a2out = (lvl == 0) ? (g_a20 + h * CN0)
                 : (lvl == 1) ? (g_a21 + h * CN1)
                              : (g_a22 + h * CN2);
    const float a2bias = a2b[h];
    const float a1bias = a1b[h];

    float2 biasv[4], w2v[4], w1v[4];
#pragma unroll
    for (int nt = 0; nt < 4; nt++) {
        int c = wC * 32 + nt * 8 + 2 * tg;
        biasv[nt] = *(const float2*)(b1  + h * 128 + c);
        w2v[nt]   = *(const float2*)(a2w + h * 128 + c);
        w1v[nt]   = (lvl == 0) ? *(const float2*)(a1w + h * 128 + c) : make_float2(0.f, 0.f);
    }

#pragma unroll
    for (int mt = 0; mt < 4; mt++) {
        int r0 = row0 + wR * 64 + mt * 16 + gid;
        int r1 = r0 + 8;
        float s2a = 0.f, s2b = 0.f, s1a = 0.f, s1b = 0.f;
#pragma unroll
        for (int nt = 0; nt < 4; nt++) {
            int c = wC * 32 + nt * 8 + 2 * tg;
            float v0 = fmaxf(acc[mt][nt][0] + biasv[nt].x, 0.f);
            float v1 = fmaxf(acc[mt][nt][1] + biasv[nt].y, 0.f);
            float v2 = fmaxf(acc[mt][nt][2] + biasv[nt].x, 0.f);
            float v3 = fmaxf(acc[mt][nt][3] + biasv[nt].y, 0.f);
            if (r0 < Nl) *(float2*)(out + (size_t)r0 * ldo + c) = make_float2(v0, v1);
            if (r1 < Nl) *(float2*)(out + (size_t)r1 * ldo + c) = make_float2(v2, v3);
            s2a += v0 * w2v[nt].x + v1 * w2v[nt].y;
            s2b += v2 * w2v[nt].x + v3 * w2v[nt].y;
            if (lvl == 0) {
                s1a += v0 * w1v[nt].x + v1 * w1v[nt].y;
                s1b += v2 * w1v[nt].x + v3 * w1v[nt].y;
            }
        }
        // reduce across quad (lanes sharing gid)
        s2a += __shfl_xor_sync(0xffffffffu, s2a, 1); s2a += __shfl_xor_sync(0xffffffffu, s2a, 2);
        s2b += __shfl_xor_sync(0xffffffffu, s2b, 1); s2b += __shfl_xor_sync(0xffffffffu, s2b, 2);
        if (lvl == 0) {
            s1a += __shfl_xor_sync(0xffffffffu, s1a, 1); s1a += __shfl_xor_sync(0xffffffffu, s1a, 2);
            s1b += __shfl_xor_sync(0xffffffffu, s1b, 1); s1b += __shfl_xor_sync(0xffffffffu, s1b, 2);
        }
        if (tg == 0) {
            // NOTE: 4 col-warps each hold a partial over 32 cols -> must combine.
            // Use atomicAdd-free approach: each col-warp adds its partial via shared.
        }
        // combine partials across the 4 col-warps through shared memory
        __shared__ float s_red[2][8][4][2 + 2];  // [wR][gid][wC][{s2a,s2b,s1a,s1b}] -> use 4 floats
        if (tg == 0) {
            s_red[wR][gid][wC][0] = s2a;
            s_red[wR][gid][wC][1] = s2b;
            s_red[wR][gid][wC][2] = s1a;
            s_red[wR][gid][wC][3] = s1b;
        }
        __syncthreads();
        if (tg == 0 && wC == 0) {
            float t2a = 0.f, t2b = 0.f, t1a = 0.f, t1b = 0.f;
#pragma unroll
            for (int q = 0; q < 4; q++) {
                t2a += s_red[wR][gid][q][0];
                t2b += s_red[wR][gid][q][1];
                t1a += s_red[wR][gid][q][2];
                t1b += s_red[wR][gid][q][3];
            }
            if (r0 < Nl) a2out[r0] = t2a + a2bias;
            if (r1 < Nl) a2out[r1] = t2b + a2bias;
            if (lvl == 0) {
                if (r0 < Nl) g_a1[h * CN0 + r0] = t1a + a1bias;
                if (r1 < Nl) g_a1[h * CN0 + r1] = t1b + a1bias;
            }
        }
        __syncthreads();
    }
}

// ---------------- bucket build ----------------
__global__ void bucket_kernel(
    const int* __restrict__ rows0, const int* __restrict__ cols0,
    const int* __restrict__ rows1, const int* __restrict__ cols1,
    const int* __restrict__ rows2, const int* __restrict__ cols2)
{
    int i = blockIdx.x * blockDim.x + threadIdx.x;
    int lvl, e;
    const int *rows, *cols;
    if (i < NNZ0)                    { lvl = 0; e = i;               rows = rows0; cols = cols0; }
    else if (i < NNZ0 + NNZ1)        { lvl = 1; e = i - NNZ0;        rows = rows1; cols = cols1; }
    else if (i < NNZ0 + NNZ1 + NNZ2) { lvl = 2; e = i - NNZ0 - NNZ1; rows = rows2; cols = cols2; }
    else return;
    int r = rows[e], c = cols[e];
    int pos = atomicAdd(&g_cnt[lvl * CN0 + r], 1);
    if (pos < CAP) g_list[(size_t)(lvl * CN0 + r) * CAP + pos] = c;
}

// ---------------- attention gather: decoupled two-phase, warp per (row,h,lvl) --
__global__ __launch_bounds__(256) void agg_kernel()
{
    __shared__ int   s_c[8][64];
    __shared__ float s_att[8][64];

    int w = (blockIdx.x * blockDim.x + threadIdx.x) >> 5;
    int wl = (threadIdx.x >> 5);
    int lane = threadIdx.x & 31;
    if (w >= 3 * HEADS * CN0) return;
    int lvl = w / (HEADS * CN0);
    int rem = w - lvl * (HEADS * CN0);
    int h   = rem / CN0;
    int row = rem - h * CN0;

    int n = g_cnt[lvl * CN0 + row];
    if (n > CAP) n = CAP;
    float a1v = g_a1[h * CN0 + row];

    const float* a2p; const float* yb; int ldy;
    if (lvl == 0)      { a2p = g_a20 + h * CN0; yb = g_cat + (size_t)h * CN0 * 512; ldy = 512; }
    else if (lvl == 1) { a2p = g_a21 + h * CN1; yb = g_y1  + (size_t)h * CN1 * 128; ldy = 128; }
    else               { a2p = g_a22 + h * CN2; yb = g_y2  + (size_t)h * CN2 * 128; ldy = 128; }

    const int* lst = g_list + (size_t)(lvl * CN0 + row) * CAP;
    float4 acc[4];
#pragma unroll
    for (int q = 0; q < 4; q++) acc[q] = make_float4(0.f, 0.f, 0.f, 0.f);

    for (int j0 = 0; j0 < n; j0 += 64) {
        int m = n - j0; if (m > 64) m = 64;
        __syncwarp();
        // phase A: parallel index + score computation
        if (lane < m) {
            int c = lst[j0 + lane];
            float z = a1v + a2p[c];
            s_c[wl][lane] = c;
            s_att[wl][lane] = 1.f / (1.f + __expf(-z));
        }
        if (lane + 32 < m) {
            int c = lst[j0 + lane + 32];
            float z = a1v + a2p[c];
            s_c[wl][lane + 32] = c;
            s_att[wl][lane + 32] = 1.f / (1.f + __expf(-z));
        }
        __syncwarp();
        // phase B: pure gather + FMA, MLP=8
        int i = 0;
        for (; i + 8 <= m; i += 8) {
            int cc[8]; float tt[8];
#pragma unroll
            for (int u = 0; u < 8; u++) { cc[u] = s_c[wl][i + u]; tt[u] = s_att[wl][i + u]; }
            float4 yv[8];
#pragma unroll
            for (int u = 0; u < 8; u++)
                yv[u] = *((const float4*)(yb + (size_t)cc[u] * ldy) + lane);
#pragma unroll
            for (int u = 0; u < 8; u++) {
                int q = u & 3;
                acc[q].x = fmaf(tt[u], yv[u].x, acc[q].x);
                acc[q].y = fmaf(tt[u], yv[u].y, acc[q].y);
                acc[q].z = fmaf(tt[u], yv[u].z, acc[q].z);
                acc[q].w = fmaf(tt[u], yv[u].w, acc[q].w);
            }
        }
        for (; i < m; i++) {
            int c = s_c[wl][i]; float t = s_att[wl][i];
            float4 yv = *((const float4*)(yb + (size_t)c * ldy) + lane);
            acc[0].x = fmaf(t, yv.x, acc[0].x);
            acc[0].y = fmaf(t, yv.y, acc[0].y);
            acc[0].z = fmaf(t, yv.z, acc[0].z);
            acc[0].w = fmaf(t, yv.w, acc[0].w);
        }
    }
    float4 r;
    r.x = (acc[0].x + acc[1].x) + (acc[2].x + acc[3].x);
    r.y = (acc[0].y + acc[1].y) + (acc[2].y + acc[3].y);
    r.z = (acc[0].z + acc[1].z) + (acc[2].z + acc[3].z);
    r.w = (acc[0].w + acc[1].w) + (acc[2].w + acc[3].w);
    *(float4*)(g_cat + (size_t)h * CN0 * 512 + (size_t)row * 512 + 128 + lvl * 128 + lane * 4) = r;
}

// ============================================================================
// GEMM2 (tf32): out = mean_h(cat_h @ Wagg_h + bagg_h)
// ============================================================================
__global__ __launch_bounds__(256, 2) void gemm2_kernel(
    const float* __restrict__ Wagg, const float* __restrict__ bagg,
    float* __restrict__ out)
{
    const int row0 = blockIdx.x * 128;

    __shared__ unsigned As[2][128][20];
    __shared__ unsigned Bs[2][16][132];

    const int tid = threadIdx.x;
    const int lane = tid & 31;
    const int wid  = tid >> 5;
    const int wR = wid >> 2;
    const int wC = wid & 3;
    const int gid = lane >> 2;
    const int tg  = lane & 3;

    const int sA0 = tid, sA1 = tid + 256;
    const int mA0 = sA0 >> 2, kA0 = (sA0 & 3) * 4;
    const int mA1 = sA1 >> 2, kA1 = (sA1 & 3) * 4;
    const int kB0 = sA0 >> 5, nB0 = (sA0 & 31) * 4;
    const int kB1 = sA1 >> 5, nB1 = (sA1 & 31) * 4;
    const int grA0 = min(row0 + mA0, CN0 - 1);
    const int grA1 = min(row0 + mA1, CN0 - 1);

    float acc[4][4][4];
#pragma unroll
    for (int mt = 0; mt < 4; mt++)
#pragma unroll
        for (int nt = 0; nt < 4; nt++)
#pragma unroll
            for (int r = 0; r < 4; r++) acc[mt][nt][r] = 0.f;

    const int NT = 128;   // 4 heads * 512 / 16
    float4 a0v, a1v_, b0v, b1v;

    {
        a0v = *(const float4*)(g_cat + (size_t)grA0 * 512 + kA0);
        a1v_ = *(const float4*)(g_cat + (size_t)grA1 * 512 + kA1);
        b0v = *(const float4*)(Wagg + (size_t)kB0 * 128 + nB0);
        b1v = *(const float4*)(Wagg + (size_t)kB1 * 128 + nB1);
        uint4 t;
        t.x = f2tf(a0v.x); t.y = f2tf(a0v.y); t.z = f2tf(a0v.z); t.w = f2tf(a0v.w);
        *(uint4*)&As[0][mA0][kA0] = t;
        t.x = f2tf(a1v_.x); t.y = f2tf(a1v_.y); t.z = f2tf(a1v_.z); t.w = f2tf(a1v_.w);
        *(uint4*)&As[0][mA1][kA1] = t;
        t.x = f2tf(b0v.x); t.y = f2tf(b0v.y); t.z = f2tf(b0v.z); t.w = f2tf(b0v.w);
        *(uint4*)&Bs[0][kB0][nB0] = t;
        t.x = f2tf(b1v.x); t.y = f2tf(b1v.y); t.z = f2tf(b1v.z); t.w = f2tf(b1v.w);
        *(uint4*)&Bs[0][kB1][nB1] = t;
    }
    __syncthreads();

    int buf = 0;
    for (int kt = 0; kt < NT; kt++) {
        if (kt + 1 < NT) {
            int t = kt + 1;
            int h = t >> 5, k0 = (t & 31) * 16;
            const float* A  = g_cat + (size_t)h * CN0 * 512;
            const float* Wh = Wagg + (size_t)h * 512 * 128;
            a0v = *(const float4*)(A + (size_t)grA0 * 512 + k0 + kA0);
            a1v_ = *(const float4*)(A + (size_t)grA1 * 512 + k0 + kA1);
            b0v = *(const float4*)(Wh + (size_t)(k0 + kB0) * 128 + nB0);
            b1v = *(const float4*)(Wh + (size_t)(k0 + kB1) * 128 + nB1);
        }
#pragma unroll
        for (int ks = 0; ks < 2; ks++) {
            const int kb = ks * 8;
            unsigned af[4][4], bf[4][2];
#pragma unroll
            for (int mt = 0; mt < 4; mt++) {
                int rb = wR * 64 + mt * 16;
                af[mt][0] = As[buf][rb + gid][kb + tg];
                af[mt][1] = As[buf][rb + gid + 8][kb + tg];
                af[mt][2] = As[buf][rb + gid][kb + tg + 4];
                af[mt][3] = As[buf][rb + gid + 8][kb + tg + 4];
            }
#pragma unroll
            for (int nt = 0; nt < 4; nt++) {
                int cb = wC * 32 + nt * 8;
                bf[nt][0] = Bs[buf][kb + tg][cb + gid];
                bf[nt][1] = Bs[buf][kb + tg + 4][cb + gid];
            }
#pragma unroll
            for (int mt = 0; mt < 4; mt++)
#pragma unroll
                for (int nt = 0; nt < 4; nt++)
                    mma_tf32(acc[mt][nt], af[mt], bf[nt]);
        }
        if (kt + 1 < NT) {
            int nb = buf ^ 1;
            uint4 t;
            t.x = f2tf(a0v.x); t.y = f2tf(a0v.y); t.z = f2tf(a0v.z); t.w = f2tf(a0v.w);
            *(uint4*)&As[nb][mA0][kA0] = t;
            t.x = f2tf(a1v_.x); t.y = f2tf(a1v_.y); t.z = f2tf(a1v_.z); t.w = f2tf(a1v_.w);
            *(uint4*)&As[nb][mA1][kA1] = t;
            t.x = f2tf(b0v.x); t.y = f2tf(b0v.y); t.z = f2tf(b0v.z); t.w = f2tf(b0v.w);
            *(uint4*)&Bs[nb][kB0][nB0] = t;
            t.x = f2tf(b1v.x); t.y = f2tf(b1v.y); t.z = f2tf(b1v.z); t.w = f2tf(b1v.w);
            *(uint4*)&Bs[nb][kB1][nB1] = t;
            __syncthreads();
            buf = nb;
        }
    }

    // epilogue: + sum_h bagg, * 0.25
    float2 bsum[4];
#pragma unroll
    for (int nt = 0; nt < 4; nt++) {
        int c = wC * 32 + nt * 8 + 2 * tg;
        float2 s = make_float2(0.f, 0.f);
#pragma unroll
        for (int h = 0; h < HEADS; h++) {
            float2 bg = *(const float2*)(bagg + h * 128 + c);
            s.x += bg.x; s.y += bg.y;
        }
        bsum[nt] = s;
    }
#pragma unroll
    for (int mt = 0; mt < 4; mt++) {
        int r0 = row0 + wR * 64 + mt * 16 + gid;
        int r1 = r0 + 8;
#pragma unroll
        for (int nt = 0; nt < 4; nt++) {
            int c = wC * 32 + nt * 8 + 2 * tg;
            if (r0 < CN0) {
                float2 v;
                v.x = (acc[mt][nt][0] + bsum[nt].x) * 0.25f;
                v.y = (acc[mt][nt][1] + bsum[nt].y) * 0.25f;
                *(float2*)(out + (size_t)r0 * 128 + c) = v;
            }
            if (r1 < CN0) {
                float2 v;
                v.x = (acc[mt][nt][2] + bsum[nt].x) * 0.25f;
                v.y = (acc[mt][nt][3] + bsum[nt].y) * 0.25f;
                *(float2*)(out + (size_t)r1 * 128 + c) = v;
            }
        }
    }
}

// ---------------- launch ----------------
extern "C" void kernel_launch(void* const* d_in, const int* in_sizes, int n_in,
                              void* d_out, int out_size)
{
    const float* x0    = (const float*)d_in[0];
    const float* x1    = (const float*)d_in[1];
    const float* x2    = (const float*)d_in[2];
    const int*   rows0 = (const int*)d_in[3];
    const int*   cols0 = (const int*)d_in[4];
    const int*   rows1 = (const int*)d_in[5];
    const int*   cols1 = (const int*)d_in[6];
    const int*   rows2 = (const int*)d_in[7];
    const int*   cols2 = (const int*)d_in[8];
    const float* W1    = (const float*)d_in[9];
    const float* b1    = (const float*)d_in[10];
    const float* a1w   = (const float*)d_in[11];
    const float* a1b   = (const float*)d_in[12];
    const float* a2w   = (const float*)d_in[13];
    const float* a2b   = (const float*)d_in[14];
    const float* Wagg  = (const float*)d_in[15];
    const float* bagg  = (const float*)d_in[16];
    float* out = (float*)d_out;

    zero_cnt_kernel<<<(3 * CN0 + 255) / 256, 256>>>();
    bucket_kernel<<<(NNZ0 + NNZ1 + NNZ2 + 255) / 256, 256>>>(
        rows0, cols0, rows1, cols1, rows2, cols2);

    {
        dim3 grid((CN1 + 127) / 128, 3, HEADS);
        gemm1_kernel<<<grid, 256>>>(x0, x1, x2, W1, b1, a1w, a1b, a2w, a2b);
    }
    {
        int warps = 3 * HEADS * CN0;
        agg_kernel<<<(warps * 32 + 255) / 256, 256>>>();
    }
    gemm2_kernel<<<(CN0 + 127) / 128, 256>>>(Wagg, bagg, out);
}

// round 5
// speedup vs baseline: 2.2203x; 1.0148x over previous
#include <cuda_runtime.h>
#include <math.h>

#define CN0 30000
#define CN1 90000
#define CN2 60000
#define D_IN 256
#define D_OUT 128
#define HEADS 4
#define NNZ0 960000
#define NNZ1 180000
#define NNZ2 180000
#define CAP 256

// dynamic smem layout for the GEMMs
#define A_STRIDE 20
#define B_STRIDE 132
#define A_ELEMS (3 * 128 * A_STRIDE)
#define B_ELEMS (3 * 16 * B_STRIDE)
#define GEMM_SMEM_BYTES ((A_ELEMS + B_ELEMS) * 4)

// ---------------- scratch ----------------
__device__ float g_y1[HEADS * CN1 * D_OUT];
__device__ float g_y2[HEADS * CN2 * D_OUT];
__device__ float g_cat[HEADS * CN0 * 4 * D_OUT];   // [h][row][ xi0 | agg0 | agg1 | agg2 ]
__device__ float g_a1[HEADS * CN0];
__device__ float g_a20[HEADS * CN0];
__device__ float g_a21[HEADS * CN1];
__device__ float g_a22[HEADS * CN2];
__device__ int   g_cnt[3 * CN0];
__device__ int   g_list[3 * CN0 * CAP];

__global__ void zero_cnt_kernel() {
    int i = blockIdx.x * blockDim.x + threadIdx.x;
    if (i < 3 * CN0) g_cnt[i] = 0;
}

// ---------------- helpers ----------------
__device__ __forceinline__ unsigned f2tf(float f) {
    unsigned u;
    asm("cvt.rna.tf32.f32 %0, %1;" : "=r"(u) : "f"(f));
    return u;
}
__device__ __forceinline__ void mma_tf32(float d[4], const unsigned a[4], const unsigned b[2]) {
    asm volatile(
        "mma.sync.aligned.m16n8k8.row.col.f32.tf32.tf32.f32 "
        "{%0,%1,%2,%3}, {%4,%5,%6,%7}, {%8,%9}, {%0,%1,%2,%3};\n"
        : "+f"(d[0]), "+f"(d[1]), "+f"(d[2]), "+f"(d[3])
        : "r"(a[0]), "r"(a[1]), "r"(a[2]), "r"(a[3]), "r"(b[0]), "r"(b[1]));
}
__device__ __forceinline__ void cp_async16(void* smem_dst, const void* gmem_src) {
    unsigned s = (unsigned)__cvta_generic_to_shared(smem_dst);
    asm volatile("cp.async.ca.shared.global [%0], [%1], 16;\n" :: "r"(s), "l"(gmem_src));
}
__device__ __forceinline__ void cp_commit() {
    asm volatile("cp.async.commit_group;\n" ::: "memory");
}
template <int N>
__device__ __forceinline__ void cp_wait() {
    asm volatile("cp.async.wait_group %0;\n" :: "n"(N) : "memory");
}

// ============================================================================
// GEMM1 (tf32, cp.async 3-stage, dynamic smem): y = relu(X @ W1h + b1h)
// + fused a1/a2 dots. CTA tile 128x128, BK=16, 256 threads.
// grid: (12 = lvl*4+h, rowblocks)  -> adjacent bids share X tile in L2
// ============================================================================
__global__ __launch_bounds__(256, 2) void gemm1_kernel(
    const float* __restrict__ x0, const float* __restrict__ x1, const float* __restrict__ x2,
    const float* __restrict__ W1, const float* __restrict__ b1,
    const float* __restrict__ a1w, const float* __restrict__ a1b,
    const float* __restrict__ a2w, const float* __restrict__ a2b)
{
    extern __shared__ float smem_dyn[];
    float (*Asf)[128][A_STRIDE] = (float (*)[128][A_STRIDE])smem_dyn;
    float (*Bsf)[16][B_STRIDE]  = (float (*)[16][B_STRIDE])(smem_dyn + A_ELEMS);

    const int lh  = blockIdx.x;
    const int lvl = lh >> 2;
    const int h   = lh & 3;
    const int Nl  = (lvl == 0) ? CN0 : (lvl == 1) ? CN1 : CN2;
    const int row0 = blockIdx.y * 128;
    if (row0 >= Nl) return;

    const float* X = (lvl == 0) ? x0 : (lvl == 1) ? x1 : x2;
    float* out; int ldo;
    if (lvl == 0)      { out = g_cat + (size_t)h * CN0 * 512; ldo = 512; }
    else if (lvl == 1) { out = g_y1  + (size_t)h * CN1 * 128; ldo = 128; }
    else               { out = g_y2  + (size_t)h * CN2 * 128; ldo = 128; }
    const float* Wh = W1 + (size_t)h * D_IN * D_OUT;

    const int tid = threadIdx.x;
    const int lane = tid & 31;
    const int wid  = tid >> 5;
    const int wR = wid >> 2;
    const int wC = wid & 3;
    const int gid = lane >> 2;
    const int tg  = lane & 3;

    const int sA0 = tid, sA1 = tid + 256;
    const int mA0 = sA0 >> 2, kA0 = (sA0 & 3) * 4;
    const int mA1 = sA1 >> 2, kA1 = (sA1 & 3) * 4;
    const int kB0 = sA0 >> 5, nB0 = (sA0 & 31) * 4;
    const int kB1 = sA1 >> 5, nB1 = (sA1 & 31) * 4;
    const int grA0 = min(row0 + mA0, Nl - 1);
    const int grA1 = min(row0 + mA1, Nl - 1);

    float acc[4][4][4];
#pragma unroll
    for (int mt = 0; mt < 4; mt++)
#pragma unroll
        for (int nt = 0; nt < 4; nt++)
#pragma unroll
            for (int r = 0; r < 4; r++) acc[mt][nt][r] = 0.f;

    const int NT = D_IN / 16;   // 16

#define G1_ISSUE(kt, s) do {                                                   \
        int k0_ = (kt) * 16;                                                   \
        cp_async16(&Asf[s][mA0][kA0], X + (size_t)grA0 * D_IN + k0_ + kA0);    \
        cp_async16(&Asf[s][mA1][kA1], X + (size_t)grA1 * D_IN + k0_ + kA1);    \
        cp_async16(&Bsf[s][kB0][nB0], Wh + (size_t)(k0_ + kB0) * 128 + nB0);   \
        cp_async16(&Bsf[s][kB1][nB1], Wh + (size_t)(k0_ + kB1) * 128 + nB1);   \
        cp_commit();                                                           \
    } while (0)

    G1_ISSUE(0, 0);
    G1_ISSUE(1, 1);
    cp_wait<1>();
    __syncthreads();

    for (int kt = 0; kt < NT; kt++) {
        if (kt + 2 < NT) G1_ISSUE(kt + 2, (kt + 2) % 3);
        const int s = kt % 3;
#pragma unroll
        for (int ks = 0; ks < 2; ks++) {
            const int kb = ks * 8;
            unsigned af[4][4], bf[4][2];
#pragma unroll
            for (int mt = 0; mt < 4; mt++) {
                int rb = wR * 64 + mt * 16;
                af[mt][0] = f2tf(Asf[s][rb + gid][kb + tg]);
                af[mt][1] = f2tf(Asf[s][rb + gid + 8][kb + tg]);
                af[mt][2] = f2tf(Asf[s][rb + gid][kb + tg + 4]);
                af[mt][3] = f2tf(Asf[s][rb + gid + 8][kb + tg + 4]);
            }
#pragma unroll
            for (int nt = 0; nt < 4; nt++) {
                int cb = wC * 32 + nt * 8;
                bf[nt][0] = f2tf(Bsf[s][kb + tg][cb + gid]);
                bf[nt][1] = f2tf(Bsf[s][kb + tg + 4][cb + gid]);
            }
#pragma unroll
            for (int mt = 0; mt < 4; mt++)
#pragma unroll
                for (int nt = 0; nt < 4; nt++)
                    mma_tf32(acc[mt][nt], af[mt], bf[nt]);
        }
        if (kt + 1 < NT) {
            if (kt + 2 < NT) cp_wait<1>(); else cp_wait<0>();
            __syncthreads();
        }
    }
#undef G1_ISSUE

    // ---- epilogue: bias + relu + store + fused attention dots ----
    float* a2out = (lvl == 0) ? (g_a20 + h * CN0)
                 : (lvl == 1) ? (g_a21 + h * CN1)
                              : (g_a22 + h * CN2);
    const float a2bias = a2b[h];
    const float a1bias = a1b[h];

    float2 biasv[4], w2v[4], w1v[4];
#pragma unroll
    for (int nt = 0; nt < 4; nt++) {
        int c = wC * 32 + nt * 8 + 2 * tg;
        biasv[nt] = *(const float2*)(b1  + h * 128 + c);
        w2v[nt]   = *(const float2*)(a2w + h * 128 + c);
        w1v[nt]   = (lvl == 0) ? *(const float2*)(a1w + h * 128 + c) : make_float2(0.f, 0.f);
    }

    __shared__ float s_red[2][8][4][4];
#pragma unroll
    for (int mt = 0; mt < 4; mt++) {
        int r0 = row0 + wR * 64 + mt * 16 + gid;
        int r1 = r0 + 8;
        float s2a = 0.f, s2b = 0.f, s1a = 0.f, s1b = 0.f;
#pragma unroll
        for (int nt = 0; nt < 4; nt++) {
            int c = wC * 32 + nt * 8 + 2 * tg;
            float v0 = fmaxf(acc[mt][nt][0] + biasv[nt].x, 0.f);
            float v1 = fmaxf(acc[mt][nt][1] + biasv[nt].y, 0.f);
            float v2 = fmaxf(acc[mt][nt][2] + biasv[nt].x, 0.f);
            float v3 = fmaxf(acc[mt][nt][3] + biasv[nt].y, 0.f);
            if (r0 < Nl) *(float2*)(out + (size_t)r0 * ldo + c) = make_float2(v0, v1);
            if (r1 < Nl) *(float2*)(out + (size_t)r1 * ldo + c) = make_float2(v2, v3);
            s2a += v0 * w2v[nt].x + v1 * w2v[nt].y;
            s2b += v2 * w2v[nt].x + v3 * w2v[nt].y;
            if (lvl == 0) {
                s1a += v0 * w1v[nt].x + v1 * w1v[nt].y;
                s1b += v2 * w1v[nt].x + v3 * w1v[nt].y;
            }
        }
        s2a += __shfl_xor_sync(0xffffffffu, s2a, 1); s2a += __shfl_xor_sync(0xffffffffu, s2a, 2);
        s2b += __shfl_xor_sync(0xffffffffu, s2b, 1); s2b += __shfl_xor_sync(0xffffffffu, s2b, 2);
        if (lvl == 0) {
            s1a += __shfl_xor_sync(0xffffffffu, s1a, 1); s1a += __shfl_xor_sync(0xffffffffu, s1a, 2);
            s1b += __shfl_xor_sync(0xffffffffu, s1b, 1); s1b += __shfl_xor_sync(0xffffffffu, s1b, 2);
        }
        if (tg == 0) {
            s_red[wR][gid][wC][0] = s2a;
            s_red[wR][gid][wC][1] = s2b;
            s_red[wR][gid][wC][2] = s1a;
            s_red[wR][gid][wC][3] = s1b;
        }
        __syncthreads();
        if (tg == 0 && wC == 0) {
            float t2a = 0.f, t2b = 0.f, t1a = 0.f, t1b = 0.f;
#pragma unroll
            for (int q = 0; q < 4; q++) {
                t2a += s_red[wR][gid][q][0];
                t2b += s_red[wR][gid][q][1];
                t1a += s_red[wR][gid][q][2];
                t1b += s_red[wR][gid][q][3];
            }
            if (r0 < Nl) a2out[r0] = t2a + a2bias;
            if (r1 < Nl) a2out[r1] = t2b + a2bias;
            if (lvl == 0) {
                if (r0 < Nl) g_a1[h * CN0 + r0] = t1a + a1bias;
                if (r1 < Nl) g_a1[h * CN0 + r1] = t1b + a1bias;
            }
        }
        __syncthreads();
    }
}

// ---------------- bucket build ----------------
__global__ void bucket_kernel(
    const int* __restrict__ rows0, const int* __restrict__ cols0,
    const int* __restrict__ rows1, const int* __restrict__ cols1,
    const int* __restrict__ rows2, const int* __restrict__ cols2)
{
    int i = blockIdx.x * blockDim.x + threadIdx.x;
    int lvl, e;
    const int *rows, *cols;
    if (i < NNZ0)                    { lvl = 0; e = i;               rows = rows0; cols = cols0; }
    else if (i < NNZ0 + NNZ1)        { lvl = 1; e = i - NNZ0;        rows = rows1; cols = cols1; }
    else if (i < NNZ0 + NNZ1 + NNZ2) { lvl = 2; e = i - NNZ0 - NNZ1; rows = rows2; cols = cols2; }
    else return;
    int r = rows[e], c = cols[e];
    int pos = atomicAdd(&g_cnt[lvl * CN0 + r], 1);
    if (pos < CAP) g_list[(size_t)(lvl * CN0 + r) * CAP + pos] = c;
}

// ---------------- attention gather: decoupled two-phase, warp per (row,h,lvl) --
__global__ __launch_bounds__(256) void agg_kernel()
{
    __shared__ int   s_c[8][64];
    __shared__ float s_att[8][64];

    int w = (blockIdx.x * blockDim.x + threadIdx.x) >> 5;
    int wl = (threadIdx.x >> 5);
    int lane = threadIdx.x & 31;
    if (w >= 3 * HEADS * CN0) return;
    int lvl = w / (HEADS * CN0);
    int rem = w - lvl * (HEADS * CN0);
    int h   = rem / CN0;
    int row = rem - h * CN0;

    int n = g_cnt[lvl * CN0 + row];
    if (n > CAP) n = CAP;
    float a1v = g_a1[h * CN0 + row];

    const float* a2p; const float* yb; int ldy;
    if (lvl == 0)      { a2p = g_a20 + h * CN0; yb = g_cat + (size_t)h * CN0 * 512; ldy = 512; }
    else if (lvl == 1) { a2p = g_a21 + h * CN1; yb = g_y1  + (size_t)h * CN1 * 128; ldy = 128; }
    else               { a2p = g_a22 + h * CN2; yb = g_y2  + (size_t)h * CN2 * 128; ldy = 128; }

    const int* lst = g_list + (size_t)(lvl * CN0 + row) * CAP;
    float4 acc[4];
#pragma unroll
    for (int q = 0; q < 4; q++) acc[q] = make_float4(0.f, 0.f, 0.f, 0.f);

    for (int j0 = 0; j0 < n; j0 += 64) {
        int m = n - j0; if (m > 64) m = 64;
        __syncwarp();
        if (lane < m) {
            int c = lst[j0 + lane];
            float z = a1v + a2p[c];
            s_c[wl][lane] = c;
            s_att[wl][lane] = 1.f / (1.f + __expf(-z));
        }
        if (lane + 32 < m) {
            int c = lst[j0 + lane + 32];
            float z = a1v + a2p[c];
            s_c[wl][lane + 32] = c;
            s_att[wl][lane + 32] = 1.f / (1.f + __expf(-z));
        }
        __syncwarp();
        int i = 0;
        for (; i + 8 <= m; i += 8) {
            int cc[8]; float tt[8];
#pragma unroll
            for (int u = 0; u < 8; u++) { cc[u] = s_c[wl][i + u]; tt[u] = s_att[wl][i + u]; }
            float4 yv[8];
#pragma unroll
            for (int u = 0; u < 8; u++)
                yv[u] = *((const float4*)(yb + (size_t)cc[u] * ldy) + lane);
#pragma unroll
            for (int u = 0; u < 8; u++) {
                int q = u & 3;
                acc[q].x = fmaf(tt[u], yv[u].x, acc[q].x);
                acc[q].y = fmaf(tt[u], yv[u].y, acc[q].y);
                acc[q].z = fmaf(tt[u], yv[u].z, acc[q].z);
                acc[q].w = fmaf(tt[u], yv[u].w, acc[q].w);
            }
        }
        for (; i < m; i++) {
            int c = s_c[wl][i]; float t = s_att[wl][i];
            float4 yv = *((const float4*)(yb + (size_t)c * ldy) + lane);
            acc[0].x = fmaf(t, yv.x, acc[0].x);
            acc[0].y = fmaf(t, yv.y, acc[0].y);
            acc[0].z = fmaf(t, yv.z, acc[0].z);
            acc[0].w = fmaf(t, yv.w, acc[0].w);
        }
    }
    float4 r;
    r.x = (acc[0].x + acc[1].x) + (acc[2].x + acc[3].x);
    r.y = (acc[0].y + acc[1].y) + (acc[2].y + acc[3].y);
    r.z = (acc[0].z + acc[1].z) + (acc[2].z + acc[3].z);
    r.w = (acc[0].w + acc[1].w) + (acc[2].w + acc[3].w);
    *(float4*)(g_cat + (size_t)h * CN0 * 512 + (size_t)row * 512 + 128 + lvl * 128 + lane * 4) = r;
}

// ============================================================================
// GEMM2 (tf32, cp.async 3-stage, dynamic smem): out = mean_h(cat_h@Wagg_h + bagg_h)
// ============================================================================
__global__ __launch_bounds__(256, 2) void gemm2_kernel(
    const float* __restrict__ Wagg, const float* __restrict__ bagg,
    float* __restrict__ out)
{
    extern __shared__ float smem_dyn[];
    float (*Asf)[128][A_STRIDE] = (float (*)[128][A_STRIDE])smem_dyn;
    float (*Bsf)[16][B_STRIDE]  = (float (*)[16][B_STRIDE])(smem_dyn + A_ELEMS);

    const int row0 = blockIdx.x * 128;

    const int tid = threadIdx.x;
    const int lane = tid & 31;
    const int wid  = tid >> 5;
    const int wR = wid >> 2;
    const int wC = wid & 3;
    const int gid = lane >> 2;
    const int tg  = lane & 3;

    const int sA0 = tid, sA1 = tid + 256;
    const int mA0 = sA0 >> 2, kA0 = (sA0 & 3) * 4;
    const int mA1 = sA1 >> 2, kA1 = (sA1 & 3) * 4;
    const int kB0 = sA0 >> 5, nB0 = (sA0 & 31) * 4;
    const int kB1 = sA1 >> 5, nB1 = (sA1 & 31) * 4;
    const int grA0 = min(row0 + mA0, CN0 - 1);
    const int grA1 = min(row0 + mA1, CN0 - 1);

    float acc[4][4][4];
#pragma unroll
    for (int mt = 0; mt < 4; mt++)
#pragma unroll
        for (int nt = 0; nt < 4; nt++)
#pragma unroll
            for (int r = 0; r < 4; r++) acc[mt][nt][r] = 0.f;

    const int NT = 128;   // 4 heads * 512/16

#define G2_ISSUE(kt, s) do {                                                        \
        int t_ = (kt);                                                              \
        int h_ = t_ >> 5, k0_ = (t_ & 31) * 16;                                     \
        const float* A_  = g_cat + (size_t)h_ * CN0 * 512;                          \
        const float* Wh_ = Wagg + (size_t)h_ * 512 * 128;                           \
        cp_async16(&Asf[s][mA0][kA0], A_ + (size_t)grA0 * 512 + k0_ + kA0);         \
        cp_async16(&Asf[s][mA1][kA1], A_ + (size_t)grA1 * 512 + k0_ + kA1);         \
        cp_async16(&Bsf[s][kB0][nB0], Wh_ + (size_t)(k0_ + kB0) * 128 + nB0);       \
        cp_async16(&Bsf[s][kB1][nB1], Wh_ + (size_t)(k0_ + kB1) * 128 + nB1);       \
        cp_commit();                                                                \
    } while (0)

    G2_ISSUE(0, 0);
    G2_ISSUE(1, 1);
    cp_wait<1>();
    __syncthreads();

    for (int kt = 0; kt < NT; kt++) {
        if (kt + 2 < NT) G2_ISSUE(kt + 2, (kt + 2) % 3);
        const int s = kt % 3;
#pragma unroll
        for (int ks = 0; ks < 2; ks++) {
            const int kb = ks * 8;
            unsigned af[4][4], bf[4][2];
#pragma unroll
            for (int mt = 0; mt < 4; mt++) {
                int rb = wR * 64 + mt * 16;
                af[mt][0] = f2tf(Asf[s][rb + gid][kb + tg]);
                af[mt][1] = f2tf(Asf[s][rb + gid + 8][kb + tg]);
                af[mt][2] = f2tf(Asf[s][rb + gid][kb + tg + 4]);
                af[mt][3] = f2tf(Asf[s][rb + gid + 8][kb + tg + 4]);
            }
#pragma unroll
            for (int nt = 0; nt < 4; nt++) {
                int cb = wC * 32 + nt * 8;
                bf[nt][0] = f2tf(Bsf[s][kb + tg][cb + gid]);
                bf[nt][1] = f2tf(Bsf[s][kb + tg + 4][cb + gid]);
            }
#pragma unroll
            for (int mt = 0; mt < 4; mt++)
#pragma unroll
                for (int nt = 0; nt < 4; nt++)
                    mma_tf32(acc[mt][nt], af[mt], bf[nt]);
        }
        if (kt + 1 < NT) {
            if (kt + 2 < NT) cp_wait<1>(); else cp_wait<0>();
            __syncthreads();
        }
    }
#undef G2_ISSUE

    float2 bsum[4];
#pragma unroll
    for (int nt = 0; nt < 4; nt++) {
        int c = wC * 32 + nt * 8 + 2 * tg;
        float2 s = make_float2(0.f, 0.f);
#pragma unroll
        for (int h = 0; h < HEADS; h++) {
            float2 bg = *(const float2*)(bagg + h * 128 + c);
            s.x += bg.x; s.y += bg.y;
        }
        bsum[nt] = s;
    }
#pragma unroll
    for (int mt = 0; mt < 4; mt++) {
        int r0 = row0 + wR * 64 + mt * 16 + gid;
        int r1 = r0 + 8;
#pragma unroll
        for (int nt = 0; nt < 4; nt++) {
            int c = wC * 32 + nt * 8 + 2 * tg;
            if (r0 < CN0) {
                float2 v;
                v.x = (acc[mt][nt][0] + bsum[nt].x) * 0.25f;
                v.y = (acc[mt][nt][1] + bsum[nt].y) * 0.25f;
                *(float2*)(out + (size_t)r0 * 128 + c) = v;
            }
            if (r1 < CN0) {
                float2 v;
                v.x = (acc[mt][nt][2] + bsum[nt].x) * 0.25f;
                v.y = (acc[mt][nt][3] + bsum[nt].y) * 0.25f;
                *(float2*)(out + (size_t)r1 * 128 + c) = v;
            }
        }
    }
}

// ---------------- launch ----------------
extern "C" void kernel_launch(void* const* d_in, const int* in_sizes, int n_in,
                              void* d_out, int out_size)
{
    const float* x0    = (const float*)d_in[0];
    const float* x1    = (const float*)d_in[1];
    const float* x2    = (const float*)d_in[2];
    const int*   rows0 = (const int*)d_in[3];
    const int*   cols0 = (const int*)d_in[4];
    const int*   rows1 = (const int*)d_in[5];
    const int*   cols1 = (const int*)d_in[6];
    const int*   rows2 = (const int*)d_in[7];
    const int*   cols2 = (const int*)d_in[8];
    const float* W1    = (const float*)d_in[9];
    const float* b1    = (const float*)d_in[10];
    const float* a1w   = (const float*)d_in[11];
    const float* a1b   = (const float*)d_in[12];
    const float* a2w   = (const float*)d_in[13];
    const float* a2b   = (const float*)d_in[14];
    const float* Wagg  = (const float*)d_in[15];
    const float* bagg  = (const float*)d_in[16];
    float* out = (float*)d_out;

    // opt in to >48KB dynamic smem (immediate host API, not a stream op;
    // deterministic and graph-capture-safe)
    cudaFuncSetAttribute(gemm1_kernel, cudaFuncAttributeMaxDynamicSharedMemorySize, GEMM_SMEM_BYTES);
    cudaFuncSetAttribute(gemm2_kernel, cudaFuncAttributeMaxDynamicSharedMemorySize, GEMM_SMEM_BYTES);

    zero_cnt_kernel<<<(3 * CN0 + 255) / 256, 256>>>();
    bucket_kernel<<<(NNZ0 + NNZ1 + NNZ2 + 255) / 256, 256>>>(
        rows0, cols0, rows1, cols1, rows2, cols2);

    {
        dim3 grid(12, (CN1 + 127) / 128);   // x = lvl*4+h, y = rowblock
        gemm1_kernel<<<grid, 256, GEMM_SMEM_BYTES>>>(x0, x1, x2, W1, b1, a1w, a1b, a2w, a2b);
    }
    {
        int warps = 3 * HEADS * CN0;
        agg_kernel<<<(warps * 32 + 255) / 256, 256>>>();
    }
    gemm2_kernel<<<(CN0 + 127) / 128, 256, GEMM_SMEM_BYTES>>>(Wagg, bagg, out);
}

// round 6
// speedup vs baseline: 2.3275x; 1.0483x over previous
#include <cuda_runtime.h>
#include <cuda_fp16.h>
#include <math.h>

#define CN0 30000
#define CN1 90000
#define CN2 60000
#define D_IN 256
#define D_OUT 128
#define HEADS 4
#define NNZ0 960000
#define NNZ1 180000
#define NNZ2 180000
#define CAP 256

// dynamic smem layout for the GEMMs
#define A_STRIDE 20
#define B_STRIDE 132
#define A_ELEMS (3 * 128 * A_STRIDE)
#define B_ELEMS (3 * 16 * B_STRIDE)
#define GEMM_SMEM_BYTES ((A_ELEMS + B_ELEMS) * 4)

// ---------------- scratch ----------------
__device__ __half g_y0h[HEADS * CN0 * D_OUT];      // fp16 gather copies
__device__ __half g_y1h[HEADS * CN1 * D_OUT];
__device__ __half g_y2h[HEADS * CN2 * D_OUT];
__device__ float g_cat[HEADS * CN0 * 4 * D_OUT];   // [h][row][ xi0 | agg0 | agg1 | agg2 ]
__device__ float g_a1[HEADS * CN0];
__device__ float g_a20[HEADS * CN0];
__device__ float g_a21[HEADS * CN1];
__device__ float g_a22[HEADS * CN2];
__device__ int   g_cnt[3 * CN0];
__device__ int   g_list[3 * CN0 * CAP];

__global__ void zero_cnt_kernel() {
    int i = blockIdx.x * blockDim.x + threadIdx.x;
    if (i < 3 * CN0) g_cnt[i] = 0;
}

// ---------------- helpers ----------------
__device__ __forceinline__ unsigned f2tf(float f) {
    unsigned u;
    asm("cvt.rna.tf32.f32 %0, %1;" : "=r"(u) : "f"(f));
    return u;
}
__device__ __forceinline__ void mma_tf32(float d[4], const unsigned a[4], const unsigned b[2]) {
    asm volatile(
        "mma.sync.aligned.m16n8k8.row.col.f32.tf32.tf32.f32 "
        "{%0,%1,%2,%3}, {%4,%5,%6,%7}, {%8,%9}, {%0,%1,%2,%3};\n"
        : "+f"(d[0]), "+f"(d[1]), "+f"(d[2]), "+f"(d[3])
        : "r"(a[0]), "r"(a[1]), "r"(a[2]), "r"(a[3]), "r"(b[0]), "r"(b[1]));
}
__device__ __forceinline__ void cp_async16(void* smem_dst, const void* gmem_src) {
    unsigned s = (unsigned)__cvta_generic_to_shared(smem_dst);
    asm volatile("cp.async.ca.shared.global [%0], [%1], 16;\n" :: "r"(s), "l"(gmem_src));
}
__device__ __forceinline__ void cp_commit() {
    asm volatile("cp.async.commit_group;\n" ::: "memory");
}
template <int N>
__device__ __forceinline__ void cp_wait() {
    asm volatile("cp.async.wait_group %0;\n" :: "n"(N) : "memory");
}

// ============================================================================
// GEMM1 (tf32, cp.async 3-stage): y = relu(X @ W1h + b1h), fused a1/a2 dots
// fp32 xi0 -> g_cat (for gemm2); fp16 copies of all levels for the gather.
// grid: (12 = lvl*4+h, rowblocks)
// ============================================================================
__global__ __launch_bounds__(256, 2) void gemm1_kernel(
    const float* __restrict__ x0, const float* __restrict__ x1, const float* __restrict__ x2,
    const float* __restrict__ W1, const float* __restrict__ b1,
    const float* __restrict__ a1w, const float* __restrict__ a1b,
    const float* __restrict__ a2w, const float* __restrict__ a2b)
{
    extern __shared__ float smem_dyn[];
    float (*Asf)[128][A_STRIDE] = (float (*)[128][A_STRIDE])smem_dyn;
    float (*Bsf)[16][B_STRIDE]  = (float (*)[16][B_STRIDE])(smem_dyn + A_ELEMS);

    const int lh  = blockIdx.x;
    const int lvl = lh >> 2;
    const int h   = lh & 3;
    const int Nl  = (lvl == 0) ? CN0 : (lvl == 1) ? CN1 : CN2;
    const int row0 = blockIdx.y * 128;
    if (row0 >= Nl) return;

    const float* X = (lvl == 0) ? x0 : (lvl == 1) ? x1 : x2;
    __half* outh = (lvl == 0) ? (g_y0h + (size_t)h * CN0 * 128)
                 : (lvl == 1) ? (g_y1h + (size_t)h * CN1 * 128)
                              : (g_y2h + (size_t)h * CN2 * 128);
    float* outf = (lvl == 0) ? (g_cat + (size_t)h * CN0 * 512) : 0;  // fp32 xi0 only
    const float* Wh = W1 + (size_t)h * D_IN * D_OUT;

    const int tid = threadIdx.x;
    const int lane = tid & 31;
    const int wid  = tid >> 5;
    const int wR = wid >> 2;
    const int wC = wid & 3;
    const int gid = lane >> 2;
    const int tg  = lane & 3;

    const int sA0 = tid, sA1 = tid + 256;
    const int mA0 = sA0 >> 2, kA0 = (sA0 & 3) * 4;
    const int mA1 = sA1 >> 2, kA1 = (sA1 & 3) * 4;
    const int kB0 = sA0 >> 5, nB0 = (sA0 & 31) * 4;
    const int kB1 = sA1 >> 5, nB1 = (sA1 & 31) * 4;
    const int grA0 = min(row0 + mA0, Nl - 1);
    const int grA1 = min(row0 + mA1, Nl - 1);

    float acc[4][4][4];
#pragma unroll
    for (int mt = 0; mt < 4; mt++)
#pragma unroll
        for (int nt = 0; nt < 4; nt++)
#pragma unroll
            for (int r = 0; r < 4; r++) acc[mt][nt][r] = 0.f;

    const int NT = D_IN / 16;   // 16

#define G1_ISSUE(kt, s) do {                                                   \
        int k0_ = (kt) * 16;                                                   \
        cp_async16(&Asf[s][mA0][kA0], X + (size_t)grA0 * D_IN + k0_ + kA0);    \
        cp_async16(&Asf[s][mA1][kA1], X + (size_t)grA1 * D_IN + k0_ + kA1);    \
        cp_async16(&Bsf[s][kB0][nB0], Wh + (size_t)(k0_ + kB0) * 128 + nB0);   \
        cp_async16(&Bsf[s][kB1][nB1], Wh + (size_t)(k0_ + kB1) * 128 + nB1);   \
        cp_commit();                                                           \
    } while (0)

    G1_ISSUE(0, 0);
    G1_ISSUE(1, 1);
    cp_wait<1>();
    __syncthreads();

    for (int kt = 0; kt < NT; kt++) {
        if (kt + 2 < NT) G1_ISSUE(kt + 2, (kt + 2) % 3);
        const int s = kt % 3;
#pragma unroll
        for (int ks = 0; ks < 2; ks++) {
            const int kb = ks * 8;
            unsigned af[4][4], bf[4][2];
#pragma unroll
            for (int mt = 0; mt < 4; mt++) {
                int rb = wR * 64 + mt * 16;
                af[mt][0] = f2tf(Asf[s][rb + gid][kb + tg]);
                af[mt][1] = f2tf(Asf[s][rb + gid + 8][kb + tg]);
                af[mt][2] = f2tf(Asf[s][rb + gid][kb + tg + 4]);
                af[mt][3] = f2tf(Asf[s][rb + gid + 8][kb + tg + 4]);
            }
#pragma unroll
            for (int nt = 0; nt < 4; nt++) {
                int cb = wC * 32 + nt * 8;
                bf[nt][0] = f2tf(Bsf[s][kb + tg][cb + gid]);
                bf[nt][1] = f2tf(Bsf[s][kb + tg + 4][cb + gid]);
            }
#pragma unroll
            for (int mt = 0; mt < 4; mt++)
#pragma unroll
                for (int nt = 0; nt < 4; nt++)
                    mma_tf32(acc[mt][nt], af[mt], bf[nt]);
        }
        if (kt + 1 < NT) {
            if (kt + 2 < NT) cp_wait<1>(); else cp_wait<0>();
            __syncthreads();
        }
    }
#undef G1_ISSUE

    // ---- epilogue: bias + relu + stores + fused attention dots ----
    float* a2out = (lvl == 0) ? (g_a20 + h * CN0)
                 : (lvl == 1) ? (g_a21 + h * CN1)
                              : (g_a22 + h * CN2);
    const float a2bias = a2b[h];
    const float a1bias = a1b[h];

    float2 biasv[4], w2v[4], w1v[4];
#pragma unroll
    for (int nt = 0; nt < 4; nt++) {
        int c = wC * 32 + nt * 8 + 2 * tg;
        biasv[nt] = *(const float2*)(b1  + h * 128 + c);
        w2v[nt]   = *(const float2*)(a2w + h * 128 + c);
        w1v[nt]   = (lvl == 0) ? *(const float2*)(a1w + h * 128 + c) : make_float2(0.f, 0.f);
    }

    __shared__ float s_red[2][8][4][4];
#pragma unroll
    for (int mt = 0; mt < 4; mt++) {
        int r0 = row0 + wR * 64 + mt * 16 + gid;
        int r1 = r0 + 8;
        float s2a = 0.f, s2b = 0.f, s1a = 0.f, s1b = 0.f;
#pragma unroll
        for (int nt = 0; nt < 4; nt++) {
            int c = wC * 32 + nt * 8 + 2 * tg;
            float v0 = fmaxf(acc[mt][nt][0] + biasv[nt].x, 0.f);
            float v1 = fmaxf(acc[mt][nt][1] + biasv[nt].y, 0.f);
            float v2 = fmaxf(acc[mt][nt][2] + biasv[nt].x, 0.f);
            float v3 = fmaxf(acc[mt][nt][3] + biasv[nt].y, 0.f);
            if (r0 < Nl) {
                *(__half2*)(outh + (size_t)r0 * 128 + c) = __floats2half2_rn(v0, v1);
                if (lvl == 0) *(float2*)(outf + (size_t)r0 * 512 + c) = make_float2(v0, v1);
            }
            if (r1 < Nl) {
                *(__half2*)(outh + (size_t)r1 * 128 + c) = __floats2half2_rn(v2, v3);
                if (lvl == 0) *(float2*)(outf + (size_t)r1 * 512 + c) = make_float2(v2, v3);
            }
            s2a += v0 * w2v[nt].x + v1 * w2v[nt].y;
            s2b += v2 * w2v[nt].x + v3 * w2v[nt].y;
            if (lvl == 0) {
                s1a += v0 * w1v[nt].x + v1 * w1v[nt].y;
                s1b += v2 * w1v[nt].x + v3 * w1v[nt].y;
            }
        }
        s2a += __shfl_xor_sync(0xffffffffu, s2a, 1); s2a += __shfl_xor_sync(0xffffffffu, s2a, 2);
        s2b += __shfl_xor_sync(0xffffffffu, s2b, 1); s2b += __shfl_xor_sync(0xffffffffu, s2b, 2);
        if (lvl == 0) {
            s1a += __shfl_xor_sync(0xffffffffu, s1a, 1); s1a += __shfl_xor_sync(0xffffffffu, s1a, 2);
            s1b += __shfl_xor_sync(0xffffffffu, s1b, 1); s1b += __shfl_xor_sync(0xffffffffu, s1b, 2);
        }
        if (tg == 0) {
            s_red[wR][gid][wC][0] = s2a;
            s_red[wR][gid][wC][1] = s2b;
            s_red[wR][gid][wC][2] = s1a;
            s_red[wR][gid][wC][3] = s1b;
        }
        __syncthreads();
        if (tg == 0 && wC == 0) {
            float t2a = 0.f, t2b = 0.f, t1a = 0.f, t1b = 0.f;
#pragma unroll
            for (int q = 0; q < 4; q++) {
                t2a += s_red[wR][gid][q][0];
                t2b += s_red[wR][gid][q][1];
                t1a += s_red[wR][gid][q][2];
                t1b += s_red[wR][gid][q][3];
            }
            if (r0 < Nl) a2out[r0] = t2a + a2bias;
            if (r1 < Nl) a2out[r1] = t2b + a2bias;
            if (lvl == 0) {
                if (r0 < Nl) g_a1[h * CN0 + r0] = t1a + a1bias;
                if (r1 < Nl) g_a1[h * CN0 + r1] = t1b + a1bias;
            }
        }
        __syncthreads();
    }
}

// ---------------- bucket build ----------------
__global__ void bucket_kernel(
    const int* __restrict__ rows0, const int* __restrict__ cols0,
    const int* __restrict__ rows1, const int* __restrict__ cols1,
    const int* __restrict__ rows2, const int* __restrict__ cols2)
{
    int i = blockIdx.x * blockDim.x + threadIdx.x;
    int lvl, e;
    const int *rows, *cols;
    if (i < NNZ0)                    { lvl = 0; e = i;               rows = rows0; cols = cols0; }
    else if (i < NNZ0 + NNZ1)        { lvl = 1; e = i - NNZ0;        rows = rows1; cols = cols1; }
    else if (i < NNZ0 + NNZ1 + NNZ2) { lvl = 2; e = i - NNZ0 - NNZ1; rows = rows2; cols = cols2; }
    else return;
    int r = rows[e], c = cols[e];
    int pos = atomicAdd(&g_cnt[lvl * CN0 + r], 1);
    if (pos < CAP) g_list[(size_t)(lvl * CN0 + r) * CAP + pos] = c;
}

// ---------------- attention gather (fp16 y): two-phase, warp per (row,h,lvl) --
__global__ __launch_bounds__(256) void agg_kernel()
{
    __shared__ int   s_c[8][64];
    __shared__ float s_att[8][64];

    int w = (blockIdx.x * blockDim.x + threadIdx.x) >> 5;
    int wl = (threadIdx.x >> 5);
    int lane = threadIdx.x & 31;
    if (w >= 3 * HEADS * CN0) return;
    int lvl = w / (HEADS * CN0);
    int rem = w - lvl * (HEADS * CN0);
    int h   = rem / CN0;
    int row = rem - h * CN0;

    int n = g_cnt[lvl * CN0 + row];
    if (n > CAP) n = CAP;
    float a1v = g_a1[h * CN0 + row];

    const float* a2p; const __half* yb;
    if (lvl == 0)      { a2p = g_a20 + h * CN0; yb = g_y0h + (size_t)h * CN0 * 128; }
    else if (lvl == 1) { a2p = g_a21 + h * CN1; yb = g_y1h + (size_t)h * CN1 * 128; }
    else               { a2p = g_a22 + h * CN2; yb = g_y2h + (size_t)h * CN2 * 128; }

    const int* lst = g_list + (size_t)(lvl * CN0 + row) * CAP;
    float4 acc[4];
#pragma unroll
    for (int q = 0; q < 4; q++) acc[q] = make_float4(0.f, 0.f, 0.f, 0.f);

    for (int j0 = 0; j0 < n; j0 += 64) {
        int m = n - j0; if (m > 64) m = 64;
        __syncwarp();
        if (lane < m) {
            int c = lst[j0 + lane];
            float z = a1v + a2p[c];
            s_c[wl][lane] = c;
            s_att[wl][lane] = 1.f / (1.f + __expf(-z));
        }
        if (lane + 32 < m) {
            int c = lst[j0 + lane + 32];
            float z = a1v + a2p[c];
            s_c[wl][lane + 32] = c;
            s_att[wl][lane + 32] = 1.f / (1.f + __expf(-z));
        }
        __syncwarp();
        int i = 0;
        for (; i + 8 <= m; i += 8) {
            int cc[8]; float tt[8];
#pragma unroll
            for (int u = 0; u < 8; u++) { cc[u] = s_c[wl][i + u]; tt[u] = s_att[wl][i + u]; }
            uint2 yv[8];
#pragma unroll
            for (int u = 0; u < 8; u++)
                yv[u] = *((const uint2*)(yb + (size_t)cc[u] * 128) + lane);
#pragma unroll
            for (int u = 0; u < 8; u++) {
                float2 f0 = __half22float2(*(__half2*)&yv[u].x);
                float2 f1 = __half22float2(*(__half2*)&yv[u].y);
                int q = u & 3;
                acc[q].x = fmaf(tt[u], f0.x, acc[q].x);
                acc[q].y = fmaf(tt[u], f0.y, acc[q].y);
                acc[q].z = fmaf(tt[u], f1.x, acc[q].z);
                acc[q].w = fmaf(tt[u], f1.y, acc[q].w);
            }
        }
        for (; i < m; i++) {
            int c = s_c[wl][i]; float t = s_att[wl][i];
            uint2 yv = *((const uint2*)(yb + (size_t)c * 128) + lane);
            float2 f0 = __half22float2(*(__half2*)&yv.x);
            float2 f1 = __half22float2(*(__half2*)&yv.y);
            acc[0].x = fmaf(t, f0.x, acc[0].x);
            acc[0].y = fmaf(t, f0.y, acc[0].y);
            acc[0].z = fmaf(t, f1.x, acc[0].z);
            acc[0].w = fmaf(t, f1.y, acc[0].w);
        }
    }
    float4 r;
    r.x = (acc[0].x + acc[1].x) + (acc[2].x + acc[3].x);
    r.y = (acc[0].y + acc[1].y) + (acc[2].y + acc[3].y);
    r.z = (acc[0].z + acc[1].z) + (acc[2].z + acc[3].z);
    r.w = (acc[0].w + acc[1].w) + (acc[2].w + acc[3].w);
    *(float4*)(g_cat + (size_t)h * CN0 * 512 + (size_t)row * 512 + 128 + lvl * 128 + lane * 4) = r;
}

// ============================================================================
// GEMM2 (tf32, cp.async 3-stage): out = mean_h(cat_h @ Wagg_h + bagg_h)
// ============================================================================
__global__ __launch_bounds__(256, 2) void gemm2_kernel(
    const float* __restrict__ Wagg, const float* __restrict__ bagg,
    float* __restrict__ out)
{
    extern __shared__ float smem_dyn[];
    float (*Asf)[128][A_STRIDE] = (float (*)[128][A_STRIDE])smem_dyn;
    float (*Bsf)[16][B_STRIDE]  = (float (*)[16][B_STRIDE])(smem_dyn + A_ELEMS);

    const int row0 = blockIdx.x * 128;

    const int tid = threadIdx.x;
    const int lane = tid & 31;
    const int wid  = tid >> 5;
    const int wR = wid >> 2;
    const int wC = wid & 3;
    const int gid = lane >> 2;
    const int tg  = lane & 3;

    const int sA0 = tid, sA1 = tid + 256;
    const int mA0 = sA0 >> 2, kA0 = (sA0 & 3) * 4;
    const int mA1 = sA1 >> 2, kA1 = (sA1 & 3) * 4;
    const int kB0 = sA0 >> 5, nB0 = (sA0 & 31) * 4;
    const int kB1 = sA1 >> 5, nB1 = (sA1 & 31) * 4;
    const int grA0 = min(row0 + mA0, CN0 - 1);
    const int grA1 = min(row0 + mA1, CN0 - 1);

    float acc[4][4][4];
#pragma unroll
    for (int mt = 0; mt < 4; mt++)
#pragma unroll
        for (int nt = 0; nt < 4; nt++)
#pragma unroll
            for (int r = 0; r < 4; r++) acc[mt][nt][r] = 0.f;

    const int NT = 128;

#define G2_ISSUE(kt, s) do {                                                        \
        int t_ = (kt);                                                              \
        int h_ = t_ >> 5, k0_ = (t_ & 31) * 16;                                     \
        const float* A_  = g_cat + (size_t)h_ * CN0 * 512;                          \
        const float* Wh_ = Wagg + (size_t)h_ * 512 * 128;                           \
        cp_async16(&Asf[s][mA0][kA0], A_ + (size_t)grA0 * 512 + k0_ + kA0);         \
        cp_async16(&Asf[s][mA1][kA1], A_ + (size_t)grA1 * 512 + k0_ + kA1);         \
        cp_async16(&Bsf[s][kB0][nB0], Wh_ + (size_t)(k0_ + kB0) * 128 + nB0);       \
        cp_async16(&Bsf[s][kB1][nB1], Wh_ + (size_t)(k0_ + kB1) * 128 + nB1);       \
        cp_commit();                                                                \
    } while (0)

    G2_ISSUE(0, 0);
    G2_ISSUE(1, 1);
    cp_wait<1>();
    __syncthreads();

    for (int kt = 0; kt < NT; kt++) {
        if (kt + 2 < NT) G2_ISSUE(kt + 2, (kt + 2) % 3);
        const int s = kt % 3;
#pragma unroll
        for (int ks = 0; ks < 2; ks++) {
            const int kb = ks * 8;
            unsigned af[4][4], bf[4][2];
#pragma unroll
            for (int mt = 0; mt < 4; mt++) {
                int rb = wR * 64 + mt * 16;
                af[mt][0] = f2tf(Asf[s][rb + gid][kb + tg]);
                af[mt][1] = f2tf(Asf[s][rb + gid + 8][kb + tg]);
                af[mt][2] = f2tf(Asf[s][rb + gid][kb + tg + 4]);
                af[mt][3] = f2tf(Asf[s][rb + gid + 8][kb + tg + 4]);
            }
#pragma unroll
            for (int nt = 0; nt < 4; nt++) {
                int cb = wC * 32 + nt * 8;
                bf[nt][0] = f2tf(Bsf[s][kb + tg][cb + gid]);
                bf[nt][1] = f2tf(Bsf[s][kb + tg + 4][cb + gid]);
            }
#pragma unroll
            for (int mt = 0; mt < 4; mt++)
#pragma unroll
                for (int nt = 0; nt < 4; nt++)
                    mma_tf32(acc[mt][nt], af[mt], bf[nt]);
        }
        if (kt + 1 < NT) {
            if (kt + 2 < NT) cp_wait<1>(); else cp_wait<0>();
            __syncthreads();
        }
    }
#undef G2_ISSUE

    float2 bsum[4];
#pragma unroll
    for (int nt = 0; nt < 4; nt++) {
        int c = wC * 32 + nt * 8 + 2 * tg;
        float2 s = make_float2(0.f, 0.f);
#pragma unroll
        for (int h = 0; h < HEADS; h++) {
            float2 bg = *(const float2*)(bagg + h * 128 + c);
            s.x += bg.x; s.y += bg.y;
        }
        bsum[nt] = s;
    }
#pragma unroll
    for (int mt = 0; mt < 4; mt++) {
        int r0 = row0 + wR * 64 + mt * 16 + gid;
        int r1 = r0 + 8;
#pragma unroll
        for (int nt = 0; nt < 4; nt++) {
            int c = wC * 32 + nt * 8 + 2 * tg;
            if (r0 < CN0) {
                float2 v;
                v.x = (acc[mt][nt][0] + bsum[nt].x) * 0.25f;
                v.y = (acc[mt][nt][1] + bsum[nt].y) * 0.25f;
                *(float2*)(out + (size_t)r0 * 128 + c) = v;
            }
            if (r1 < CN0) {
                float2 v;
                v.x = (acc[mt][nt][2] + bsum[nt].x) * 0.25f;
                v.y = (acc[mt][nt][3] + bsum[nt].y) * 0.25f;
                *(float2*)(out + (size_t)r1 * 128 + c) = v;
            }
        }
    }
}

// ---------------- launch ----------------
extern "C" void kernel_launch(void* const* d_in, const int* in_sizes, int n_in,
                              void* d_out, int out_size)
{
    const float* x0    = (const float*)d_in[0];
    const float* x1    = (const float*)d_in[1];
    const float* x2    = (const float*)d_in[2];
    const int*   rows0 = (const int*)d_in[3];
    const int*   cols0 = (const int*)d_in[4];
    const int*   rows1 = (const int*)d_in[5];
    const int*   cols1 = (const int*)d_in[6];
    const int*   rows2 = (const int*)d_in[7];
    const int*   cols2 = (const int*)d_in[8];
    const float* W1    = (const float*)d_in[9];
    const float* b1    = (const float*)d_in[10];
    const float* a1w   = (const float*)d_in[11];
    const float* a1b   = (const float*)d_in[12];
    const float* a2w   = (const float*)d_in[13];
    const float* a2b   = (const float*)d_in[14];
    const float* Wagg  = (const float*)d_in[15];
    const float* bagg  = (const float*)d_in[16];
    float* out = (float*)d_out;

    cudaFuncSetAttribute(gemm1_kernel, cudaFuncAttributeMaxDynamicSharedMemorySize, GEMM_SMEM_BYTES);
    cudaFuncSetAttribute(gemm2_kernel, cudaFuncAttributeMaxDynamicSharedMemorySize, GEMM_SMEM_BYTES);

    zero_cnt_kernel<<<(3 * CN0 + 255) / 256, 256>>>();
    bucket_kernel<<<(NNZ0 + NNZ1 + NNZ2 + 255) / 256, 256>>>(
        rows0, cols0, rows1, cols1, rows2, cols2);

    {
        dim3 grid(12, (CN1 + 127) / 128);
        gemm1_kernel<<<grid, 256, GEMM_SMEM_BYTES>>>(x0, x1, x2, W1, b1, a1w, a1b, a2w, a2b);
    }
    {
        int warps = 3 * HEADS * CN0;
        agg_kernel<<<(warps * 32 + 255) / 256, 256>>>();
    }
    gemm2_kernel<<<(CN0 + 127) / 128, 256, GEMM_SMEM_BYTES>>>(Wagg, bagg, out);
}

// round 7
// speedup vs baseline: 3.0782x; 1.3225x over previous
#include <cuda_runtime.h>
#include <cuda_fp16.h>
#include <math.h>

#define CN0 30000
#define CN1 90000
#define CN2 60000
#define D_IN 256
#define D_OUT 128
#define HEADS 4
#define NNZ0 960000
#define NNZ1 180000
#define NNZ2 180000
#define CAP 256

// fp16 GEMM smem: 3-stage, A[128][40] + B[128][40] halves per stage
#define H_STRIDE 40
#define AH_ELEMS (3 * 128 * H_STRIDE)
#define GEMM_SMEM_BYTES (2 * AH_ELEMS * 2)

#define NXH ((size_t)(CN0 + CN1 + CN2) * 256)

// ---------------- scratch ----------------
__device__ __half g_xh[NXH];                        // fp16 inputs (x0|x1|x2)
__device__ __half g_w1h[HEADS * 256 * 128];         // W1 transposed  [h][n][k]
__device__ __half g_waggh[HEADS * 512 * 128];       // Wagg transposed [h][n][k]
__device__ __half g_y1h[HEADS * CN1 * D_OUT];       // relu(x1 W1 + b1), fp16
__device__ __half g_y2h[HEADS * CN2 * D_OUT];
__device__ __half g_cath[HEADS * CN0 * 4 * D_OUT];  // [h][row][ xi0 | agg0 | agg1 | agg2 ] fp16
__device__ float g_a1[HEADS * CN0];
__device__ float g_a20[HEADS * CN0];
__device__ float g_a21[HEADS * CN1];
__device__ float g_a22[HEADS * CN2];
__device__ int   g_cnt[3 * CN0];
__device__ int   g_list[3 * CN0 * CAP];

__global__ void zero_cnt_kernel() {
    int i = blockIdx.x * blockDim.x + threadIdx.x;
    if (i < 3 * CN0) g_cnt[i] = 0;
}

// ---------------- converts ----------------
__global__ void cvt_x_kernel(const float* __restrict__ x0, const float* __restrict__ x1,
                             const float* __restrict__ x2) {
    size_t i = (size_t)blockIdx.x * 256 + threadIdx.x;      // one float4 each
    if (i >= NXH / 4) return;
    size_t e = i * 4;
    const float* src; size_t base;
    if (e < (size_t)CN0 * 256)               { src = x0; base = 0; }
    else if (e < (size_t)(CN0 + CN1) * 256)  { src = x1; base = (size_t)CN0 * 256; }
    else                                     { src = x2; base = (size_t)(CN0 + CN1) * 256; }
    float4 v = *(const float4*)(src + (e - base));
    __half2 h0 = __floats2half2_rn(v.x, v.y);
    __half2 h1 = __floats2half2_rn(v.z, v.w);
    uint2 u; u.x = *(unsigned*)&h0; u.y = *(unsigned*)&h1;
    *(uint2*)(g_xh + e) = u;
}

__global__ void cvt_w_kernel(const float* __restrict__ W1, const float* __restrict__ Wagg) {
    int i = blockIdx.x * 256 + threadIdx.x;
    const int NW1 = HEADS * 256 * 128;
    const int NWA = HEADS * 512 * 128;
    if (i < NW1) {
        int h = i / (256 * 128), r = (i / 128) % 256, c = i % 128;
        g_w1h[h * 256 * 128 + c * 256 + r] = __float2half(W1[i]);
    } else if (i < NW1 + NWA) {
        int j = i - NW1;
        int h = j / (512 * 128), r = (j / 128) % 512, c = j % 128;
        g_waggh[h * 512 * 128 + c * 512 + r] = __float2half(Wagg[j]);
    }
}

// ---------------- mma/cp helpers ----------------
__device__ __forceinline__ void mma_f16(float d[4], const unsigned a[4], const unsigned b[2]) {
    asm volatile(
        "mma.sync.aligned.m16n8k16.row.col.f32.f16.f16.f32 "
        "{%0,%1,%2,%3}, {%4,%5,%6,%7}, {%8,%9}, {%0,%1,%2,%3};\n"
        : "+f"(d[0]), "+f"(d[1]), "+f"(d[2]), "+f"(d[3])
        : "r"(a[0]), "r"(a[1]), "r"(a[2]), "r"(a[3]), "r"(b[0]), "r"(b[1]));
}
__device__ __forceinline__ void cp_async16(void* smem_dst, const void* gmem_src) {
    unsigned s = (unsigned)__cvta_generic_to_shared(smem_dst);
    asm volatile("cp.async.ca.shared.global [%0], [%1], 16;\n" :: "r"(s), "l"(gmem_src));
}
__device__ __forceinline__ void cp_commit() {
    asm volatile("cp.async.commit_group;\n" ::: "memory");
}
template <int N>
__device__ __forceinline__ void cp_wait() {
    asm volatile("cp.async.wait_group %0;\n" :: "n"(N) : "memory");
}

// ============================================================================
// GEMM1 (fp16 m16n8k16, cp.async 3-stage): y = relu(X @ W1h + b1h) + a1/a2 dots
// CTA 128x128, BK=32, 256 threads; grid (12 = lvl*4+h, rowblocks)
// ============================================================================
__global__ __launch_bounds__(256, 2) void gemm1_kernel(
    const float* __restrict__ b1,
    const float* __restrict__ a1w, const float* __restrict__ a1b,
    const float* __restrict__ a2w, const float* __restrict__ a2b)
{
    extern __shared__ __half smem_h[];
    __half (*As)[128][H_STRIDE] = (__half (*)[128][H_STRIDE])smem_h;
    __half (*Bs)[128][H_STRIDE] = (__half (*)[128][H_STRIDE])(smem_h + AH_ELEMS);

    const int lh  = blockIdx.x;
    const int lvl = lh >> 2;
    const int h   = lh & 3;
    const int Nl  = (lvl == 0) ? CN0 : (lvl == 1) ? CN1 : CN2;
    const int row0 = blockIdx.y * 128;
    if (row0 >= Nl) return;

    const __half* Xh = g_xh + ((lvl == 0) ? 0 : (lvl == 1) ? (size_t)CN0 * 256
                                                           : (size_t)(CN0 + CN1) * 256);
    const __half* Wh = g_w1h + (size_t)h * 256 * 128;
    __half* outh; int ldo;
    if (lvl == 0)      { outh = g_cath + (size_t)h * CN0 * 512; ldo = 512; }
    else if (lvl == 1) { outh = g_y1h  + (size_t)h * CN1 * 128; ldo = 128; }
    else               { outh = g_y2h  + (size_t)h * CN2 * 128; ldo = 128; }

    const int tid = threadIdx.x;
    const int lane = tid & 31;
    const int wid  = tid >> 5;
    const int wR = wid >> 2;          // 0..1
    const int wC = wid & 3;           // 0..3
    const int gid = lane >> 2;        // 0..7
    const int tg  = lane & 3;         // 0..3

    // chunk mapping: 512 chunks of 8 halves (A: 128 rows x 4; B: 128 n x 4)
    const int rA0 = tid >> 2, rA1 = (tid >> 2) + 64;
    const int kk  = (tid & 3) * 8;
    const int grA0 = min(row0 + rA0, Nl - 1);
    const int grA1 = min(row0 + rA1, Nl - 1);

    float acc[4][4][4];
#pragma unroll
    for (int mt = 0; mt < 4; mt++)
#pragma unroll
        for (int nt = 0; nt < 4; nt++)
#pragma unroll
            for (int r = 0; r < 4; r++) acc[mt][nt][r] = 0.f;

    const int NT = D_IN / 32;   // 8 panels

#define G1_ISSUE(kt, s) do {                                               \
        int k0_ = (kt) * 32;                                               \
        cp_async16(&As[s][rA0][kk], Xh + (size_t)grA0 * 256 + k0_ + kk);   \
        cp_async16(&As[s][rA1][kk], Xh + (size_t)grA1 * 256 + k0_ + kk);   \
        cp_async16(&Bs[s][rA0][kk], Wh + (size_t)rA0 * 256 + k0_ + kk);    \
        cp_async16(&Bs[s][rA1][kk], Wh + (size_t)rA1 * 256 + k0_ + kk);    \
        cp_commit();                                                       \
    } while (0)

    G1_ISSUE(0, 0);
    G1_ISSUE(1, 1);
    cp_wait<1>();
    __syncthreads();

    for (int kt = 0; kt < NT; kt++) {
        if (kt + 2 < NT) G1_ISSUE(kt + 2, (kt + 2) % 3);
        const int s = kt % 3;
#pragma unroll
        for (int ks = 0; ks < 2; ks++) {
            const int kb = ks * 16;
            unsigned af[4][4], bf[4][2];
#pragma unroll
            for (int mt = 0; mt < 4; mt++) {
                int rb = wR * 64 + mt * 16;
                af[mt][0] = *(const unsigned*)&As[s][rb + gid][kb + 2 * tg];
                af[mt][1] = *(const unsigned*)&As[s][rb + gid + 8][kb + 2 * tg];
                af[mt][2] = *(const unsigned*)&As[s][rb + gid][kb + 2 * tg + 8];
                af[mt][3] = *(const unsigned*)&As[s][rb + gid + 8][kb + 2 * tg + 8];
            }
#pragma unroll
            for (int nt = 0; nt < 4; nt++) {
                int cb = wC * 32 + nt * 8;
                bf[nt][0] = *(const unsigned*)&Bs[s][cb + gid][kb + 2 * tg];
                bf[nt][1] = *(const unsigned*)&Bs[s][cb + gid][kb + 2 * tg + 8];
            }
#pragma unroll
            for (int mt = 0; mt < 4; mt++)
#pragma unroll
                for (int nt = 0; nt < 4; nt++)
                    mma_f16(acc[mt][nt], af[mt], bf[nt]);
        }
        if (kt + 1 < NT) {
            if (kt + 2 < NT) cp_wait<1>(); else cp_wait<0>();
            __syncthreads();
        }
    }
#undef G1_ISSUE

    // ---- epilogue: bias + relu + half store + fused attention dots ----
    float* a2out = (lvl == 0) ? (g_a20 + h * CN0)
                 : (lvl == 1) ? (g_a21 + h * CN1)
                              : (g_a22 + h * CN2);
    const float a2bias = a2b[h];
    const float a1bias = a1b[h];

    float2 biasv[4], w2v[4], w1v[4];
#pragma unroll
    for (int nt = 0; nt < 4; nt++) {
        int c = wC * 32 + nt * 8 + 2 * tg;
        biasv[nt] = *(const float2*)(b1  + h * 128 + c);
        w2v[nt]   = *(const float2*)(a2w + h * 128 + c);
        w1v[nt]   = (lvl == 0) ? *(const float2*)(a1w + h * 128 + c) : make_float2(0.f, 0.f);
    }

    __shared__ float s_red[2][8][4][4];
#pragma unroll
    for (int mt = 0; mt < 4; mt++) {
        int r0 = row0 + wR * 64 + mt * 16 + gid;
        int r1 = r0 + 8;
        float s2a = 0.f, s2b = 0.f, s1a = 0.f, s1b = 0.f;
#pragma unroll
        for (int nt = 0; nt < 4; nt++) {
            int c = wC * 32 + nt * 8 + 2 * tg;
            float v0 = fmaxf(acc[mt][nt][0] + biasv[nt].x, 0.f);
            float v1 = fmaxf(acc[mt][nt][1] + biasv[nt].y, 0.f);
            float v2 = fmaxf(acc[mt][nt][2] + biasv[nt].x, 0.f);
            float v3 = fmaxf(acc[mt][nt][3] + biasv[nt].y, 0.f);
            if (r0 < Nl) *(__half2*)(outh + (size_t)r0 * ldo + c) = __floats2half2_rn(v0, v1);
            if (r1 < Nl) *(__half2*)(outh + (size_t)r1 * ldo + c) = __floats2half2_rn(v2, v3);
            s2a += v0 * w2v[nt].x + v1 * w2v[nt].y;
            s2b += v2 * w2v[nt].x + v3 * w2v[nt].y;
            if (lvl == 0) {
                s1a += v0 * w1v[nt].x + v1 * w1v[nt].y;
                s1b += v2 * w1v[nt].x + v3 * w1v[nt].y;
            }
        }
        s2a += __shfl_xor_sync(0xffffffffu, s2a, 1); s2a += __shfl_xor_sync(0xffffffffu, s2a, 2);
        s2b += __shfl_xor_sync(0xffffffffu, s2b, 1); s2b += __shfl_xor_sync(0xffffffffu, s2b, 2);
        if (lvl == 0) {
            s1a += __shfl_xor_sync(0xffffffffu, s1a, 1); s1a += __shfl_xor_sync(0xffffffffu, s1a, 2);
            s1b += __shfl_xor_sync(0xffffffffu, s1b, 1); s1b += __shfl_xor_sync(0xffffffffu, s1b, 2);
        }
        if (tg == 0) {
            s_red[wR][gid][wC][0] = s2a;
            s_red[wR][gid][wC][1] = s2b;
            s_red[wR][gid][wC][2] = s1a;
            s_red[wR][gid][wC][3] = s1b;
        }
        __syncthreads();
        if (tg == 0 && wC == 0) {
            float t2a = 0.f, t2b = 0.f, t1a = 0.f, t1b = 0.f;
#pragma unroll
            for (int q = 0; q < 4; q++) {
                t2a += s_red[wR][gid][q][0];
                t2b += s_red[wR][gid][q][1];
                t1a += s_red[wR][gid][q][2];
                t1b += s_red[wR][gid][q][3];
            }
            if (r0 < Nl) a2out[r0] = t2a + a2bias;
            if (r1 < Nl) a2out[r1] = t2b + a2bias;
            if (lvl == 0) {
                if (r0 < Nl) g_a1[h * CN0 + r0] = t1a + a1bias;
                if (r1 < Nl) g_a1[h * CN0 + r1] = t1b + a1bias;
            }
        }
        __syncthreads();
    }
}

// ---------------- bucket build ----------------
__global__ void bucket_kernel(
    const int* __restrict__ rows0, const int* __restrict__ cols0,
    const int* __restrict__ rows1, const int* __restrict__ cols1,
    const int* __restrict__ rows2, const int* __restrict__ cols2)
{
    int i = blockIdx.x * blockDim.x + threadIdx.x;
    int lvl, e;
    const int *rows, *cols;
    if (i < NNZ0)                    { lvl = 0; e = i;               rows = rows0; cols = cols0; }
    else if (i < NNZ0 + NNZ1)        { lvl = 1; e = i - NNZ0;        rows = rows1; cols = cols1; }
    else if (i < NNZ0 + NNZ1 + NNZ2) { lvl = 2; e = i - NNZ0 - NNZ1; rows = rows2; cols = cols2; }
    else return;
    int r = rows[e], c = cols[e];
    int pos = atomicAdd(&g_cnt[lvl * CN0 + r], 1);
    if (pos < CAP) g_list[(size_t)(lvl * CN0 + r) * CAP + pos] = c;
}

// ---------------- attention gather (fp16): two-phase, warp per (row,h,lvl) ----
__global__ __launch_bounds__(256) void agg_kernel()
{
    __shared__ int   s_c[8][64];
    __shared__ float s_att[8][64];

    int w = (blockIdx.x * blockDim.x + threadIdx.x) >> 5;
    int wl = (threadIdx.x >> 5);
    int lane = threadIdx.x & 31;
    if (w >= 3 * HEADS * CN0) return;
    int lvl = w / (HEADS * CN0);
    int rem = w - lvl * (HEADS * CN0);
    int h   = rem / CN0;
    int row = rem - h * CN0;

    int n = g_cnt[lvl * CN0 + row];
    if (n > CAP) n = CAP;
    float a1v = g_a1[h * CN0 + row];

    const float* a2p; const __half* yb; int ldy;
    if (lvl == 0)      { a2p = g_a20 + h * CN0; yb = g_cath + (size_t)h * CN0 * 512; ldy = 512; }
    else if (lvl == 1) { a2p = g_a21 + h * CN1; yb = g_y1h + (size_t)h * CN1 * 128; ldy = 128; }
    else               { a2p = g_a22 + h * CN2; yb = g_y2h + (size_t)h * CN2 * 128; ldy = 128; }

    const int* lst = g_list + (size_t)(lvl * CN0 + row) * CAP;
    float4 acc[4];
#pragma unroll
    for (int q = 0; q < 4; q++) acc[q] = make_float4(0.f, 0.f, 0.f, 0.f);

    for (int j0 = 0; j0 < n; j0 += 64) {
        int m = n - j0; if (m > 64) m = 64;
        __syncwarp();
        if (lane < m) {
            int c = lst[j0 + lane];
            float z = a1v + a2p[c];
            s_c[wl][lane] = c;
            s_att[wl][lane] = 1.f / (1.f + __expf(-z));
        }
        if (lane + 32 < m) {
            int c = lst[j0 + lane + 32];
            float z = a1v + a2p[c];
            s_c[wl][lane + 32] = c;
            s_att[wl][lane + 32] = 1.f / (1.f + __expf(-z));
        }
        __syncwarp();
        int i = 0;
        for (; i + 8 <= m; i += 8) {
            int cc[8]; float tt[8];
#pragma unroll
            for (int u = 0; u < 8; u++) { cc[u] = s_c[wl][i + u]; tt[u] = s_att[wl][i + u]; }
            uint2 yv[8];
#pragma unroll
            for (int u = 0; u < 8; u++)
                yv[u] = *((const uint2*)(yb + (size_t)cc[u] * ldy) + lane);
#pragma unroll
            for (int u = 0; u < 8; u++) {
                float2 f0 = __half22float2(*(__half2*)&yv[u].x);
                float2 f1 = __half22float2(*(__half2*)&yv[u].y);
                int q = u & 3;
                acc[q].x = fmaf(tt[u], f0.x, acc[q].x);
                acc[q].y = fmaf(tt[u], f0.y, acc[q].y);
                acc[q].z = fmaf(tt[u], f1.x, acc[q].z);
                acc[q].w = fmaf(tt[u], f1.y, acc[q].w);
            }
        }
        for (; i < m; i++) {
            int c = s_c[wl][i]; float t = s_att[wl][i];
            uint2 yv = *((const uint2*)(yb + (size_t)c * ldy) + lane);
            float2 f0 = __half22float2(*(__half2*)&yv.x);
            float2 f1 = __half22float2(*(__half2*)&yv.y);
            acc[0].x = fmaf(t, f0.x, acc[0].x);
            acc[0].y = fmaf(t, f0.y, acc[0].y);
            acc[0].z = fmaf(t, f1.x, acc[0].z);
            acc[0].w = fmaf(t, f1.y, acc[0].w);
        }
    }
    float rx = (acc[0].x + acc[1].x) + (acc[2].x + acc[3].x);
    float ry = (acc[0].y + acc[1].y) + (acc[2].y + acc[3].y);
    float rz = (acc[0].z + acc[1].z) + (acc[2].z + acc[3].z);
    float rw = (acc[0].w + acc[1].w) + (acc[2].w + acc[3].w);
    __half2 o0 = __floats2half2_rn(rx, ry);
    __half2 o1 = __floats2half2_rn(rz, rw);
    uint2 o; o.x = *(unsigned*)&o0; o.y = *(unsigned*)&o1;
    *(uint2*)(g_cath + (size_t)h * CN0 * 512 + (size_t)row * 512 + 128 + lvl * 128 + lane * 4) = o;
}

// ============================================================================
// GEMM2 (fp16 m16n8k16, cp.async 3-stage): out = mean_h(cat_h @ Wagg_h + bagg_h)
// ============================================================================
__global__ __launch_bounds__(256, 2) void gemm2_kernel(
    const float* __restrict__ bagg, float* __restrict__ out)
{
    extern __shared__ __half smem_h[];
    __half (*As)[128][H_STRIDE] = (__half (*)[128][H_STRIDE])smem_h;
    __half (*Bs)[128][H_STRIDE] = (__half (*)[128][H_STRIDE])(smem_h + AH_ELEMS);

    const int row0 = blockIdx.x * 128;

    const int tid = threadIdx.x;
    const int lane = tid & 31;
    const int wid  = tid >> 5;
    const int wR = wid >> 2;
    const int wC = wid & 3;
    const int gid = lane >> 2;
    const int tg  = lane & 3;

    const int rA0 = tid >> 2, rA1 = (tid >> 2) + 64;
    const int kk  = (tid & 3) * 8;
    const int grA0 = min(row0 + rA0, CN0 - 1);
    const int grA1 = min(row0 + rA1, CN0 - 1);

    float acc[4][4][4];
#pragma unroll
    for (int mt = 0; mt < 4; mt++)
#pragma unroll
        for (int nt = 0; nt < 4; nt++)
#pragma unroll
            for (int r = 0; r < 4; r++) acc[mt][nt][r] = 0.f;

    const int NT = 64;   // 4 heads * 512/32

#define G2_ISSUE(kt, s) do {                                                       \
        int t_ = (kt);                                                             \
        int h_ = t_ >> 4, k0_ = (t_ & 15) * 32;                                    \
        const __half* A_ = g_cath + (size_t)h_ * CN0 * 512;                        \
        const __half* W_ = g_waggh + (size_t)h_ * 512 * 128;                       \
        cp_async16(&As[s][rA0][kk], A_ + (size_t)grA0 * 512 + k0_ + kk);           \
        cp_async16(&As[s][rA1][kk], A_ + (size_t)grA1 * 512 + k0_ + kk);           \
        cp_async16(&Bs[s][rA0][kk], W_ + (size_t)rA0 * 512 + k0_ + kk);            \
        cp_async16(&Bs[s][rA1][kk], W_ + (size_t)rA1 * 512 + k0_ + kk);            \
        cp_commit();                                                               \
    } while (0)

    G2_ISSUE(0, 0);
    G2_ISSUE(1, 1);
    cp_wait<1>();
    __syncthreads();

    for (int kt = 0; kt < NT; kt++) {
        if (kt + 2 < NT) G2_ISSUE(kt + 2, (kt + 2) % 3);
        const int s = kt % 3;
#pragma unroll
        for (int ks = 0; ks < 2; ks++) {
            const int kb = ks * 16;
            unsigned af[4][4], bf[4][2];
#pragma unroll
            for (int mt = 0; mt < 4; mt++) {
                int rb = wR * 64 + mt * 16;
                af[mt][0] = *(const unsigned*)&As[s][rb + gid][kb + 2 * tg];
                af[mt][1] = *(const unsigned*)&As[s][rb + gid + 8][kb + 2 * tg];
                af[mt][2] = *(const unsigned*)&As[s][rb + gid][kb + 2 * tg + 8];
                af[mt][3] = *(const unsigned*)&As[s][rb + gid + 8][kb + 2 * tg + 8];
            }
#pragma unroll
            for (int nt = 0; nt < 4; nt++) {
                int cb = wC * 32 + nt * 8;
                bf[nt][0] = *(const unsigned*)&Bs[s][cb + gid][kb + 2 * tg];
                bf[nt][1] = *(const unsigned*)&Bs[s][cb + gid][kb + 2 * tg + 8];
            }
#pragma unroll
            for (int mt = 0; mt < 4; mt++)
#pragma unroll
                for (int nt = 0; nt < 4; nt++)
                    mma_f16(acc[mt][nt], af[mt], bf[nt]);
        }
        if (kt + 1 < NT) {
            if (kt + 2 < NT) cp_wait<1>(); else cp_wait<0>();
            __syncthreads();
        }
    }
#undef G2_ISSUE

    float2 bsum[4];
#pragma unroll
    for (int nt = 0; nt < 4; nt++) {
        int c = wC * 32 + nt * 8 + 2 * tg;
        float2 s = make_float2(0.f, 0.f);
#pragma unroll
        for (int h = 0; h < HEADS; h++) {
            float2 bg = *(const float2*)(bagg + h * 128 + c);
            s.x += bg.x; s.y += bg.y;
        }
        bsum[nt] = s;
    }
#pragma unroll
    for (int mt = 0; mt < 4; mt++) {
        int r0 = row0 + wR * 64 + mt * 16 + gid;
        int r1 = r0 + 8;
#pragma unroll
        for (int nt = 0; nt < 4; nt++) {
            int c = wC * 32 + nt * 8 + 2 * tg;
            if (r0 < CN0) {
                float2 v;
                v.x = (acc[mt][nt][0] + bsum[nt].x) * 0.25f;
                v.y = (acc[mt][nt][1] + bsum[nt].y) * 0.25f;
                *(float2*)(out + (size_t)r0 * 128 + c) = v;
            }
            if (r1 < CN0) {
                float2 v;
                v.x = (acc[mt][nt][2] + bsum[nt].x) * 0.25f;
                v.y = (acc[mt][nt][3] + bsum[nt].y) * 0.25f;
                *(float2*)(out + (size_t)r1 * 128 + c) = v;
            }
        }
    }
}

// ---------------- launch ----------------
extern "C" void kernel_launch(void* const* d_in, const int* in_sizes, int n_in,
                              void* d_out, int out_size)
{
    const float* x0    = (const float*)d_in[0];
    const float* x1    = (const float*)d_in[1];
    const float* x2    = (const float*)d_in[2];
    const int*   rows0 = (const int*)d_in[3];
    const int*   cols0 = (const int*)d_in[4];
    const int*   rows1 = (const int*)d_in[5];
    const int*   cols1 = (const int*)d_in[6];
    const int*   rows2 = (const int*)d_in[7];
    const int*   cols2 = (const int*)d_in[8];
    const float* W1    = (const float*)d_in[9];
    const float* b1    = (const float*)d_in[10];
    const float* a1w   = (const float*)d_in[11];
    const float* a1b   = (const float*)d_in[12];
    const float* a2w   = (const float*)d_in[13];
    const float* a2b   = (const float*)d_in[14];
    const float* Wagg  = (const float*)d_in[15];
    const float* bagg  = (const float*)d_in[16];
    float* out = (float*)d_out;

    cudaFuncSetAttribute(gemm1_kernel, cudaFuncAttributeMaxDynamicSharedMemorySize, GEMM_SMEM_BYTES);
    cudaFuncSetAttribute(gemm2_kernel, cudaFuncAttributeMaxDynamicSharedMemorySize, GEMM_SMEM_BYTES);

    zero_cnt_kernel<<<(3 * CN0 + 255) / 256, 256>>>();
    bucket_kernel<<<(NNZ0 + NNZ1 + NNZ2 + 255) / 256, 256>>>(
        rows0, cols0, rows1, cols1, rows2, cols2);

    cvt_x_kernel<<<(int)((NXH / 4 + 255) / 256), 256>>>(x0, x1, x2);
    cvt_w_kernel<<<(HEADS * 256 * 128 + HEADS * 512 * 128 + 255) / 256, 256>>>(W1, Wagg);

    {
        dim3 grid(12, (CN1 + 127) / 128);
        gemm1_kernel<<<grid, 256, GEMM_SMEM_BYTES>>>(b1, a1w, a1b, a2w, a2b);
    }
    {
        int warps = 3 * HEADS * CN0;
        agg_kernel<<<(warps * 32 + 255) / 256, 256>>>();
    }
    gemm2_kernel<<<(CN0 + 127) / 128, 256, GEMM_SMEM_BYTES>>>(bagg, out);
}

// round 8
// speedup vs baseline: 3.1709x; 1.0301x over previous
#include <cuda_runtime.h>
#include <cuda_fp16.h>
#include <math.h>

#define CN0 30000
#define CN1 90000
#define CN2 60000
#define D_IN 256
#define D_OUT 128
#define HEADS 4
#define NNZ0 960000
#define NNZ1 180000
#define NNZ2 180000
#define CAP 256

// fp16 GEMM smem: 3-stage, A[128][40] + B[128][40] halves per stage
#define H_STRIDE 40
#define AH_ELEMS (3 * 128 * H_STRIDE)
#define GEMM_SMEM_BYTES (2 * AH_ELEMS * 2)

#define NXH ((size_t)(CN0 + CN1 + CN2) * 256)

// ---------------- scratch (node-major layouts) ----------------
__device__ __half g_xh[NXH];                        // fp16 inputs (x0|x1|x2)
__device__ __half g_w1h[HEADS * 256 * 128];         // W1 transposed  [h][n][k]
__device__ __half g_waggh[HEADS * 512 * 128];       // Wagg transposed [h][n][k]
__device__ __half g_y1h[(size_t)CN1 * HEADS * 128]; // [node][h][128]
__device__ __half g_y2h[(size_t)CN2 * HEADS * 128];
__device__ __half g_cath[(size_t)CN0 * HEADS * 512];// [row][h][ xi0 | agg0 | agg1 | agg2 ]
__device__ float g_a1[CN0 * 4];                     // [row][h]
__device__ float g_a20[CN0 * 4];
__device__ float g_a21[CN1 * 4];
__device__ float g_a22[CN2 * 4];
__device__ int   g_cnt[3 * CN0];
__device__ int   g_list[3 * CN0 * CAP];

__global__ void zero_cnt_kernel() {
    int i = blockIdx.x * blockDim.x + threadIdx.x;
    if (i < 3 * CN0) g_cnt[i] = 0;
}

// ---------------- converts ----------------
__global__ void cvt_x_kernel(const float* __restrict__ x0, const float* __restrict__ x1,
                             const float* __restrict__ x2) {
    size_t i = (size_t)blockIdx.x * 256 + threadIdx.x;
    if (i >= NXH / 4) return;
    size_t e = i * 4;
    const float* src; size_t base;
    if (e < (size_t)CN0 * 256)               { src = x0; base = 0; }
    else if (e < (size_t)(CN0 + CN1) * 256)  { src = x1; base = (size_t)CN0 * 256; }
    else                                     { src = x2; base = (size_t)(CN0 + CN1) * 256; }
    float4 v = *(const float4*)(src + (e - base));
    __half2 h0 = __floats2half2_rn(v.x, v.y);
    __half2 h1 = __floats2half2_rn(v.z, v.w);
    uint2 u; u.x = *(unsigned*)&h0; u.y = *(unsigned*)&h1;
    *(uint2*)(g_xh + e) = u;
}

__global__ void cvt_w_kernel(const float* __restrict__ W1, const float* __restrict__ Wagg) {
    int i = blockIdx.x * 256 + threadIdx.x;
    const int NW1 = HEADS * 256 * 128;
    const int NWA = HEADS * 512 * 128;
    if (i < NW1) {
        int h = i / (256 * 128), r = (i / 128) % 256, c = i % 128;
        g_w1h[h * 256 * 128 + c * 256 + r] = __float2half(W1[i]);
    } else if (i < NW1 + NWA) {
        int j = i - NW1;
        int h = j / (512 * 128), r = (j / 128) % 512, c = j % 128;
        g_waggh[h * 512 * 128 + c * 512 + r] = __float2half(Wagg[j]);
    }
}

// ---------------- mma/cp helpers ----------------
__device__ __forceinline__ void mma_f16(float d[4], const unsigned a[4], const unsigned b[2]) {
    asm volatile(
        "mma.sync.aligned.m16n8k16.row.col.f32.f16.f16.f32 "
        "{%0,%1,%2,%3}, {%4,%5,%6,%7}, {%8,%9}, {%0,%1,%2,%3};\n"
        : "+f"(d[0]), "+f"(d[1]), "+f"(d[2]), "+f"(d[3])
        : "r"(a[0]), "r"(a[1]), "r"(a[2]), "r"(a[3]), "r"(b[0]), "r"(b[1]));
}
__device__ __forceinline__ void cp_async16(void* smem_dst, const void* gmem_src) {
    unsigned s = (unsigned)__cvta_generic_to_shared(smem_dst);
    asm volatile("cp.async.ca.shared.global [%0], [%1], 16;\n" :: "r"(s), "l"(gmem_src));
}
__device__ __forceinline__ void cp_commit() {
    asm volatile("cp.async.commit_group;\n" ::: "memory");
}
template <int N>
__device__ __forceinline__ void cp_wait() {
    asm volatile("cp.async.wait_group %0;\n" :: "n"(N) : "memory");
}

// ============================================================================
// GEMM1 (fp16 m16n8k16, cp.async 3-stage): y = relu(X @ W1h + b1h) + a1/a2 dots
// node-major outputs. grid (12 = lvl*4+h, rowblocks)
// ============================================================================
__global__ __launch_bounds__(256, 2) void gemm1_kernel(
    const float* __restrict__ b1,
    const float* __restrict__ a1w, const float* __restrict__ a1b,
    const float* __restrict__ a2w, const float* __restrict__ a2b)
{
    extern __shared__ __half smem_h[];
    __half (*As)[128][H_STRIDE] = (__half (*)[128][H_STRIDE])smem_h;
    __half (*Bs)[128][H_STRIDE] = (__half (*)[128][H_STRIDE])(smem_h + AH_ELEMS);

    const int lh  = blockIdx.x;
    const int lvl = lh >> 2;
    const int h   = lh & 3;
    const int Nl  = (lvl == 0) ? CN0 : (lvl == 1) ? CN1 : CN2;
    const int row0 = blockIdx.y * 128;
    if (row0 >= Nl) return;

    const __half* Xh = g_xh + ((lvl == 0) ? 0 : (lvl == 1) ? (size_t)CN0 * 256
                                                           : (size_t)(CN0 + CN1) * 256);
    const __half* Wh = g_w1h + (size_t)h * 256 * 128;
    __half* outh; int ldo;
    if (lvl == 0)      { outh = g_cath + (size_t)h * 512; ldo = 2048; }
    else if (lvl == 1) { outh = g_y1h  + (size_t)h * 128; ldo = 512; }
    else               { outh = g_y2h  + (size_t)h * 128; ldo = 512; }

    const int tid = threadIdx.x;
    const int lane = tid & 31;
    const int wid  = tid >> 5;
    const int wR = wid >> 2;
    const int wC = wid & 3;
    const int gid = lane >> 2;
    const int tg  = lane & 3;

    const int rA0 = tid >> 2, rA1 = (tid >> 2) + 64;
    const int kk  = (tid & 3) * 8;
    const int grA0 = min(row0 + rA0, Nl - 1);
    const int grA1 = min(row0 + rA1, Nl - 1);

    float acc[4][4][4];
#pragma unroll
    for (int mt = 0; mt < 4; mt++)
#pragma unroll
        for (int nt = 0; nt < 4; nt++)
#pragma unroll
            for (int r = 0; r < 4; r++) acc[mt][nt][r] = 0.f;

    const int NT = D_IN / 32;   // 8

#define G1_ISSUE(kt, s) do {                                               \
        int k0_ = (kt) * 32;                                               \
        cp_async16(&As[s][rA0][kk], Xh + (size_t)grA0 * 256 + k0_ + kk);   \
        cp_async16(&As[s][rA1][kk], Xh + (size_t)grA1 * 256 + k0_ + kk);   \
        cp_async16(&Bs[s][rA0][kk], Wh + (size_t)rA0 * 256 + k0_ + kk);    \
        cp_async16(&Bs[s][rA1][kk], Wh + (size_t)rA1 * 256 + k0_ + kk);    \
        cp_commit();                                                       \
    } while (0)

    G1_ISSUE(0, 0);
    G1_ISSUE(1, 1);
    cp_wait<1>();
    __syncthreads();

    for (int kt = 0; kt < NT; kt++) {
        if (kt + 2 < NT) G1_ISSUE(kt + 2, (kt + 2) % 3);
        const int s = kt % 3;
#pragma unroll
        for (int ks = 0; ks < 2; ks++) {
            const int kb = ks * 16;
            unsigned af[4][4], bf[4][2];
#pragma unroll
            for (int mt = 0; mt < 4; mt++) {
                int rb = wR * 64 + mt * 16;
                af[mt][0] = *(const unsigned*)&As[s][rb + gid][kb + 2 * tg];
                af[mt][1] = *(const unsigned*)&As[s][rb + gid + 8][kb + 2 * tg];
                af[mt][2] = *(const unsigned*)&As[s][rb + gid][kb + 2 * tg + 8];
                af[mt][3] = *(const unsigned*)&As[s][rb + gid + 8][kb + 2 * tg + 8];
            }
#pragma unroll
            for (int nt = 0; nt < 4; nt++) {
                int cb = wC * 32 + nt * 8;
                bf[nt][0] = *(const unsigned*)&Bs[s][cb + gid][kb + 2 * tg];
                bf[nt][1] = *(const unsigned*)&Bs[s][cb + gid][kb + 2 * tg + 8];
            }
#pragma unroll
            for (int mt = 0; mt < 4; mt++)
#pragma unroll
                for (int nt = 0; nt < 4; nt++)
                    mma_f16(acc[mt][nt], af[mt], bf[nt]);
        }
        if (kt + 1 < NT) {
            if (kt + 2 < NT) cp_wait<1>(); else cp_wait<0>();
            __syncthreads();
        }
    }
#undef G1_ISSUE

    // ---- epilogue: bias + relu + half store + fused attention dots ----
    float* a2out = ((lvl == 0) ? g_a20 : (lvl == 1) ? g_a21 : g_a22) + h; // [node][4]
    const float a2bias = a2b[h];
    const float a1bias = a1b[h];

    float2 biasv[4], w2v[4], w1v[4];
#pragma unroll
    for (int nt = 0; nt < 4; nt++) {
        int c = wC * 32 + nt * 8 + 2 * tg;
        biasv[nt] = *(const float2*)(b1  + h * 128 + c);
        w2v[nt]   = *(const float2*)(a2w + h * 128 + c);
        w1v[nt]   = (lvl == 0) ? *(const float2*)(a1w + h * 128 + c) : make_float2(0.f, 0.f);
    }

    __shared__ float s_red[2][8][4][4];
#pragma unroll
    for (int mt = 0; mt < 4; mt++) {
        int r0 = row0 + wR * 64 + mt * 16 + gid;
        int r1 = r0 + 8;
        float s2a = 0.f, s2b = 0.f, s1a = 0.f, s1b = 0.f;
#pragma unroll
        for (int nt = 0; nt < 4; nt++) {
            int c = wC * 32 + nt * 8 + 2 * tg;
            float v0 = fmaxf(acc[mt][nt][0] + biasv[nt].x, 0.f);
            float v1 = fmaxf(acc[mt][nt][1] + biasv[nt].y, 0.f);
            float v2 = fmaxf(acc[mt][nt][2] + biasv[nt].x, 0.f);
            float v3 = fmaxf(acc[mt][nt][3] + biasv[nt].y, 0.f);
            if (r0 < Nl) *(__half2*)(outh + (size_t)r0 * ldo + c) = __floats2half2_rn(v0, v1);
            if (r1 < Nl) *(__half2*)(outh + (size_t)r1 * ldo + c) = __floats2half2_rn(v2, v3);
            s2a += v0 * w2v[nt].x + v1 * w2v[nt].y;
            s2b += v2 * w2v[nt].x + v3 * w2v[nt].y;
            if (lvl == 0) {
                s1a += v0 * w1v[nt].x + v1 * w1v[nt].y;
                s1b += v2 * w1v[nt].x + v3 * w1v[nt].y;
            }
        }
        s2a += __shfl_xor_sync(0xffffffffu, s2a, 1); s2a += __shfl_xor_sync(0xffffffffu, s2a, 2);
        s2b += __shfl_xor_sync(0xffffffffu, s2b, 1); s2b += __shfl_xor_sync(0xffffffffu, s2b, 2);
        if (lvl == 0) {
            s1a += __shfl_xor_sync(0xffffffffu, s1a, 1); s1a += __shfl_xor_sync(0xffffffffu, s1a, 2);
            s1b += __shfl_xor_sync(0xffffffffu, s1b, 1); s1b += __shfl_xor_sync(0xffffffffu, s1b, 2);
        }
        if (tg == 0) {
            s_red[wR][gid][wC][0] = s2a;
            s_red[wR][gid][wC][1] = s2b;
            s_red[wR][gid][wC][2] = s1a;
            s_red[wR][gid][wC][3] = s1b;
        }
        __syncthreads();
        if (tg == 0 && wC == 0) {
            float t2a = 0.f, t2b = 0.f, t1a = 0.f, t1b = 0.f;
#pragma unroll
            for (int q = 0; q < 4; q++) {
                t2a += s_red[wR][gid][q][0];
                t2b += s_red[wR][gid][q][1];
                t1a += s_red[wR][gid][q][2];
                t1b += s_red[wR][gid][q][3];
            }
            if (r0 < Nl) a2out[r0 * 4] = t2a + a2bias;
            if (r1 < Nl) a2out[r1 * 4] = t2b + a2bias;
            if (lvl == 0) {
                if (r0 < Nl) g_a1[r0 * 4 + h] = t1a + a1bias;
                if (r1 < Nl) g_a1[r1 * 4 + h] = t1b + a1bias;
            }
        }
        __syncthreads();
    }
}

// ---------------- bucket build ----------------
__global__ void bucket_kernel(
    const int* __restrict__ rows0, const int* __restrict__ cols0,
    const int* __restrict__ rows1, const int* __restrict__ cols1,
    const int* __restrict__ rows2, const int* __restrict__ cols2)
{
    int i = blockIdx.x * blockDim.x + threadIdx.x;
    int lvl, e;
    const int *rows, *cols;
    if (i < NNZ0)                    { lvl = 0; e = i;               rows = rows0; cols = cols0; }
    else if (i < NNZ0 + NNZ1)        { lvl = 1; e = i - NNZ0;        rows = rows1; cols = cols1; }
    else if (i < NNZ0 + NNZ1 + NNZ2) { lvl = 2; e = i - NNZ0 - NNZ1; rows = rows2; cols = cols2; }
    else return;
    int r = rows[e], c = cols[e];
    int pos = atomicAdd(&g_cnt[lvl * CN0 + r], 1);
    if (pos < CAP) g_list[(size_t)(lvl * CN0 + r) * CAP + pos] = c;
}

// ---------------- attention gather: head-merged, warp per (lvl,row) -----------
__global__ __launch_bounds__(256) void agg_kernel()
{
    __shared__ int    s_c[8][64];
    __shared__ float4 s_att[8][64];

    int w = (blockIdx.x * blockDim.x + threadIdx.x) >> 5;
    int wl = (threadIdx.x >> 5);
    int lane = threadIdx.x & 31;
    if (w >= 3 * CN0) return;
    int lvl = w / CN0;
    int row = w - lvl * CN0;

    int n = g_cnt[lvl * CN0 + row];
    if (n > CAP) n = CAP;

    float4 a1v = *(const float4*)(g_a1 + row * 4);   // all 4 heads

    const float* a2p; const __half* yb; int ns, hs;
    if (lvl == 0)      { a2p = g_a20; yb = g_cath; ns = 2048; hs = 512; }
    else if (lvl == 1) { a2p = g_a21; yb = g_y1h;  ns = 512;  hs = 128; }
    else               { a2p = g_a22; yb = g_y2h;  ns = 512;  hs = 128; }

    const int* lst = g_list + (size_t)(lvl * CN0 + row) * CAP;

    float4 acc[4];   // per head: 4 halves/lane as floats
#pragma unroll
    for (int q = 0; q < 4; q++) acc[q] = make_float4(0.f, 0.f, 0.f, 0.f);

    for (int j0 = 0; j0 < n; j0 += 64) {
        int m = n - j0; if (m > 64) m = 64;
        __syncwarp();
        // phase A: per-edge scores for all 4 heads (one float4 a2 load)
        if (lane < m) {
            int c = lst[j0 + lane];
            float4 a2v = *(const float4*)(a2p + c * 4);
            float4 t;
            t.x = 1.f / (1.f + __expf(-(a1v.x + a2v.x)));
            t.y = 1.f / (1.f + __expf(-(a1v.y + a2v.y)));
            t.z = 1.f / (1.f + __expf(-(a1v.z + a2v.z)));
            t.w = 1.f / (1.f + __expf(-(a1v.w + a2v.w)));
            s_c[wl][lane] = c;
            s_att[wl][lane] = t;
        }
        if (lane + 32 < m) {
            int c = lst[j0 + lane + 32];
            float4 a2v = *(const float4*)(a2p + c * 4);
            float4 t;
            t.x = 1.f / (1.f + __expf(-(a1v.x + a2v.x)));
            t.y = 1.f / (1.f + __expf(-(a1v.y + a2v.y)));
            t.z = 1.f / (1.f + __expf(-(a1v.z + a2v.z)));
            t.w = 1.f / (1.f + __expf(-(a1v.w + a2v.w)));
            s_c[wl][lane + 32] = c;
            s_att[wl][lane + 32] = t;
        }
        __syncwarp();
        // phase B: 2 edges x 4 heads = 8 independent gathers in flight
        int i = 0;
        for (; i + 2 <= m; i += 2) {
            int c0 = s_c[wl][i], c1 = s_c[wl][i + 1];
            float4 t0 = s_att[wl][i], t1 = s_att[wl][i + 1];
            const __half* p0 = yb + (size_t)c0 * ns;
            const __half* p1 = yb + (size_t)c1 * ns;
            uint2 yv0[4], yv1[4];
#pragma unroll
            for (int hh = 0; hh < 4; hh++) {
                yv0[hh] = *((const uint2*)(p0 + hh * hs) + lane);
                yv1[hh] = *((const uint2*)(p1 + hh * hs) + lane);
            }
            float t0a[4] = {t0.x, t0.y, t0.z, t0.w};
            float t1a[4] = {t1.x, t1.y, t1.z, t1.w};
#pragma unroll
            for (int hh = 0; hh < 4; hh++) {
                float2 f0 = __half22float2(*(__half2*)&yv0[hh].x);
                float2 f1 = __half22float2(*(__half2*)&yv0[hh].y);
                acc[hh].x = fmaf(t0a[hh], f0.x, acc[hh].x);
                acc[hh].y = fmaf(t0a[hh], f0.y, acc[hh].y);
                acc[hh].z = fmaf(t0a[hh], f1.x, acc[hh].z);
                acc[hh].w = fmaf(t0a[hh], f1.y, acc[hh].w);
                float2 g0 = __half22float2(*(__half2*)&yv1[hh].x);
                float2 g1 = __half22float2(*(__half2*)&yv1[hh].y);
                acc[hh].x = fmaf(t1a[hh], g0.x, acc[hh].x);
                acc[hh].y = fmaf(t1a[hh], g0.y, acc[hh].y);
                acc[hh].z = fmaf(t1a[hh], g1.x, acc[hh].z);
                acc[hh].w = fmaf(t1a[hh], g1.y, acc[hh].w);
            }
        }
        if (i < m) {
            int c0 = s_c[wl][i];
            float4 t0 = s_att[wl][i];
            const __half* p0 = yb + (size_t)c0 * ns;
            float t0a[4] = {t0.x, t0.y, t0.z, t0.w};
#pragma unroll
            for (int hh = 0; hh < 4; hh++) {
                uint2 yv = *((const uint2*)(p0 + hh * hs) + lane);
                float2 f0 = __half22float2(*(__half2*)&yv.x);
                float2 f1 = __half22float2(*(__half2*)&yv.y);
                acc[hh].x = fmaf(t0a[hh], f0.x, acc[hh].x);
                acc[hh].y = fmaf(t0a[hh], f0.y, acc[hh].y);
                acc[hh].z = fmaf(t0a[hh], f1.x, acc[hh].z);
                acc[hh].w = fmaf(t0a[hh], f1.y, acc[hh].w);
            }
        }
    }
    // write agg segment for each head: [row][h][128 + lvl*128 ..]
#pragma unroll
    for (int hh = 0; hh < 4; hh++) {
        __half2 o0 = __floats2half2_rn(acc[hh].x, acc[hh].y);
        __half2 o1 = __floats2half2_rn(acc[hh].z, acc[hh].w);
        uint2 o; o.x = *(unsigned*)&o0; o.y = *(unsigned*)&o1;
        *(uint2*)(g_cath + (size_t)row * 2048 + hh * 512 + 128 + lvl * 128 + lane * 4) = o;
    }
}

// ============================================================================
// GEMM2 (fp16 m16n8k16): out = mean_h(cat_h @ Wagg_h + bagg_h); cat node-major
// ============================================================================
__global__ __launch_bounds__(256, 2) void gemm2_kernel(
    const float* __restrict__ bagg, float* __restrict__ out)
{
    extern __shared__ __half smem_h[];
    __half (*As)[128][H_STRIDE] = (__half (*)[128][H_STRIDE])smem_h;
    __half (*Bs)[128][H_STRIDE] = (__half (*)[128][H_STRIDE])(smem_h + AH_ELEMS);

    const int row0 = blockIdx.x * 128;

    const int tid = threadIdx.x;
    const int lane = tid & 31;
    const int wid  = tid >> 5;
    const int wR = wid >> 2;
    const int wC = wid & 3;
    const int gid = lane >> 2;
    const int tg  = lane & 3;

    const int rA0 = tid >> 2, rA1 = (tid >> 2) + 64;
    const int kk  = (tid & 3) * 8;
    const int grA0 = min(row0 + rA0, CN0 - 1);
    const int grA1 = min(row0 + rA1, CN0 - 1);

    float acc[4][4][4];
#pragma unroll
    for (int mt = 0; mt < 4; mt++)
#pragma unroll
        for (int nt = 0; nt < 4; nt++)
#pragma unroll
            for (int r = 0; r < 4; r++) acc[mt][nt][r] = 0.f;

    const int NT = 64;

#define G2_ISSUE(kt, s) do {                                                          \
        int t_ = (kt);                                                                \
        int h_ = t_ >> 4, k0_ = (t_ & 15) * 32;                                       \
        const __half* W_ = g_waggh + (size_t)h_ * 512 * 128;                          \
        cp_async16(&As[s][rA0][kk], g_cath + (size_t)grA0 * 2048 + h_ * 512 + k0_ + kk); \
        cp_async16(&As[s][rA1][kk], g_cath + (size_t)grA1 * 2048 + h_ * 512 + k0_ + kk); \
        cp_async16(&Bs[s][rA0][kk], W_ + (size_t)rA0 * 512 + k0_ + kk);               \
        cp_async16(&Bs[s][rA1][kk], W_ + (size_t)rA1 * 512 + k0_ + kk);               \
        cp_commit();                                                                  \
    } while (0)

    G2_ISSUE(0, 0);
    G2_ISSUE(1, 1);
    cp_wait<1>();
    __syncthreads();

    for (int kt = 0; kt < NT; kt++) {
        if (kt + 2 < NT) G2_ISSUE(kt + 2, (kt + 2) % 3);
        const int s = kt % 3;
#pragma unroll
        for (int ks = 0; ks < 2; ks++) {
            const int kb = ks * 16;
            unsigned af[4][4], bf[4][2];
#pragma unroll
            for (int mt = 0; mt < 4; mt++) {
                int rb = wR * 64 + mt * 16;
                af[mt][0] = *(const unsigned*)&As[s][rb + gid][kb + 2 * tg];
                af[mt][1] = *(const unsigned*)&As[s][rb + gid + 8][kb + 2 * tg];
                af[mt][2] = *(const unsigned*)&As[s][rb + gid][kb + 2 * tg + 8];
                af[mt][3] = *(const unsigned*)&As[s][rb + gid + 8][kb + 2 * tg + 8];
            }
#pragma unroll
            for (int nt = 0; nt < 4; nt++) {
                int cb = wC * 32 + nt * 8;
                bf[nt][0] = *(const unsigned*)&Bs[s][cb + gid][kb + 2 * tg];
                bf[nt][1] = *(const unsigned*)&Bs[s][cb + gid][kb + 2 * tg + 8];
            }
#pragma unroll
            for (int mt = 0; mt < 4; mt++)
#pragma unroll
                for (int nt = 0; nt < 4; nt++)
                    mma_f16(acc[mt][nt], af[mt], bf[nt]);
        }
        if (kt + 1 < NT) {
            if (kt + 2 < NT) cp_wait<1>(); else cp_wait<0>();
            __syncthreads();
        }
    }
#undef G2_ISSUE

    float2 bsum[4];
#pragma unroll
    for (int nt = 0; nt < 4; nt++) {
        int c = wC * 32 + nt * 8 + 2 * tg;
        float2 s = make_float2(0.f, 0.f);
#pragma unroll
        for (int h = 0; h < HEADS; h++) {
            float2 bg = *(const float2*)(bagg + h * 128 + c);
            s.x += bg.x; s.y += bg.y;
        }
        bsum[nt] = s;
    }
#pragma unroll
    for (int mt = 0; mt < 4; mt++) {
        int r0 = row0 + wR * 64 + mt * 16 + gid;
        int r1 = r0 + 8;
#pragma unroll
        for (int nt = 0; nt < 4; nt++) {
            int c = wC * 32 + nt * 8 + 2 * tg;
            if (r0 < CN0) {
                float2 v;
                v.x = (acc[mt][nt][0] + bsum[nt].x) * 0.25f;
                v.y = (acc[mt][nt][1] + bsum[nt].y) * 0.25f;
                *(float2*)(out + (size_t)r0 * 128 + c) = v;
            }
            if (r1 < CN0) {
                float2 v;
                v.x = (acc[mt][nt][2] + bsum[nt].x) * 0.25f;
                v.y = (acc[mt][nt][3] + bsum[nt].y) * 0.25f;
                *(float2*)(out + (size_t)r1 * 128 + c) = v;
            }
        }
    }
}

// ---------------- launch ----------------
extern "C" void kernel_launch(void* const* d_in, const int* in_sizes, int n_in,
                              void* d_out, int out_size)
{
    const float* x0    = (const float*)d_in[0];
    const float* x1    = (const float*)d_in[1];
    const float* x2    = (const float*)d_in[2];
    const int*   rows0 = (const int*)d_in[3];
    const int*   cols0 = (const int*)d_in[4];
    const int*   rows1 = (const int*)d_in[5];
    const int*   cols1 = (const int*)d_in[6];
    const int*   rows2 = (const int*)d_in[7];
    const int*   cols2 = (const int*)d_in[8];
    const float* W1    = (const float*)d_in[9];
    const float* b1    = (const float*)d_in[10];
    const float* a1w   = (const float*)d_in[11];
    const float* a1b   = (const float*)d_in[12];
    const float* a2w   = (const float*)d_in[13];
    const float* a2b   = (const float*)d_in[14];
    const float* Wagg  = (const float*)d_in[15];
    const float* bagg  = (const float*)d_in[16];
    float* out = (float*)d_out;

    cudaFuncSetAttribute(gemm1_kernel, cudaFuncAttributeMaxDynamicSharedMemorySize, GEMM_SMEM_BYTES);
    cudaFuncSetAttribute(gemm2_kernel, cudaFuncAttributeMaxDynamicSharedMemorySize, GEMM_SMEM_BYTES);

    zero_cnt_kernel<<<(3 * CN0 + 255) / 256, 256>>>();
    bucket_kernel<<<(NNZ0 + NNZ1 + NNZ2 + 255) / 256, 256>>>(
        rows0, cols0, rows1, cols1, rows2, cols2);

    cvt_x_kernel<<<(int)((NXH / 4 + 255) / 256), 256>>>(x0, x1, x2);
    cvt_w_kernel<<<(HEADS * 256 * 128 + HEADS * 512 * 128 + 255) / 256, 256>>>(W1, Wagg);

    {
        dim3 grid(12, (CN1 + 127) / 128);
        gemm1_kernel<<<grid, 256, GEMM_SMEM_BYTES>>>(b1, a1w, a1b, a2w, a2b);
    }
    {
        int warps = 3 * CN0;
        agg_kernel<<<(warps * 32 + 255) / 256, 256>>>();
    }
    gemm2_kernel<<<(CN0 + 127) / 128, 256, GEMM_SMEM_BYTES>>>(bagg, out);
}

// round 10
// speedup vs baseline: 3.6176x; 1.1409x over previous
#include <cuda_runtime.h>
#include <cuda_fp16.h>
#include <math.h>

#define CN0 30000
#define CN1 90000
#define CN2 60000
#define D_IN 256
#define D_OUT 128
#define HEADS 4
#define NNZ0 960000
#define NNZ1 180000
#define NNZ2 180000
#define CAP 256

// fp16 GEMM smem: 3-stage, A[128][40] + B[128][40] halves per stage
#define H_STRIDE 40
#define AH_ELEMS (3 * 128 * H_STRIDE)
#define GEMM_SMEM_BYTES (2 * AH_ELEMS * 2)

#define NXH ((size_t)(CN0 + CN1 + CN2) * 256)

// ---------------- scratch (node-major layouts) ----------------
__device__ __half g_xh[NXH];                        // fp16 inputs (x0|x1|x2)
__device__ __half g_w1h[HEADS * 256 * 128];         // W1 transposed  [h][n][k]
__device__ __half g_waggh[HEADS * 512 * 128];       // Wagg transposed [h][n][k]
__device__ __half g_y1h[(size_t)CN1 * HEADS * 128]; // [node][h][128]
__device__ __half g_y2h[(size_t)CN2 * HEADS * 128];
__device__ __half g_cath[(size_t)CN0 * HEADS * 512];// [row][h][ xi0 | agg0 | agg1 | agg2 ]
__device__ float g_a1[CN0 * 4];                     // [row][h]
__device__ float g_a20[CN0 * 4];
__device__ float g_a21[CN1 * 4];
__device__ float g_a22[CN2 * 4];
__device__ int   g_cnt[3 * CN0];
__device__ int   g_list[3 * CN0 * CAP];

__global__ void zero_cnt_kernel() {
    int i = blockIdx.x * blockDim.x + threadIdx.x;
    if (i < 3 * CN0) g_cnt[i] = 0;
}

// ---------------- converts ----------------
__global__ void cvt_x_kernel(const float* __restrict__ x0, const float* __restrict__ x1,
                             const float* __restrict__ x2) {
    size_t i = (size_t)blockIdx.x * 256 + threadIdx.x;
    if (i >= NXH / 4) return;
    size_t e = i * 4;
    const float* src; size_t base;
    if (e < (size_t)CN0 * 256)               { src = x0; base = 0; }
    else if (e < (size_t)(CN0 + CN1) * 256)  { src = x1; base = (size_t)CN0 * 256; }
    else                                     { src = x2; base = (size_t)(CN0 + CN1) * 256; }
    float4 v = *(const float4*)(src + (e - base));
    __half2 h0 = __floats2half2_rn(v.x, v.y);
    __half2 h1 = __floats2half2_rn(v.z, v.w);
    uint2 u; u.x = *(unsigned*)&h0; u.y = *(unsigned*)&h1;
    *(uint2*)(g_xh + e) = u;
}

__global__ void cvt_w_kernel(const float* __restrict__ W1, const float* __restrict__ Wagg) {
    int i = blockIdx.x * 256 + threadIdx.x;
    const int NW1 = HEADS * 256 * 128;
    const int NWA = HEADS * 512 * 128;
    if (i < NW1) {
        int h = i / (256 * 128), r = (i / 128) % 256, c = i % 128;
        g_w1h[h * 256 * 128 + c * 256 + r] = __float2half(W1[i]);
    } else if (i < NW1 + NWA) {
        int j = i - NW1;
        int h = j / (512 * 128), r = (j / 128) % 512, c = j % 128;
        g_waggh[h * 512 * 128 + c * 512 + r] = __float2half(Wagg[j]);
    }
}

// ---------------- mma/cp helpers ----------------
__device__ __forceinline__ void mma_f16(float d[4], const unsigned a[4], const unsigned b[2]) {
    asm volatile(
        "mma.sync.aligned.m16n8k16.row.col.f32.f16.f16.f32 "
        "{%0,%1,%2,%3}, {%4,%5,%6,%7}, {%8,%9}, {%0,%1,%2,%3};\n"
        : "+f"(d[0]), "+f"(d[1]), "+f"(d[2]), "+f"(d[3])
        : "r"(a[0]), "r"(a[1]), "r"(a[2]), "r"(a[3]), "r"(b[0]), "r"(b[1]));
}
__device__ __forceinline__ void cp_async16(void* smem_dst, const void* gmem_src) {
    unsigned s = (unsigned)__cvta_generic_to_shared(smem_dst);
    asm volatile("cp.async.ca.shared.global [%0], [%1], 16;\n" :: "r"(s), "l"(gmem_src));
}
__device__ __forceinline__ void cp_commit() {
    asm volatile("cp.async.commit_group;\n" ::: "memory");
}
template <int N>
__device__ __forceinline__ void cp_wait() {
    asm volatile("cp.async.wait_group %0;\n" :: "n"(N) : "memory");
}

// ============================================================================
// GEMM1 (fp16 m16n8k16, cp.async 3-stage): y = relu(X @ W1h + b1h) + a1/a2 dots
// node-major outputs. grid (12 = lvl*4+h, rowblocks)
// ============================================================================
__global__ __launch_bounds__(256, 2) void gemm1_kernel(
    const float* __restrict__ b1,
    const float* __restrict__ a1w, const float* __restrict__ a1b,
    const float* __restrict__ a2w, const float* __restrict__ a2b)
{
    extern __shared__ __half smem_h[];
    __half (*As)[128][H_STRIDE] = (__half (*)[128][H_STRIDE])smem_h;
    __half (*Bs)[128][H_STRIDE] = (__half (*)[128][H_STRIDE])(smem_h + AH_ELEMS);

    const int lh  = blockIdx.x;
    const int lvl = lh >> 2;
    const int h   = lh & 3;
    const int Nl  = (lvl == 0) ? CN0 : (lvl == 1) ? CN1 : CN2;
    const int row0 = blockIdx.y * 128;
    if (row0 >= Nl) return;

    const __half* Xh = g_xh + ((lvl == 0) ? 0 : (lvl == 1) ? (size_t)CN0 * 256
                                                           : (size_t)(CN0 + CN1) * 256);
    const __half* Wh = g_w1h + (size_t)h * 256 * 128;
    __half* outh; int ldo;
    if (lvl == 0)      { outh = g_cath + (size_t)h * 512; ldo = 2048; }
    else if (lvl == 1) { outh = g_y1h  + (size_t)h * 128; ldo = 512; }
    else               { outh = g_y2h  + (size_t)h * 128; ldo = 512; }

    const int tid = threadIdx.x;
    const int lane = tid & 31;
    const int wid  = tid >> 5;
    const int wR = wid >> 2;
    const int wC = wid & 3;
    const int gid = lane >> 2;
    const int tg  = lane & 3;

    const int rA0 = tid >> 2, rA1 = (tid >> 2) + 64;
    const int kk  = (tid & 3) * 8;
    const int grA0 = min(row0 + rA0, Nl - 1);
    const int grA1 = min(row0 + rA1, Nl - 1);

    float acc[4][4][4];
#pragma unroll
    for (int mt = 0; mt < 4; mt++)
#pragma unroll
        for (int nt = 0; nt < 4; nt++)
#pragma unroll
            for (int r = 0; r < 4; r++) acc[mt][nt][r] = 0.f;

    const int NT = D_IN / 32;   // 8

#define G1_ISSUE(kt, s) do {                                               \
        int k0_ = (kt) * 32;                                               \
        cp_async16(&As[s][rA0][kk], Xh + (size_t)grA0 * 256 + k0_ + kk);   \
        cp_async16(&As[s][rA1][kk], Xh + (size_t)grA1 * 256 + k0_ + kk);   \
        cp_async16(&Bs[s][rA0][kk], Wh + (size_t)rA0 * 256 + k0_ + kk);    \
        cp_async16(&Bs[s][rA1][kk], Wh + (size_t)rA1 * 256 + k0_ + kk);    \
        cp_commit();                                                       \
    } while (0)

    G1_ISSUE(0, 0);
    G1_ISSUE(1, 1);
    cp_wait<1>();
    __syncthreads();

    for (int kt = 0; kt < NT; kt++) {
        if (kt + 2 < NT) G1_ISSUE(kt + 2, (kt + 2) % 3);
        const int s = kt % 3;
#pragma unroll
        for (int ks = 0; ks < 2; ks++) {
            const int kb = ks * 16;
            unsigned af[4][4], bf[4][2];
#pragma unroll
            for (int mt = 0; mt < 4; mt++) {
                int rb = wR * 64 + mt * 16;
                af[mt][0] = *(const unsigned*)&As[s][rb + gid][kb + 2 * tg];
                af[mt][1] = *(const unsigned*)&As[s][rb + gid + 8][kb + 2 * tg];
                af[mt][2] = *(const unsigned*)&As[s][rb + gid][kb + 2 * tg + 8];
                af[mt][3] = *(const unsigned*)&As[s][rb + gid + 8][kb + 2 * tg + 8];
            }
#pragma unroll
            for (int nt = 0; nt < 4; nt++) {
                int cb = wC * 32 + nt * 8;
                bf[nt][0] = *(const unsigned*)&Bs[s][cb + gid][kb + 2 * tg];
                bf[nt][1] = *(const unsigned*)&Bs[s][cb + gid][kb + 2 * tg + 8];
            }
#pragma unroll
            for (int mt = 0; mt < 4; mt++)
#pragma unroll
                for (int nt = 0; nt < 4; nt++)
                    mma_f16(acc[mt][nt], af[mt], bf[nt]);
        }
        if (kt + 1 < NT) {
            if (kt + 2 < NT) cp_wait<1>(); else cp_wait<0>();
            __syncthreads();
        }
    }
#undef G1_ISSUE

    // ---- epilogue: bias + relu + half store + fused attention dots ----
    float* a2out = ((lvl == 0) ? g_a20 : (lvl == 1) ? g_a21 : g_a22) + h;
    const float a2bias = a2b[h];
    const float a1bias = a1b[h];

    float2 biasv[4], w2v[4], w1v[4];
#pragma unroll
    for (int nt = 0; nt < 4; nt++) {
        int c = wC * 32 + nt * 8 + 2 * tg;
        biasv[nt] = *(const float2*)(b1  + h * 128 + c);
        w2v[nt]   = *(const float2*)(a2w + h * 128 + c);
        w1v[nt]   = (lvl == 0) ? *(const float2*)(a1w + h * 128 + c) : make_float2(0.f, 0.f);
    }

    __shared__ float s_red[2][8][4][4];
#pragma unroll
    for (int mt = 0; mt < 4; mt++) {
        int r0 = row0 + wR * 64 + mt * 16 + gid;
        int r1 = r0 + 8;
        float s2a = 0.f, s2b = 0.f, s1a = 0.f, s1b = 0.f;
#pragma unroll
        for (int nt = 0; nt < 4; nt++) {
            int c = wC * 32 + nt * 8 + 2 * tg;
            float v0 = fmaxf(acc[mt][nt][0] + biasv[nt].x, 0.f);
            float v1 = fmaxf(acc[mt][nt][1] + biasv[nt].y, 0.f);
            float v2 = fmaxf(acc[mt][nt][2] + biasv[nt].x, 0.f);
            float v3 = fmaxf(acc[mt][nt][3] + biasv[nt].y, 0.f);
            if (r0 < Nl) *(__half2*)(outh + (size_t)r0 * ldo + c) = __floats2half2_rn(v0, v1);
            if (r1 < Nl) *(__half2*)(outh + (size_t)r1 * ldo + c) = __floats2half2_rn(v2, v3);
            s2a += v0 * w2v[nt].x + v1 * w2v[nt].y;
            s2b += v2 * w2v[nt].x + v3 * w2v[nt].y;
            if (lvl == 0) {
                s1a += v0 * w1v[nt].x + v1 * w1v[nt].y;
                s1b += v2 * w1v[nt].x + v3 * w1v[nt].y;
            }
        }
        s2a += __shfl_xor_sync(0xffffffffu, s2a, 1); s2a += __shfl_xor_sync(0xffffffffu, s2a, 2);
        s2b += __shfl_xor_sync(0xffffffffu, s2b, 1); s2b += __shfl_xor_sync(0xffffffffu, s2b, 2);
        if (lvl == 0) {
            s1a += __shfl_xor_sync(0xffffffffu, s1a, 1); s1a += __shfl_xor_sync(0xffffffffu, s1a, 2);
            s1b += __shfl_xor_sync(0xffffffffu, s1b, 1); s1b += __shfl_xor_sync(0xffffffffu, s1b, 2);
        }
        if (tg == 0) {
            s_red[wR][gid][wC][0] = s2a;
            s_red[wR][gid][wC][1] = s2b;
            s_red[wR][gid][wC][2] = s1a;
            s_red[wR][gid][wC][3] = s1b;
        }
        __syncthreads();
        if (tg == 0 && wC == 0) {
            float t2a = 0.f, t2b = 0.f, t1a = 0.f, t1b = 0.f;
#pragma unroll
            for (int q = 0; q < 4; q++) {
                t2a += s_red[wR][gid][q][0];
                t2b += s_red[wR][gid][q][1];
                t1a += s_red[wR][gid][q][2];
                t1b += s_red[wR][gid][q][3];
            }
            if (r0 < Nl) a2out[r0 * 4] = t2a + a2bias;
            if (r1 < Nl) a2out[r1 * 4] = t2b + a2bias;
            if (lvl == 0) {
                if (r0 < Nl) g_a1[r0 * 4 + h] = t1a + a1bias;
                if (r1 < Nl) g_a1[r1 * 4 + h] = t1b + a1bias;
            }
        }
        __syncthreads();
    }
}

// ---------------- bucket build ----------------
__global__ void bucket_kernel(
    const int* __restrict__ rows0, const int* __restrict__ cols0,
    const int* __restrict__ rows1, const int* __restrict__ cols1,
    const int* __restrict__ rows2, const int* __restrict__ cols2)
{
    int i = blockIdx.x * blockDim.x + threadIdx.x;
    int lvl, e;
    const int *rows, *cols;
    if (i < NNZ0)                    { lvl = 0; e = i;               rows = rows0; cols = cols0; }
    else if (i < NNZ0 + NNZ1)        { lvl = 1; e = i - NNZ0;        rows = rows1; cols = cols1; }
    else if (i < NNZ0 + NNZ1 + NNZ2) { lvl = 2; e = i - NNZ0 - NNZ1; rows = rows2; cols = cols2; }
    else return;
    int r = rows[e], c = cols[e];
    int pos = atomicAdd(&g_cnt[lvl * CN0 + r], 1);
    if (pos < CAP) g_list[(size_t)(lvl * CN0 + r) * CAP + pos] = c;
}

// ---------------- attention gather: head-merged, 4-edge unrolled phase B ------
__global__ __launch_bounds__(256) void agg_kernel()
{
    __shared__ int    s_c[8][64];
    __shared__ float4 s_att[8][64];

    int w = (blockIdx.x * blockDim.x + threadIdx.x) >> 5;
    int wl = (threadIdx.x >> 5);
    int lane = threadIdx.x & 31;
    if (w >= 3 * CN0) return;
    int lvl = w / CN0;
    int row = w - lvl * CN0;

    int n = g_cnt[lvl * CN0 + row];
    if (n > CAP) n = CAP;

    float4 a1v = *(const float4*)(g_a1 + row * 4);

    const float* a2p; const __half* yb; int ns, hs;
    if (lvl == 0)      { a2p = g_a20; yb = g_cath; ns = 2048; hs = 512; }
    else if (lvl == 1) { a2p = g_a21; yb = g_y1h;  ns = 512;  hs = 128; }
    else               { a2p = g_a22; yb = g_y2h;  ns = 512;  hs = 128; }

    const int* lst = g_list + (size_t)(lvl * CN0 + row) * CAP;

    float4 acc[4];
#pragma unroll
    for (int q = 0; q < 4; q++) acc[q] = make_float4(0.f, 0.f, 0.f, 0.f);

    for (int j0 = 0; j0 < n; j0 += 64) {
        int m = n - j0; if (m > 64) m = 64;
        __syncwarp();
        if (lane < m) {
            int c = lst[j0 + lane];
            float4 a2v = *(const float4*)(a2p + c * 4);
            float4 t;
            t.x = 1.f / (1.f + __expf(-(a1v.x + a2v.x)));
            t.y = 1.f / (1.f + __expf(-(a1v.y + a2v.y)));
            t.z = 1.f / (1.f + __expf(-(a1v.z + a2v.z)));
            t.w = 1.f / (1.f + __expf(-(a1v.w + a2v.w)));
            s_c[wl][lane] = c;
            s_att[wl][lane] = t;
        }
        if (lane + 32 < m) {
            int c = lst[j0 + lane + 32];
            float4 a2v = *(const float4*)(a2p + c * 4);
            float4 t;
            t.x = 1.f / (1.f + __expf(-(a1v.x + a2v.x)));
            t.y = 1.f / (1.f + __expf(-(a1v.y + a2v.y)));
            t.z = 1.f / (1.f + __expf(-(a1v.z + a2v.z)));
            t.w = 1.f / (1.f + __expf(-(a1v.w + a2v.w)));
            s_c[wl][lane + 32] = c;
            s_att[wl][lane + 32] = t;
        }
        __syncwarp();
        // phase B: 4 edges x 4 heads = 16 independent gathers in flight
        int i = 0;
        for (; i + 4 <= m; i += 4) {
            const __half* pe[4];
            float4 te[4];
#pragma unroll
            for (int u = 0; u < 4; u++) {
                pe[u] = yb + (size_t)s_c[wl][i + u] * ns;
                te[u] = s_att[wl][i + u];
            }
            uint2 yv[4][4];
#pragma unroll
            for (int u = 0; u < 4; u++)
#pragma unroll
                for (int hh = 0; hh < 4; hh++)
                    yv[u][hh] = *((const uint2*)(pe[u] + hh * hs) + lane);
#pragma unroll
            for (int u = 0; u < 4; u++) {
                float ta[4] = {te[u].x, te[u].y, te[u].z, te[u].w};
#pragma unroll
                for (int hh = 0; hh < 4; hh++) {
                    float2 f0 = __half22float2(*(__half2*)&yv[u][hh].x);
                    float2 f1 = __half22float2(*(__half2*)&yv[u][hh].y);
                    acc[hh].x = fmaf(ta[hh], f0.x, acc[hh].x);
                    acc[hh].y = fmaf(ta[hh], f0.y, acc[hh].y);
                    acc[hh].z = fmaf(ta[hh], f1.x, acc[hh].z);
                    acc[hh].w = fmaf(ta[hh], f1.y, acc[hh].w);
                }
            }
        }
        for (; i < m; i++) {
            int c0 = s_c[wl][i];
            float4 t0 = s_att[wl][i];
            const __half* p0 = yb + (size_t)c0 * ns;
            float t0a[4] = {t0.x, t0.y, t0.z, t0.w};
#pragma unroll
            for (int hh = 0; hh < 4; hh++) {
                uint2 yv = *((const uint2*)(p0 + hh * hs) + lane);
                float2 f0 = __half22float2(*(__half2*)&yv.x);
                float2 f1 = __half22float2(*(__half2*)&yv.y);
                acc[hh].x = fmaf(t0a[hh], f0.x, acc[hh].x);
                acc[hh].y = fmaf(t0a[hh], f0.y, acc[hh].y);
                acc[hh].z = fmaf(t0a[hh], f1.x, acc[hh].z);
                acc[hh].w = fmaf(t0a[hh], f1.y, acc[hh].w);
            }
        }
    }
#pragma unroll
    for (int hh = 0; hh < 4; hh++) {
        __half2 o0 = __floats2half2_rn(acc[hh].x, acc[hh].y);
        __half2 o1 = __floats2half2_rn(acc[hh].z, acc[hh].w);
        uint2 o; o.x = *(unsigned*)&o0; o.y = *(unsigned*)&o1;
        *(uint2*)(g_cath + (size_t)row * 2048 + hh * 512 + 128 + lvl * 128 + lane * 4) = o;
    }
}

// ============================================================================
// GEMM2 (fp16 m16n8k16): out = mean_h(cat_h @ Wagg_h + bagg_h); cat node-major
// ============================================================================
__global__ __launch_bounds__(256, 2) void gemm2_kernel(
    const float* __restrict__ bagg, float* __restrict__ out)
{
    extern __shared__ __half smem_h[];
    __half (*As)[128][H_STRIDE] = (__half (*)[128][H_STRIDE])smem_h;
    __half (*Bs)[128][H_STRIDE] = (__half (*)[128][H_STRIDE])(smem_h + AH_ELEMS);

    const int row0 = blockIdx.x * 128;

    const int tid = threadIdx.x;
    const int lane = tid & 31;
    const int wid  = tid >> 5;
    const int wR = wid >> 2;
    const int wC = wid & 3;
    const int gid = lane >> 2;
    const int tg  = lane & 3;

    const int rA0 = tid >> 2, rA1 = (tid >> 2) + 64;
    const int kk  = (tid & 3) * 8;
    const int grA0 = min(row0 + rA0, CN0 - 1);
    const int grA1 = min(row0 + rA1, CN0 - 1);

    float acc[4][4][4];
#pragma unroll
    for (int mt = 0; mt < 4; mt++)
#pragma unroll
        for (int nt = 0; nt < 4; nt++)
#pragma unroll
            for (int r = 0; r < 4; r++) acc[mt][nt][r] = 0.f;

    const int NT = 64;

#define G2_ISSUE(kt, s) do {                                                          \
        int t_ = (kt);                                                                \
        int h_ = t_ >> 4, k0_ = (t_ & 15) * 32;                                       \
        const __half* W_ = g_waggh + (size_t)h_ * 512 * 128;                          \
        cp_async16(&As[s][rA0][kk], g_cath + (size_t)grA0 * 2048 + h_ * 512 + k0_ + kk); \
        cp_async16(&As[s][rA1][kk], g_cath + (size_t)grA1 * 2048 + h_ * 512 + k0_ + kk); \
        cp_async16(&Bs[s][rA0][kk], W_ + (size_t)rA0 * 512 + k0_ + kk);               \
        cp_async16(&Bs[s][rA1][kk], W_ + (size_t)rA1 * 512 + k0_ + kk);               \
        cp_commit();                                                                  \
    } while (0)

    G2_ISSUE(0, 0);
    G2_ISSUE(1, 1);
    cp_wait<1>();
    __syncthreads();

    for (int kt = 0; kt < NT; kt++) {
        if (kt + 2 < NT) G2_ISSUE(kt + 2, (kt + 2) % 3);
        const int s = kt % 3;
#pragma unroll
        for (int ks = 0; ks < 2; ks++) {
            const int kb = ks * 16;
            unsigned af[4][4], bf[4][2];
#pragma unroll
            for (int mt = 0; mt < 4; mt++) {
                int rb = wR * 64 + mt * 16;
                af[mt][0] = *(const unsigned*)&As[s][rb + gid][kb + 2 * tg];
                af[mt][1] = *(const unsigned*)&As[s][rb + gid + 8][kb + 2 * tg];
                af[mt][2] = *(const unsigned*)&As[s][rb + gid][kb + 2 * tg + 8];
                af[mt][3] = *(const unsigned*)&As[s][rb + gid + 8][kb + 2 * tg + 8];
            }
#pragma unroll
            for (int nt = 0; nt < 4; nt++) {
                int cb = wC * 32 + nt * 8;
                bf[nt][0] = *(const unsigned*)&Bs[s][cb + gid][kb + 2 * tg];
                bf[nt][1] = *(const unsigned*)&Bs[s][cb + gid][kb + 2 * tg + 8];
            }
#pragma unroll
            for (int mt = 0; mt < 4; mt++)
#pragma unroll
                for (int nt = 0; nt < 4; nt++)
                    mma_f16(acc[mt][nt], af[mt], bf[nt]);
        }
        if (kt + 1 < NT) {
            if (kt + 2 < NT) cp_wait<1>(); else cp_wait<0>();
            __syncthreads();
        }
    }
#undef G2_ISSUE

    float2 bsum[4];
#pragma unroll
    for (int nt = 0; nt < 4; nt++) {
        int c = wC * 32 + nt * 8 + 2 * tg;
        float2 s = make_float2(0.f, 0.f);
#pragma unroll
        for (int h = 0; h < HEADS; h++) {
            float2 bg = *(const float2*)(bagg + h * 128 + c);
            s.x += bg.x; s.y += bg.y;
        }
        bsum[nt] = s;
    }
#pragma unroll
    for (int mt = 0; mt < 4; mt++) {
        int r0 = row0 + wR * 64 + mt * 16 + gid;
        int r1 = r0 + 8;
#pragma unroll
        for (int nt = 0; nt < 4; nt++) {
            int c = wC * 32 + nt * 8 + 2 * tg;
            if (r0 < CN0) {
                float2 v;
                v.x = (acc[mt][nt][0] + bsum[nt].x) * 0.25f;
                v.y = (acc[mt][nt][1] + bsum[nt].y) * 0.25f;
                *(float2*)(out + (size_t)r0 * 128 + c) = v;
            }
            if (r1 < CN0) {
                float2 v;
                v.x = (acc[mt][nt][2] + bsum[nt].x) * 0.25f;
                v.y = (acc[mt][nt][3] + bsum[nt].y) * 0.25f;
                *(float2*)(out + (size_t)r1 * 128 + c) = v;
            }
        }
    }
}

// ---------------- launch ----------------
extern "C" void kernel_launch(void* const* d_in, const int* in_sizes, int n_in,
                              void* d_out, int out_size)
{
    const float* x0    = (const float*)d_in[0];
    const float* x1    = (const float*)d_in[1];
    const float* x2    = (const float*)d_in[2];
    const int*   rows0 = (const int*)d_in[3];
    const int*   cols0 = (const int*)d_in[4];
    const int*   rows1 = (const int*)d_in[5];
    const int*   cols1 = (const int*)d_in[6];
    const int*   rows2 = (const int*)d_in[7];
    const int*   cols2 = (const int*)d_in[8];
    const float* W1    = (const float*)d_in[9];
    const float* b1    = (const float*)d_in[10];
    const float* a1w   = (const float*)d_in[11];
    const float* a1b   = (const float*)d_in[12];
    const float* a2w   = (const float*)d_in[13];
    const float* a2b   = (const float*)d_in[14];
    const float* Wagg  = (const float*)d_in[15];
    const float* bagg  = (const float*)d_in[16];
    float* out = (float*)d_out;

    cudaFuncSetAttribute(gemm1_kernel, cudaFuncAttributeMaxDynamicSharedMemorySize, GEMM_SMEM_BYTES);
    cudaFuncSetAttribute(gemm2_kernel, cudaFuncAttributeMaxDynamicSharedMemorySize, GEMM_SMEM_BYTES);

    zero_cnt_kernel<<<(3 * CN0 + 255) / 256, 256>>>();
    bucket_kernel<<<(NNZ0 + NNZ1 + NNZ2 + 255) / 256, 256>>>(
        rows0, cols0, rows1, cols1, rows2, cols2);

    cvt_x_kernel<<<(int)((NXH / 4 + 255) / 256), 256>>>(x0, x1, x2);
    cvt_w_kernel<<<(HEADS * 256 * 128 + HEADS * 512 * 128 + 255) / 256, 256>>>(W1, Wagg);

    {
        dim3 grid(12, (CN1 + 127) / 128);
        gemm1_kernel<<<grid, 256, GEMM_SMEM_BYTES>>>(b1, a1w, a1b, a2w, a2b);
    }
    {
        int warps = 3 * CN0;
        agg_kernel<<<(warps * 32 + 255) / 256, 256>>>();
    }
    gemm2_kernel<<<(CN0 + 127) / 128, 256, GEMM_SMEM_BYTES>>>(bagg, out);
}

// round 11
// speedup vs baseline: 3.7730x; 1.0430x over previous
#include <cuda_runtime.h>
#include <cuda_fp16.h>
#include <math.h>

#define CN0 30000
#define CN1 90000
#define CN2 60000
#define D_IN 256
#define D_OUT 128
#define HEADS 4
#define NNZ0 960000
#define NNZ1 180000
#define NNZ2 180000
#define CAP 256

// fp16 GEMM smem: 3-stage, A[128][40] + B[128][40] halves per stage
#define H_STRIDE 40
#define AH_ELEMS (3 * 128 * H_STRIDE)
#define GEMM_SMEM_BYTES (2 * AH_ELEMS * 2)

#define NXH ((size_t)(CN0 + CN1 + CN2) * 256)

// ---------------- scratch (node-major layouts) ----------------
__device__ __half g_xh[NXH];                        // fp16 inputs (x0|x1|x2)
__device__ __half g_w1h[HEADS * 256 * 128];         // W1 transposed  [h][n][k]
__device__ __half g_waggh[HEADS * 512 * 128];       // Wagg transposed [h][n][k]
__device__ __half g_y1h[(size_t)CN1 * HEADS * 128]; // [node][h][128]
__device__ __half g_y2h[(size_t)CN2 * HEADS * 128];
__device__ __half g_cath[(size_t)CN0 * HEADS * 512];// [row][h][ xi0 | agg0 | agg1 | agg2 ]
__device__ float g_a1[CN0 * 4];                     // [row][h]
__device__ float g_a20[CN0 * 4];
__device__ float g_a21[CN1 * 4];
__device__ float g_a22[CN2 * 4];
__device__ int   g_cnt[3 * CN0];
__device__ int   g_list[3 * CN0 * CAP];

__global__ void zero_cnt_kernel() {
    int i = blockIdx.x * blockDim.x + threadIdx.x;
    if (i < 3 * CN0) g_cnt[i] = 0;
}

// ---------------- converts ----------------
__global__ void cvt_x_kernel(const float* __restrict__ x0, const float* __restrict__ x1,
                             const float* __restrict__ x2) {
    size_t i = (size_t)blockIdx.x * 256 + threadIdx.x;
    if (i >= NXH / 4) return;
    size_t e = i * 4;
    const float* src; size_t base;
    if (e < (size_t)CN0 * 256)               { src = x0; base = 0; }
    else if (e < (size_t)(CN0 + CN1) * 256)  { src = x1; base = (size_t)CN0 * 256; }
    else                                     { src = x2; base = (size_t)(CN0 + CN1) * 256; }
    float4 v = *(const float4*)(src + (e - base));
    __half2 h0 = __floats2half2_rn(v.x, v.y);
    __half2 h1 = __floats2half2_rn(v.z, v.w);
    uint2 u; u.x = *(unsigned*)&h0; u.y = *(unsigned*)&h1;
    *(uint2*)(g_xh + e) = u;
}

__global__ void cvt_w_kernel(const float* __restrict__ W1, const float* __restrict__ Wagg) {
    int i = blockIdx.x * 256 + threadIdx.x;
    const int NW1 = HEADS * 256 * 128;
    const int NWA = HEADS * 512 * 128;
    if (i < NW1) {
        int h = i / (256 * 128), r = (i / 128) % 256, c = i % 128;
        g_w1h[h * 256 * 128 + c * 256 + r] = __float2half(W1[i]);
    } else if (i < NW1 + NWA) {
        int j = i - NW1;
        int h = j / (512 * 128), r = (j / 128) % 512, c = j % 128;
        g_waggh[h * 512 * 128 + c * 512 + r] = __float2half(Wagg[j]);
    }
}

// ---------------- helpers ----------------
__device__ __forceinline__ unsigned smem_u32(const void* p) {
    unsigned a;
    asm("{ .reg .u64 t; cvta.to.shared.u64 t, %1; cvt.u32.u64 %0, t; }" : "=r"(a) : "l"(p));
    return a;
}
__device__ __forceinline__ void mma_f16(float d[4], const unsigned a[4], const unsigned b[2]) {
    asm volatile(
        "mma.sync.aligned.m16n8k16.row.col.f32.f16.f16.f32 "
        "{%0,%1,%2,%3}, {%4,%5,%6,%7}, {%8,%9}, {%0,%1,%2,%3};\n"
        : "+f"(d[0]), "+f"(d[1]), "+f"(d[2]), "+f"(d[3])
        : "r"(a[0]), "r"(a[1]), "r"(a[2]), "r"(a[3]), "r"(b[0]), "r"(b[1]));
}
__device__ __forceinline__ void ldsm_x4(unsigned& r0, unsigned& r1, unsigned& r2, unsigned& r3,
                                        unsigned addr) {
    asm volatile("ldmatrix.sync.aligned.m8n8.x4.shared.b16 {%0,%1,%2,%3}, [%4];"
                 : "=r"(r0), "=r"(r1), "=r"(r2), "=r"(r3) : "r"(addr));
}
__device__ __forceinline__ void cp_async16(void* smem_dst, const void* gmem_src) {
    unsigned s = (unsigned)__cvta_generic_to_shared(smem_dst);
    asm volatile("cp.async.ca.shared.global [%0], [%1], 16;\n" :: "r"(s), "l"(gmem_src));
}
__device__ __forceinline__ void cp_commit() {
    asm volatile("cp.async.commit_group;\n" ::: "memory");
}
template <int N>
__device__ __forceinline__ void cp_wait() {
    asm volatile("cp.async.wait_group %0;\n" :: "n"(N) : "memory");
}

// ============================================================================
// GEMM1 (fp16 m16n8k16 + ldmatrix, cp.async 3-stage)
// y = relu(X @ W1h + b1h) + fused a1/a2 dots; node-major outputs.
// grid (12 = lvl*4+h, rowblocks)
// ============================================================================
__global__ __launch_bounds__(256, 2) void gemm1_kernel(
    const float* __restrict__ b1,
    const float* __restrict__ a1w, const float* __restrict__ a1b,
    const float* __restrict__ a2w, const float* __restrict__ a2b)
{
    extern __shared__ __half smem_h[];
    __half (*As)[128][H_STRIDE] = (__half (*)[128][H_STRIDE])smem_h;
    __half (*Bs)[128][H_STRIDE] = (__half (*)[128][H_STRIDE])(smem_h + AH_ELEMS);

    const int lh  = blockIdx.x;
    const int lvl = lh >> 2;
    const int h   = lh & 3;
    const int Nl  = (lvl == 0) ? CN0 : (lvl == 1) ? CN1 : CN2;
    const int row0 = blockIdx.y * 128;
    if (row0 >= Nl) return;

    const __half* Xh = g_xh + ((lvl == 0) ? 0 : (lvl == 1) ? (size_t)CN0 * 256
                                                           : (size_t)(CN0 + CN1) * 256);
    const __half* Wh = g_w1h + (size_t)h * 256 * 128;
    __half* outh; int ldo;
    if (lvl == 0)      { outh = g_cath + (size_t)h * 512; ldo = 2048; }
    else if (lvl == 1) { outh = g_y1h  + (size_t)h * 128; ldo = 512; }
    else               { outh = g_y2h  + (size_t)h * 128; ldo = 512; }

    const int tid = threadIdx.x;
    const int lane = tid & 31;
    const int wid  = tid >> 5;
    const int wR = wid >> 2;
    const int wC = wid & 3;
    const int gid = lane >> 2;
    const int tg  = lane & 3;

    const int rA0 = tid >> 2, rA1 = (tid >> 2) + 64;
    const int kk  = (tid & 3) * 8;
    const int grA0 = min(row0 + rA0, Nl - 1);
    const int grA1 = min(row0 + rA1, Nl - 1);

    // ldmatrix lane addressing
    const int a_row = lane & 15;
    const int a_koff = (lane >> 4) << 3;
    const int b_row = lane & 7;
    const int b_koff = ((lane >> 3) & 1) << 3;
    const int b_ngrp = (lane >> 4) << 3;

    float acc[4][4][4];
#pragma unroll
    for (int mt = 0; mt < 4; mt++)
#pragma unroll
        for (int nt = 0; nt < 4; nt++)
#pragma unroll
            for (int r = 0; r < 4; r++) acc[mt][nt][r] = 0.f;

    const int NT = D_IN / 32;   // 8

#define G1_ISSUE(kt, s) do {                                               \
        int k0_ = (kt) * 32;                                               \
        cp_async16(&As[s][rA0][kk], Xh + (size_t)grA0 * 256 + k0_ + kk);   \
        cp_async16(&As[s][rA1][kk], Xh + (size_t)grA1 * 256 + k0_ + kk);   \
        cp_async16(&Bs[s][rA0][kk], Wh + (size_t)rA0 * 256 + k0_ + kk);    \
        cp_async16(&Bs[s][rA1][kk], Wh + (size_t)rA1 * 256 + k0_ + kk);    \
        cp_commit();                                                       \
    } while (0)

    G1_ISSUE(0, 0);
    G1_ISSUE(1, 1);
    cp_wait<1>();
    __syncthreads();

    for (int kt = 0; kt < NT; kt++) {
        if (kt + 2 < NT) G1_ISSUE(kt + 2, (kt + 2) % 3);
        const int s = kt % 3;
#pragma unroll
        for (int ks = 0; ks < 2; ks++) {
            const int kb = ks * 16;
            unsigned af[4][4], bf[4][2];
#pragma unroll
            for (int mt = 0; mt < 4; mt++) {
                int rb = wR * 64 + mt * 16;
                unsigned addr = smem_u32(&As[s][rb + a_row][kb + a_koff]);
                ldsm_x4(af[mt][0], af[mt][1], af[mt][2], af[mt][3], addr);
            }
#pragma unroll
            for (int p = 0; p < 2; p++) {
                int cb = wC * 32 + p * 16;
                unsigned addr = smem_u32(&Bs[s][cb + b_ngrp + b_row][kb + b_koff]);
                unsigned r0, r1, r2, r3;
                ldsm_x4(r0, r1, r2, r3, addr);
                bf[2 * p][0] = r0; bf[2 * p][1] = r1;
                bf[2 * p + 1][0] = r2; bf[2 * p + 1][1] = r3;
            }
#pragma unroll
            for (int mt = 0; mt < 4; mt++)
#pragma unroll
                for (int nt = 0; nt < 4; nt++)
                    mma_f16(acc[mt][nt], af[mt], bf[nt]);
        }
        if (kt + 1 < NT) {
            if (kt + 2 < NT) cp_wait<1>(); else cp_wait<0>();
            __syncthreads();
        }
    }
#undef G1_ISSUE

    // ---- epilogue: bias + relu + half store + fused attention dots ----
    float* a2out = ((lvl == 0) ? g_a20 : (lvl == 1) ? g_a21 : g_a22) + h;
    const float a2bias = a2b[h];
    const float a1bias = a1b[h];

    float2 biasv[4], w2v[4], w1v[4];
#pragma unroll
    for (int nt = 0; nt < 4; nt++) {
        int c = wC * 32 + nt * 8 + 2 * tg;
        biasv[nt] = *(const float2*)(b1  + h * 128 + c);
        w2v[nt]   = *(const float2*)(a2w + h * 128 + c);
        w1v[nt]   = (lvl == 0) ? *(const float2*)(a1w + h * 128 + c) : make_float2(0.f, 0.f);
    }

    __shared__ float s_red[2][8][4][4];
#pragma unroll
    for (int mt = 0; mt < 4; mt++) {
        int r0 = row0 + wR * 64 + mt * 16 + gid;
        int r1 = r0 + 8;
        float s2a = 0.f, s2b = 0.f, s1a = 0.f, s1b = 0.f;
#pragma unroll
        for (int nt = 0; nt < 4; nt++) {
            int c = wC * 32 + nt * 8 + 2 * tg;
            float v0 = fmaxf(acc[mt][nt][0] + biasv[nt].x, 0.f);
            float v1 = fmaxf(acc[mt][nt][1] + biasv[nt].y, 0.f);
            float v2 = fmaxf(acc[mt][nt][2] + biasv[nt].x, 0.f);
            float v3 = fmaxf(acc[mt][nt][3] + biasv[nt].y, 0.f);
            if (r0 < Nl) *(__half2*)(outh + (size_t)r0 * ldo + c) = __floats2half2_rn(v0, v1);
            if (r1 < Nl) *(__half2*)(outh + (size_t)r1 * ldo + c) = __floats2half2_rn(v2, v3);
            s2a += v0 * w2v[nt].x + v1 * w2v[nt].y;
            s2b += v2 * w2v[nt].x + v3 * w2v[nt].y;
            if (lvl == 0) {
                s1a += v0 * w1v[nt].x + v1 * w1v[nt].y;
                s1b += v2 * w1v[nt].x + v3 * w1v[nt].y;
            }
        }
        s2a += __shfl_xor_sync(0xffffffffu, s2a, 1); s2a += __shfl_xor_sync(0xffffffffu, s2a, 2);
        s2b += __shfl_xor_sync(0xffffffffu, s2b, 1); s2b += __shfl_xor_sync(0xffffffffu, s2b, 2);
        if (lvl == 0) {
            s1a += __shfl_xor_sync(0xffffffffu, s1a, 1); s1a += __shfl_xor_sync(0xffffffffu, s1a, 2);
            s1b += __shfl_xor_sync(0xffffffffu, s1b, 1); s1b += __shfl_xor_sync(0xffffffffu, s1b, 2);
        }
        if (tg == 0) {
            s_red[wR][gid][wC][0] = s2a;
            s_red[wR][gid][wC][1] = s2b;
            s_red[wR][gid][wC][2] = s1a;
            s_red[wR][gid][wC][3] = s1b;
        }
        __syncthreads();
        if (tg == 0 && wC == 0) {
            float t2a = 0.f, t2b = 0.f, t1a = 0.f, t1b = 0.f;
#pragma unroll
            for (int q = 0; q < 4; q++) {
                t2a += s_red[wR][gid][q][0];
                t2b += s_red[wR][gid][q][1];
                t1a += s_red[wR][gid][q][2];
                t1b += s_red[wR][gid][q][3];
            }
            if (r0 < Nl) a2out[r0 * 4] = t2a + a2bias;
            if (r1 < Nl) a2out[r1 * 4] = t2b + a2bias;
            if (lvl == 0) {
                if (r0 < Nl) g_a1[r0 * 4 + h] = t1a + a1bias;
                if (r1 < Nl) g_a1[r1 * 4 + h] = t1b + a1bias;
            }
        }
        __syncthreads();
    }
}

// ---------------- bucket build ----------------
__global__ void bucket_kernel(
    const int* __restrict__ rows0, const int* __restrict__ cols0,
    const int* __restrict__ rows1, const int* __restrict__ cols1,
    const int* __restrict__ rows2, const int* __restrict__ cols2)
{
    int i = blockIdx.x * blockDim.x + threadIdx.x;
    int lvl, e;
    const int *rows, *cols;
    if (i < NNZ0)                    { lvl = 0; e = i;               rows = rows0; cols = cols0; }
    else if (i < NNZ0 + NNZ1)        { lvl = 1; e = i - NNZ0;        rows = rows1; cols = cols1; }
    else if (i < NNZ0 + NNZ1 + NNZ2) { lvl = 2; e = i - NNZ0 - NNZ1; rows = rows2; cols = cols2; }
    else return;
    int r = rows[e], c = cols[e];
    int pos = atomicAdd(&g_cnt[lvl * CN0 + r], 1);
    if (pos < CAP) g_list[(size_t)(lvl * CN0 + r) * CAP + pos] = c;
}

// ---------------- attention gather: head-merged, 4-edge unrolled phase B ------
__global__ __launch_bounds__(256) void agg_kernel()
{
    __shared__ int    s_c[8][64];
    __shared__ float4 s_att[8][64];

    int w = (blockIdx.x * blockDim.x + threadIdx.x) >> 5;
    int wl = (threadIdx.x >> 5);
    int lane = threadIdx.x & 31;
    if (w >= 3 * CN0) return;
    int lvl = w / CN0;
    int row = w - lvl * CN0;

    int n = g_cnt[lvl * CN0 + row];
    if (n > CAP) n = CAP;

    float4 a1v = *(const float4*)(g_a1 + row * 4);

    const float* a2p; const __half* yb; int ns, hs;
    if (lvl == 0)      { a2p = g_a20; yb = g_cath; ns = 2048; hs = 512; }
    else if (lvl == 1) { a2p = g_a21; yb = g_y1h;  ns = 512;  hs = 128; }
    else               { a2p = g_a22; yb = g_y2h;  ns = 512;  hs = 128; }

    const int* lst = g_list + (size_t)(lvl * CN0 + row) * CAP;

    float4 acc[4];
#pragma unroll
    for (int q = 0; q < 4; q++) acc[q] = make_float4(0.f, 0.f, 0.f, 0.f);

    for (int j0 = 0; j0 < n; j0 += 64) {
        int m = n - j0; if (m > 64) m = 64;
        __syncwarp();
        if (lane < m) {
            int c = lst[j0 + lane];
            float4 a2v = *(const float4*)(a2p + c * 4);
            float4 t;
            t.x = 1.f / (1.f + __expf(-(a1v.x + a2v.x)));
            t.y = 1.f / (1.f + __expf(-(a1v.y + a2v.y)));
            t.z = 1.f / (1.f + __expf(-(a1v.z + a2v.z)));
            t.w = 1.f / (1.f + __expf(-(a1v.w + a2v.w)));
            s_c[wl][lane] = c;
            s_att[wl][lane] = t;
        }
        if (lane + 32 < m) {
            int c = lst[j0 + lane + 32];
            float4 a2v = *(const float4*)(a2p + c * 4);
            float4 t;
            t.x = 1.f / (1.f + __expf(-(a1v.x + a2v.x)));
            t.y = 1.f / (1.f + __expf(-(a1v.y + a2v.y)));
            t.z = 1.f / (1.f + __expf(-(a1v.z + a2v.z)));
            t.w = 1.f / (1.f + __expf(-(a1v.w + a2v.w)));
            s_c[wl][lane + 32] = c;
            s_att[wl][lane + 32] = t;
        }
        __syncwarp();
        int i = 0;
        for (; i + 4 <= m; i += 4) {
            const __half* pe[4];
            float4 te[4];
#pragma unroll
            for (int u = 0; u < 4; u++) {
                pe[u] = yb + (size_t)s_c[wl][i + u] * ns;
                te[u] = s_att[wl][i + u];
            }
            uint2 yv[4][4];
#pragma unroll
            for (int u = 0; u < 4; u++)
#pragma unroll
                for (int hh = 0; hh < 4; hh++)
                    yv[u][hh] = *((const uint2*)(pe[u] + hh * hs) + lane);
#pragma unroll
            for (int u = 0; u < 4; u++) {
                float ta[4] = {te[u].x, te[u].y, te[u].z, te[u].w};
#pragma unroll
                for (int hh = 0; hh < 4; hh++) {
                    float2 f0 = __half22float2(*(__half2*)&yv[u][hh].x);
                    float2 f1 = __half22float2(*(__half2*)&yv[u][hh].y);
                    acc[hh].x = fmaf(ta[hh], f0.x, acc[hh].x);
                    acc[hh].y = fmaf(ta[hh], f0.y, acc[hh].y);
                    acc[hh].z = fmaf(ta[hh], f1.x, acc[hh].z);
                    acc[hh].w = fmaf(ta[hh], f1.y, acc[hh].w);
                }
            }
        }
        for (; i < m; i++) {
            int c0 = s_c[wl][i];
            float4 t0 = s_att[wl][i];
            const __half* p0 = yb + (size_t)c0 * ns;
            float t0a[4] = {t0.x, t0.y, t0.z, t0.w};
#pragma unroll
            for (int hh = 0; hh < 4; hh++) {
                uint2 yv = *((const uint2*)(p0 + hh * hs) + lane);
                float2 f0 = __half22float2(*(__half2*)&yv.x);
                float2 f1 = __half22float2(*(__half2*)&yv.y);
                acc[hh].x = fmaf(t0a[hh], f0.x, acc[hh].x);
                acc[hh].y = fmaf(t0a[hh], f0.y, acc[hh].y);
                acc[hh].z = fmaf(t0a[hh], f1.x, acc[hh].z);
                acc[hh].w = fmaf(t0a[hh], f1.y, acc[hh].w);
            }
        }
    }
#pragma unroll
    for (int hh = 0; hh < 4; hh++) {
        __half2 o0 = __floats2half2_rn(acc[hh].x, acc[hh].y);
        __half2 o1 = __floats2half2_rn(acc[hh].z, acc[hh].w);
        uint2 o; o.x = *(unsigned*)&o0; o.y = *(unsigned*)&o1;
        *(uint2*)(g_cath + (size_t)row * 2048 + hh * 512 + 128 + lvl * 128 + lane * 4) = o;
    }
}

// ============================================================================
// GEMM2 (fp16 m16n8k16 + ldmatrix): out = mean_h(cat_h @ Wagg_h + bagg_h)
// ============================================================================
__global__ __launch_bounds__(256, 2) void gemm2_kernel(
    const float* __restrict__ bagg, float* __restrict__ out)
{
    extern __shared__ __half smem_h[];
    __half (*As)[128][H_STRIDE] = (__half (*)[128][H_STRIDE])smem_h;
    __half (*Bs)[128][H_STRIDE] = (__half (*)[128][H_STRIDE])(smem_h + AH_ELEMS);

    const int row0 = blockIdx.x * 128;

    const int tid = threadIdx.x;
    const int lane = tid & 31;
    const int wid  = tid >> 5;
    const int wR = wid >> 2;
    const int wC = wid & 3;
    const int gid = lane >> 2;
    const int tg  = lane & 3;

    const int rA0 = tid >> 2, rA1 = (tid >> 2) + 64;
    const int kk  = (tid & 3) * 8;
    const int grA0 = min(row0 + rA0, CN0 - 1);
    const int grA1 = min(row0 + rA1, CN0 - 1);

    const int a_row = lane & 15;
    const int a_koff = (lane >> 4) << 3;
    const int b_row = lane & 7;
    const int b_koff = ((lane >> 3) & 1) << 3;
    const int b_ngrp = (lane >> 4) << 3;

    float acc[4][4][4];
#pragma unroll
    for (int mt = 0; mt < 4; mt++)
#pragma unroll
        for (int nt = 0; nt < 4; nt++)
#pragma unroll
            for (int r = 0; r < 4; r++) acc[mt][nt][r] = 0.f;

    const int NT = 64;

#define G2_ISSUE(kt, s) do {                                                          \
        int t_ = (kt);                                                                \
        int h_ = t_ >> 4, k0_ = (t_ & 15) * 32;                                       \
        const __half* W_ = g_waggh + (size_t)h_ * 512 * 128;                          \
        cp_async16(&As[s][rA0][kk], g_cath + (size_t)grA0 * 2048 + h_ * 512 + k0_ + kk); \
        cp_async16(&As[s][rA1][kk], g_cath + (size_t)grA1 * 2048 + h_ * 512 + k0_ + kk); \
        cp_async16(&Bs[s][rA0][kk], W_ + (size_t)rA0 * 512 + k0_ + kk);               \
        cp_async16(&Bs[s][rA1][kk], W_ + (size_t)rA1 * 512 + k0_ + kk);               \
        cp_commit();                                                                  \
    } while (0)

    G2_ISSUE(0, 0);
    G2_ISSUE(1, 1);
    cp_wait<1>();
    __syncthreads();

    for (int kt = 0; kt < NT; kt++) {
        if (kt + 2 < NT) G2_ISSUE(kt + 2, (kt + 2) % 3);
        const int s = kt % 3;
#pragma unroll
        for (int ks = 0; ks < 2; ks++) {
            const int kb = ks * 16;
            unsigned af[4][4], bf[4][2];
#pragma unroll
            for (int mt = 0; mt < 4; mt++) {
                int rb = wR * 64 + mt * 16;
                unsigned addr = smem_u32(&As[s][rb + a_row][kb + a_koff]);
                ldsm_x4(af[mt][0], af[mt][1], af[mt][2], af[mt][3], addr);
            }
#pragma unroll
            for (int p = 0; p < 2; p++) {
                int cb = wC * 32 + p * 16;
                unsigned addr = smem_u32(&Bs[s][cb + b_ngrp + b_row][kb + b_koff]);
                unsigned r0, r1, r2, r3;
                ldsm_x4(r0, r1, r2, r3, addr);
                bf[2 * p][0] = r0; bf[2 * p][1] = r1;
                bf[2 * p + 1][0] = r2; bf[2 * p + 1][1] = r3;
            }
#pragma unroll
            for (int mt = 0; mt < 4; mt++)
#pragma unroll
                for (int nt = 0; nt < 4; nt++)
                    mma_f16(acc[mt][nt], af[mt], bf[nt]);
        }
        if (kt + 1 < NT) {
            if (kt + 2 < NT) cp_wait<1>(); else cp_wait<0>();
            __syncthreads();
        }
    }
#undef G2_ISSUE

    float2 bsum[4];
#pragma unroll
    for (int nt = 0; nt < 4; nt++) {
        int c = wC * 32 + nt * 8 + 2 * tg;
        float2 s = make_float2(0.f, 0.f);
#pragma unroll
        for (int h = 0; h < HEADS; h++) {
            float2 bg = *(const float2*)(bagg + h * 128 + c);
            s.x += bg.x; s.y += bg.y;
        }
        bsum[nt] = s;
    }
#pragma unroll
    for (int mt = 0; mt < 4; mt++) {
        int r0 = row0 + wR * 64 + mt * 16 + gid;
        int r1 = r0 + 8;
#pragma unroll
        for (int nt = 0; nt < 4; nt++) {
            int c = wC * 32 + nt * 8 + 2 * tg;
            if (r0 < CN0) {
                float2 v;
                v.x = (acc[mt][nt][0] + bsum[nt].x) * 0.25f;
                v.y = (acc[mt][nt][1] + bsum[nt].y) * 0.25f;
                *(float2*)(out + (size_t)r0 * 128 + c) = v;
            }
            if (r1 < CN0) {
                float2 v;
                v.x = (acc[mt][nt][2] + bsum[nt].x) * 0.25f;
                v.y = (acc[mt][nt][3] + bsum[nt].y) * 0.25f;
                *(float2*)(out + (size_t)r1 * 128 + c) = v;
            }
        }
    }
}

// ---------------- launch ----------------
extern "C" void kernel_launch(void* const* d_in, const int* in_sizes, int n_in,
                              void* d_out, int out_size)
{
    const float* x0    = (const float*)d_in[0];
    const float* x1    = (const float*)d_in[1];
    const float* x2    = (const float*)d_in[2];
    const int*   rows0 = (const int*)d_in[3];
    const int*   cols0 = (const int*)d_in[4];
    const int*   rows1 = (const int*)d_in[5];
    const int*   cols1 = (const int*)d_in[6];
    const int*   rows2 = (const int*)d_in[7];
    const int*   cols2 = (const int*)d_in[8];
    const float* W1    = (const float*)d_in[9];
    const float* b1    = (const float*)d_in[10];
    const float* a1w   = (const float*)d_in[11];
    const float* a1b   = (const float*)d_in[12];
    const float* a2w   = (const float*)d_in[13];
    const float* a2b   = (const float*)d_in[14];
    const float* Wagg  = (const float*)d_in[15];
    const float* bagg  = (const float*)d_in[16];
    float* out = (float*)d_out;

    cudaFuncSetAttribute(gemm1_kernel, cudaFuncAttributeMaxDynamicSharedMemorySize, GEMM_SMEM_BYTES);
    cudaFuncSetAttribute(gemm2_kernel, cudaFuncAttributeMaxDynamicSharedMemorySize, GEMM_SMEM_BYTES);

    zero_cnt_kernel<<<(3 * CN0 + 255) / 256, 256>>>();
    bucket_kernel<<<(NNZ0 + NNZ1 + NNZ2 + 255) / 256, 256>>>(
        rows0, cols0, rows1, cols1, rows2, cols2);

    cvt_x_kernel<<<(int)((NXH / 4 + 255) / 256), 256>>>(x0, x1, x2);
    cvt_w_kernel<<<(HEADS * 256 * 128 + HEADS * 512 * 128 + 255) / 256, 256>>>(W1, Wagg);

    {
        dim3 grid(12, (CN1 + 127) / 128);
        gemm1_kernel<<<grid, 256, GEMM_SMEM_BYTES>>>(b1, a1w, a1b, a2w, a2b);
    }
    {
        int warps = 3 * CN0;
        agg_kernel<<<(warps * 32 + 255) / 256, 256>>>();
    }
    gemm2_kernel<<<(CN0 + 127) / 128, 256, GEMM_SMEM_BYTES>>>(bagg, out);
}

// round 12
// speedup vs baseline: 3.8281x; 1.0146x over previous
#include <cuda_runtime.h>
#include <cuda_fp16.h>
#include <math.h>

#define CN0 30000
#define CN1 90000
#define CN2 60000
#define D_IN 256
#define D_OUT 128
#define HEADS 4
#define NNZ0 960000
#define NNZ1 180000
#define NNZ2 180000
#define CAP 256

#define H_STRIDE 40
#define AH_ELEMS (3 * 128 * H_STRIDE)
#define GEMM_SMEM_BYTES (2 * AH_ELEMS * 2)

#define NXH ((size_t)(CN0 + CN1 + CN2) * 256)

// ---------------- scratch ----------------
// g_cath layout: [row][seg][h][128]  seg: 0=xi0 1=agg0 2=agg1 3=agg2
//   -> every seg is a 1KB contiguous block of 4 heads x 256B
// g_y1h/g_y2h: [node][h][128] -> 1KB contiguous block
__device__ __half g_xh[NXH];
__device__ __half g_w1h[HEADS * 256 * 128];         // [h][n][k]
__device__ __half g_waggh[HEADS * 512 * 128];       // [h][n][k]
__device__ __half g_y1h[(size_t)CN1 * HEADS * 128];
__device__ __half g_y2h[(size_t)CN2 * HEADS * 128];
__device__ __half g_cath[(size_t)CN0 * HEADS * 512];
__device__ float g_a1[CN0 * 4];
__device__ float g_a20[CN0 * 4];
__device__ float g_a21[CN1 * 4];
__device__ float g_a22[CN2 * 4];
__device__ int   g_cnt[3 * CN0];
__device__ int   g_list[3 * CN0 * CAP];

// ---------------- converts (+ counter zeroing folded in) ----------------
__global__ void cvt_x_kernel(const float* __restrict__ x0, const float* __restrict__ x1,
                             const float* __restrict__ x2) {
    size_t i = (size_t)blockIdx.x * 256 + threadIdx.x;
    if (i >= NXH / 4) return;
    size_t e = i * 4;
    const float* src; size_t base;
    if (e < (size_t)CN0 * 256)               { src = x0; base = 0; }
    else if (e < (size_t)(CN0 + CN1) * 256)  { src = x1; base = (size_t)CN0 * 256; }
    else                                     { src = x2; base = (size_t)(CN0 + CN1) * 256; }
    float4 v = *(const float4*)(src + (e - base));
    __half2 h0 = __floats2half2_rn(v.x, v.y);
    __half2 h1 = __floats2half2_rn(v.z, v.w);
    uint2 u; u.x = *(unsigned*)&h0; u.y = *(unsigned*)&h1;
    *(uint2*)(g_xh + e) = u;
}

__global__ void cvt_w_kernel(const float* __restrict__ W1, const float* __restrict__ Wagg) {
    int i = blockIdx.x * 256 + threadIdx.x;
    if (i < 3 * CN0) g_cnt[i] = 0;          // fold zero_cnt here (runs before bucket)
    const int NW1 = HEADS * 256 * 128;
    const int NWA = HEADS * 512 * 128;
    if (i < NW1) {
        int h = i / (256 * 128), r = (i / 128) % 256, c = i % 128;
        g_w1h[h * 256 * 128 + c * 256 + r] = __float2half(W1[i]);
    } else if (i < NW1 + NWA) {
        int j = i - NW1;
        int h = j / (512 * 128), r = (j / 128) % 512, c = j % 128;
        g_waggh[h * 512 * 128 + c * 512 + r] = __float2half(Wagg[j]);
    }
}

// ---------------- helpers ----------------
__device__ __forceinline__ unsigned smem_u32(const void* p) {
    unsigned a;
    asm("{ .reg .u64 t; cvta.to.shared.u64 t, %1; cvt.u32.u64 %0, t; }" : "=r"(a) : "l"(p));
    return a;
}
__device__ __forceinline__ void mma_f16(float d[4], const unsigned a[4], const unsigned b[2]) {
    asm volatile(
        "mma.sync.aligned.m16n8k16.row.col.f32.f16.f16.f32 "
        "{%0,%1,%2,%3}, {%4,%5,%6,%7}, {%8,%9}, {%0,%1,%2,%3};\n"
        : "+f"(d[0]), "+f"(d[1]), "+f"(d[2]), "+f"(d[3])
        : "r"(a[0]), "r"(a[1]), "r"(a[2]), "r"(a[3]), "r"(b[0]), "r"(b[1]));
}
__device__ __forceinline__ void ldsm_x4(unsigned& r0, unsigned& r1, unsigned& r2, unsigned& r3,
                                        unsigned addr) {
    asm volatile("ldmatrix.sync.aligned.m8n8.x4.shared.b16 {%0,%1,%2,%3}, [%4];"
                 : "=r"(r0), "=r"(r1), "=r"(r2), "=r"(r3) : "r"(addr));
}
__device__ __forceinline__ void cp_async16(void* smem_dst, const void* gmem_src) {
    unsigned s = (unsigned)__cvta_generic_to_shared(smem_dst);
    asm volatile("cp.async.ca.shared.global [%0], [%1], 16;\n" :: "r"(s), "l"(gmem_src));
}
__device__ __forceinline__ void cp_commit() {
    asm volatile("cp.async.commit_group;\n" ::: "memory");
}
template <int N>
__device__ __forceinline__ void cp_wait() {
    asm volatile("cp.async.wait_group %0;\n" :: "n"(N) : "memory");
}

// ============================================================================
// GEMM1 (fp16 m16n8k16 + ldmatrix, cp.async 3-stage)
// ============================================================================
__global__ __launch_bounds__(256, 2) void gemm1_kernel(
    const float* __restrict__ b1,
    const float* __restrict__ a1w, const float* __restrict__ a1b,
    const float* __restrict__ a2w, const float* __restrict__ a2b)
{
    extern __shared__ __half smem_h[];
    __half (*As)[128][H_STRIDE] = (__half (*)[128][H_STRIDE])smem_h;
    __half (*Bs)[128][H_STRIDE] = (__half (*)[128][H_STRIDE])(smem_h + AH_ELEMS);

    const int lh  = blockIdx.x;
    const int lvl = lh >> 2;
    const int h   = lh & 3;
    const int Nl  = (lvl == 0) ? CN0 : (lvl == 1) ? CN1 : CN2;
    const int row0 = blockIdx.y * 128;
    if (row0 >= Nl) return;

    const __half* Xh = g_xh + ((lvl == 0) ? 0 : (lvl == 1) ? (size_t)CN0 * 256
                                                           : (size_t)(CN0 + CN1) * 256);
    const __half* Wh = g_w1h + (size_t)h * 256 * 128;
    // unified: out offset = r*ldo + h*128 + c
    __half* outh; int ldo;
    if (lvl == 0)      { outh = g_cath + (size_t)h * 128; ldo = 2048; }
    else if (lvl == 1) { outh = g_y1h  + (size_t)h * 128; ldo = 512; }
    else               { outh = g_y2h  + (size_t)h * 128; ldo = 512; }

    const int tid = threadIdx.x;
    const int lane = tid & 31;
    const int wid  = tid >> 5;
    const int wR = wid >> 2;
    const int wC = wid & 3;
    const int gid = lane >> 2;
    const int tg  = lane & 3;

    const int rA0 = tid >> 2, rA1 = (tid >> 2) + 64;
    const int kk  = (tid & 3) * 8;
    const int grA0 = min(row0 + rA0, Nl - 1);
    const int grA1 = min(row0 + rA1, Nl - 1);

    const int a_row = lane & 15;
    const int a_koff = (lane >> 4) << 3;
    const int b_row = lane & 7;
    const int b_koff = ((lane >> 3) & 1) << 3;
    const int b_ngrp = (lane >> 4) << 3;

    float acc[4][4][4];
#pragma unroll
    for (int mt = 0; mt < 4; mt++)
#pragma unroll
        for (int nt = 0; nt < 4; nt++)
#pragma unroll
            for (int r = 0; r < 4; r++) acc[mt][nt][r] = 0.f;

    const int NT = D_IN / 32;   // 8

#define G1_ISSUE(kt, s) do {                                               \
        int k0_ = (kt) * 32;                                               \
        cp_async16(&As[s][rA0][kk], Xh + (size_t)grA0 * 256 + k0_ + kk);   \
        cp_async16(&As[s][rA1][kk], Xh + (size_t)grA1 * 256 + k0_ + kk);   \
        cp_async16(&Bs[s][rA0][kk], Wh + (size_t)rA0 * 256 + k0_ + kk);    \
        cp_async16(&Bs[s][rA1][kk], Wh + (size_t)rA1 * 256 + k0_ + kk);    \
        cp_commit();                                                       \
    } while (0)

    G1_ISSUE(0, 0);
    G1_ISSUE(1, 1);
    cp_wait<1>();
    __syncthreads();

    for (int kt = 0; kt < NT; kt++) {
        if (kt + 2 < NT) G1_ISSUE(kt + 2, (kt + 2) % 3);
        const int s = kt % 3;
#pragma unroll
        for (int ks = 0; ks < 2; ks++) {
            const int kb = ks * 16;
            unsigned af[4][4], bf[4][2];
#pragma unroll
            for (int mt = 0; mt < 4; mt++) {
                int rb = wR * 64 + mt * 16;
                unsigned addr = smem_u32(&As[s][rb + a_row][kb + a_koff]);
                ldsm_x4(af[mt][0], af[mt][1], af[mt][2], af[mt][3], addr);
            }
#pragma unroll
            for (int p = 0; p < 2; p++) {
                int cb = wC * 32 + p * 16;
                unsigned addr = smem_u32(&Bs[s][cb + b_ngrp + b_row][kb + b_koff]);
                unsigned r0, r1, r2, r3;
                ldsm_x4(r0, r1, r2, r3, addr);
                bf[2 * p][0] = r0; bf[2 * p][1] = r1;
                bf[2 * p + 1][0] = r2; bf[2 * p + 1][1] = r3;
            }
#pragma unroll
            for (int mt = 0; mt < 4; mt++)
#pragma unroll
                for (int nt = 0; nt < 4; nt++)
                    mma_f16(acc[mt][nt], af[mt], bf[nt]);
        }
        if (kt + 1 < NT) {
            if (kt + 2 < NT) cp_wait<1>(); else cp_wait<0>();
            __syncthreads();
        }
    }
#undef G1_ISSUE

    // ---- epilogue: bias + relu + half store + fused dots (single sync) ----
    float* a2out = ((lvl == 0) ? g_a20 : (lvl == 1) ? g_a21 : g_a22) + h;
    const float a2bias = a2b[h];
    const float a1bias = a1b[h];

    float2 biasv[4], w2v[4], w1v[4];
#pragma unroll
    for (int nt = 0; nt < 4; nt++) {
        int c = wC * 32 + nt * 8 + 2 * tg;
        biasv[nt] = *(const float2*)(b1  + h * 128 + c);
        w2v[nt]   = *(const float2*)(a2w + h * 128 + c);
        w1v[nt]   = (lvl == 0) ? *(const float2*)(a1w + h * 128 + c) : make_float2(0.f, 0.f);
    }

    __shared__ float s_red[2][8][4][4][4];   // [wR][gid][wC][mt][{s2a,s2b,s1a,s1b}]
#pragma unroll
    for (int mt = 0; mt < 4; mt++) {
        int r0 = row0 + wR * 64 + mt * 16 + gid;
        int r1 = r0 + 8;
        float s2a = 0.f, s2b = 0.f, s1a = 0.f, s1b = 0.f;
#pragma unroll
        for (int nt = 0; nt < 4; nt++) {
            int c = wC * 32 + nt * 8 + 2 * tg;
            float v0 = fmaxf(acc[mt][nt][0] + biasv[nt].x, 0.f);
            float v1 = fmaxf(acc[mt][nt][1] + biasv[nt].y, 0.f);
            float v2 = fmaxf(acc[mt][nt][2] + biasv[nt].x, 0.f);
            float v3 = fmaxf(acc[mt][nt][3] + biasv[nt].y, 0.f);
            if (r0 < Nl) *(__half2*)(outh + (size_t)r0 * ldo + c) = __floats2half2_rn(v0, v1);
            if (r1 < Nl) *(__half2*)(outh + (size_t)r1 * ldo + c) = __floats2half2_rn(v2, v3);
            s2a += v0 * w2v[nt].x + v1 * w2v[nt].y;
            s2b += v2 * w2v[nt].x + v3 * w2v[nt].y;
            if (lvl == 0) {
                s1a += v0 * w1v[nt].x + v1 * w1v[nt].y;
                s1b += v2 * w1v[nt].x + v3 * w1v[nt].y;
            }
        }
        s2a += __shfl_xor_sync(0xffffffffu, s2a, 1); s2a += __shfl_xor_sync(0xffffffffu, s2a, 2);
        s2b += __shfl_xor_sync(0xffffffffu, s2b, 1); s2b += __shfl_xor_sync(0xffffffffu, s2b, 2);
        if (lvl == 0) {
            s1a += __shfl_xor_sync(0xffffffffu, s1a, 1); s1a += __shfl_xor_sync(0xffffffffu, s1a, 2);
            s1b += __shfl_xor_sync(0xffffffffu, s1b, 1); s1b += __shfl_xor_sync(0xffffffffu, s1b, 2);
        }
        if (tg == 0) {
            s_red[wR][gid][wC][mt][0] = s2a;
            s_red[wR][gid][wC][mt][1] = s2b;
            s_red[wR][gid][wC][mt][2] = s1a;
            s_red[wR][gid][wC][mt][3] = s1b;
        }
    }
    __syncthreads();
    if (tg == 0 && wC == 0) {
#pragma unroll
        for (int mt = 0; mt < 4; mt++) {
            int r0 = row0 + wR * 64 + mt * 16 + gid;
            int r1 = r0 + 8;
            float t2a = 0.f, t2b = 0.f, t1a = 0.f, t1b = 0.f;
#pragma unroll
            for (int q = 0; q < 4; q++) {
                t2a += s_red[wR][gid][q][mt][0];
                t2b += s_red[wR][gid][q][mt][1];
                t1a += s_red[wR][gid][q][mt][2];
                t1b += s_red[wR][gid][q][mt][3];
            }
            if (r0 < Nl) a2out[r0 * 4] = t2a + a2bias;
            if (r1 < Nl) a2out[r1 * 4] = t2b + a2bias;
            if (lvl == 0) {
                if (r0 < Nl) g_a1[r0 * 4 + h] = t1a + a1bias;
                if (r1 < Nl) g_a1[r1 * 4 + h] = t1b + a1bias;
            }
        }
    }
}

// ---------------- bucket build ----------------
__global__ void bucket_kernel(
    const int* __restrict__ rows0, const int* __restrict__ cols0,
    const int* __restrict__ rows1, const int* __restrict__ cols1,
    const int* __restrict__ rows2, const int* __restrict__ cols2)
{
    int i = blockIdx.x * blockDim.x + threadIdx.x;
    int lvl, e;
    const int *rows, *cols;
    if (i < NNZ0)                    { lvl = 0; e = i;               rows = rows0; cols = cols0; }
    else if (i < NNZ0 + NNZ1)        { lvl = 1; e = i - NNZ0;        rows = rows1; cols = cols1; }
    else if (i < NNZ0 + NNZ1 + NNZ2) { lvl = 2; e = i - NNZ0 - NNZ1; rows = rows2; cols = cols2; }
    else return;
    int r = rows[e], c = cols[e];
    int pos = atomicAdd(&g_cnt[lvl * CN0 + r], 1);
    if (pos < CAP) g_list[(size_t)(lvl * CN0 + r) * CAP + pos] = c;
}

// ---------------- attention gather: 1KB blocks, 2xLDG.128/edge, 8-edge unroll -
__global__ __launch_bounds__(256) void agg_kernel()
{
    __shared__ int    s_c[8][64];
    __shared__ float4 s_att[8][64];

    int w = (blockIdx.x * blockDim.x + threadIdx.x) >> 5;
    int wl = (threadIdx.x >> 5);
    int lane = threadIdx.x & 31;
    if (w >= 3 * CN0) return;
    int lvl = w / CN0;
    int row = w - lvl * CN0;

    int n = g_cnt[lvl * CN0 + row];
    if (n > CAP) n = CAP;

    float4 a1v = *(const float4*)(g_a1 + row * 4);

    const float* a2p; const __half* yb; int ns;
    if (lvl == 0)      { a2p = g_a20; yb = g_cath; ns = 2048; }  // seg0 = xi0 at block start
    else if (lvl == 1) { a2p = g_a21; yb = g_y1h;  ns = 512; }
    else               { a2p = g_a22; yb = g_y2h;  ns = 512; }

    const int* lst = g_list + (size_t)(lvl * CN0 + row) * CAP;
    const int hsel = lane >> 4;   // 0: even head of group, 1: odd head

    float acc0[8], acc1[8];       // group0 (heads 0/1), group1 (heads 2/3)
#pragma unroll
    for (int j = 0; j < 8; j++) { acc0[j] = 0.f; acc1[j] = 0.f; }

    for (int j0 = 0; j0 < n; j0 += 64) {
        int m = n - j0; if (m > 64) m = 64;
        __syncwarp();
        if (lane < m) {
            int c = lst[j0 + lane];
            float4 a2v = *(const float4*)(a2p + c * 4);
            float4 t;
            t.x = 1.f / (1.f + __expf(-(a1v.x + a2v.x)));
            t.y = 1.f / (1.f + __expf(-(a1v.y + a2v.y)));
            t.z = 1.f / (1.f + __expf(-(a1v.z + a2v.z)));
            t.w = 1.f / (1.f + __expf(-(a1v.w + a2v.w)));
            s_c[wl][lane] = c;
            s_att[wl][lane] = t;
        }
        if (lane + 32 < m) {
            int c = lst[j0 + lane + 32];
            float4 a2v = *(const float4*)(a2p + c * 4);
            float4 t;
            t.x = 1.f / (1.f + __expf(-(a1v.x + a2v.x)));
            t.y = 1.f / (1.f + __expf(-(a1v.y + a2v.y)));
            t.z = 1.f / (1.f + __expf(-(a1v.z + a2v.z)));
            t.w = 1.f / (1.f + __expf(-(a1v.w + a2v.w)));
            s_c[wl][lane + 32] = c;
            s_att[wl][lane + 32] = t;
        }
        __syncwarp();
        int i = 0;
        for (; i + 8 <= m; i += 8) {
            const uint4* pb[8];
#pragma unroll
            for (int u = 0; u < 8; u++)
                pb[u] = (const uint4*)(yb + (size_t)s_c[wl][i + u] * ns);
            uint4 v0[8], v1[8];
#pragma unroll
            for (int u = 0; u < 8; u++) {
                v0[u] = pb[u][lane];        // heads 0/1, 512B
                v1[u] = pb[u][lane + 32];   // heads 2/3
            }
#pragma unroll
            for (int u = 0; u < 8; u++) {
                float4 t = s_att[wl][i + u];
                float a0 = hsel ? t.y : t.x;
                float a1 = hsel ? t.w : t.z;
                const unsigned* q0 = (const unsigned*)&v0[u];
                const unsigned* q1 = (const unsigned*)&v1[u];
#pragma unroll
                for (int p = 0; p < 4; p++) {
                    float2 f0 = __half22float2(*(const __half2*)&q0[p]);
                    float2 f1 = __half22float2(*(const __half2*)&q1[p]);
                    acc0[2 * p]     = fmaf(a0, f0.x, acc0[2 * p]);
                    acc0[2 * p + 1] = fmaf(a0, f0.y, acc0[2 * p + 1]);
                    acc1[2 * p]     = fmaf(a1, f1.x, acc1[2 * p]);
                    acc1[2 * p + 1] = fmaf(a1, f1.y, acc1[2 * p + 1]);
                }
            }
        }
        for (; i < m; i++) {
            const uint4* pb = (const uint4*)(yb + (size_t)s_c[wl][i] * ns);
            uint4 v0 = pb[lane];
            uint4 v1 = pb[lane + 32];
            float4 t = s_att[wl][i];
            float a0 = hsel ? t.y : t.x;
            float a1 = hsel ? t.w : t.z;
            const unsigned* q0 = (const unsigned*)&v0;
            const unsigned* q1 = (const unsigned*)&v1;
#pragma unroll
            for (int p = 0; p < 4; p++) {
                float2 f0 = __half22float2(*(const __half2*)&q0[p]);
                float2 f1 = __half22float2(*(const __half2*)&q1[p]);
                acc0[2 * p]     = fmaf(a0, f0.x, acc0[2 * p]);
                acc0[2 * p + 1] = fmaf(a0, f0.y, acc0[2 * p + 1]);
                acc1[2 * p]     = fmaf(a1, f1.x, acc1[2 * p]);
                acc1[2 * p + 1] = fmaf(a1, f1.y, acc1[2 * p + 1]);
            }
        }
    }
    // write agg seg (lvl+1): 1KB block, group0 at +0, group1 at +512B
    {
        __half* outb = g_cath + (size_t)row * 2048 + (size_t)(lvl + 1) * 512;
        uint4 o0, o1;
        unsigned* w0 = (unsigned*)&o0;
        unsigned* w1 = (unsigned*)&o1;
#pragma unroll
        for (int p = 0; p < 4; p++) {
            __half2 h0 = __floats2half2_rn(acc0[2 * p], acc0[2 * p + 1]);
            __half2 h1 = __floats2half2_rn(acc1[2 * p], acc1[2 * p + 1]);
            w0[p] = *(unsigned*)&h0;
            w1[p] = *(unsigned*)&h1;
        }
        ((uint4*)outb)[lane]      = o0;
        ((uint4*)outb)[lane + 32] = o1;
    }
}

// ============================================================================
// GEMM2 (fp16 m16n8k16 + ldmatrix): out = mean_h(cat_h @ Wagg_h + bagg_h)
// A address: [row][seg][h][128]; k = seg*128+off
// ============================================================================
__global__ __launch_bounds__(256, 2) void gemm2_kernel(
    const float* __restrict__ bagg, float* __restrict__ out)
{
    extern __shared__ __half smem_h[];
    __half (*As)[128][H_STRIDE] = (__half (*)[128][H_STRIDE])smem_h;
    __half (*Bs)[128][H_STRIDE] = (__half (*)[128][H_STRIDE])(smem_h + AH_ELEMS);

    const int row0 = blockIdx.x * 128;

    const int tid = threadIdx.x;
    const int lane = tid & 31;
    const int wid  = tid >> 5;
    const int wR = wid >> 2;
    const int wC = wid & 3;
    const int gid = lane >> 2;
    const int tg  = lane & 3;

    const int rA0 = tid >> 2, rA1 = (tid >> 2) + 64;
    const int kk  = (tid & 3) * 8;
    const int grA0 = min(row0 + rA0, CN0 - 1);
    const int grA1 = min(row0 + rA1, CN0 - 1);

    const int a_row = lane & 15;
    const int a_koff = (lane >> 4) << 3;
    const int b_row = lane & 7;
    const int b_koff = ((lane >> 3) & 1) << 3;
    const int b_ngrp = (lane >> 4) << 3;

    float acc[4][4][4];
#pragma unroll
    for (int mt = 0; mt < 4; mt++)
#pragma unroll
        for (int nt = 0; nt < 4; nt++)
#pragma unroll
            for (int r = 0; r < 4; r++) acc[mt][nt][r] = 0.f;

    const int NT = 64;

#define G2_ISSUE(kt, s) do {                                                          \
        int t_ = (kt);                                                                \
        int h_ = t_ >> 4, k0_ = (t_ & 15) * 32;                                       \
        int kA_ = k0_ + kk;                                                           \
        int segA_ = kA_ >> 7, offA_ = kA_ & 127;                                      \
        size_t aoff_ = (size_t)segA_ * 512 + (size_t)h_ * 128 + offA_;                \
        const __half* W_ = g_waggh + (size_t)h_ * 512 * 128;                          \
        cp_async16(&As[s][rA0][kk], g_cath + (size_t)grA0 * 2048 + aoff_);            \
        cp_async16(&As[s][rA1][kk], g_cath + (size_t)grA1 * 2048 + aoff_);            \
        cp_async16(&Bs[s][rA0][kk], W_ + (size_t)rA0 * 512 + k0_ + kk);               \
        cp_async16(&Bs[s][rA1][kk], W_ + (size_t)rA1 * 512 + k0_ + kk);               \
        cp_commit();                                                                  \
    } while (0)

    G2_ISSUE(0, 0);
    G2_ISSUE(1, 1);
    cp_wait<1>();
    __syncthreads();

    for (int kt = 0; kt < NT; kt++) {
        if (kt + 2 < NT) G2_ISSUE(kt + 2, (kt + 2) % 3);
        const int s = kt % 3;
#pragma unroll
        for (int ks = 0; ks < 2; ks++) {
            const int kb = ks * 16;
            unsigned af[4][4], bf[4][2];
#pragma unroll
            for (int mt = 0; mt < 4; mt++) {
                int rb = wR * 64 + mt * 16;
                unsigned addr = smem_u32(&As[s][rb + a_row][kb + a_koff]);
                ldsm_x4(af[mt][0], af[mt][1], af[mt][2], af[mt][3], addr);
            }
#pragma unroll
            for (int p = 0; p < 2; p++) {
                int cb = wC * 32 + p * 16;
                unsigned addr = smem_u32(&Bs[s][cb + b_ngrp + b_row][kb + b_koff]);
                unsigned r0, r1, r2, r3;
                ldsm_x4(r0, r1, r2, r3, addr);
                bf[2 * p][0] = r0; bf[2 * p][1] = r1;
                bf[2 * p + 1][0] = r2; bf[2 * p + 1][1] = r3;
            }
#pragma unroll
            for (int mt = 0; mt < 4; mt++)
#pragma unroll
                for (int nt = 0; nt < 4; nt++)
                    mma_f16(acc[mt][nt], af[mt], bf[nt]);
        }
        if (kt + 1 < NT) {
            if (kt + 2 < NT) cp_wait<1>(); else cp_wait<0>();
            __syncthreads();
        }
    }
#undef G2_ISSUE

    float2 bsum[4];
#pragma unroll
    for (int nt = 0; nt < 4; nt++) {
        int c = wC * 32 + nt * 8 + 2 * tg;
        float2 s = make_float2(0.f, 0.f);
#pragma unroll
        for (int h = 0; h < HEADS; h++) {
            float2 bg = *(const float2*)(bagg + h * 128 + c);
            s.x += bg.x; s.y += bg.y;
        }
        bsum[nt] = s;
    }
#pragma unroll
    for (int mt = 0; mt < 4; mt++) {
        int r0 = row0 + wR * 64 + mt * 16 + gid;
        int r1 = r0 + 8;
#pragma unroll
        for (int nt = 0; nt < 4; nt++) {
            int c = wC * 32 + nt * 8 + 2 * tg;
            if (r0 < CN0) {
                float2 v;
                v.x = (acc[mt][nt][0] + bsum[nt].x) * 0.25f;
                v.y = (acc[mt][nt][1] + bsum[nt].y) * 0.25f;
                *(float2*)(out + (size_t)r0 * 128 + c) = v;
            }
            if (r1 < CN0) {
                float2 v;
                v.x = (acc[mt][nt][2] + bsum[nt].x) * 0.25f;
                v.y = (acc[mt][nt][3] + bsum[nt].y) * 0.25f;
                *(float2*)(out + (size_t)r1 * 128 + c) = v;
            }
        }
    }
}

// ---------------- launch ----------------
extern "C" void kernel_launch(void* const* d_in, const int* in_sizes, int n_in,
                              void* d_out, int out_size)
{
    const float* x0    = (const float*)d_in[0];
    const float* x1    = (const float*)d_in[1];
    const float* x2    = (const float*)d_in[2];
    const int*   rows0 = (const int*)d_in[3];
    const int*   cols0 = (const int*)d_in[4];
    const int*   rows1 = (const int*)d_in[5];
    const int*   cols1 = (const int*)d_in[6];
    const int*   rows2 = (const int*)d_in[7];
    const int*   cols2 = (const int*)d_in[8];
    const float* W1    = (const float*)d_in[9];
    const float* b1    = (const float*)d_in[10];
    const float* a1w   = (const float*)d_in[11];
    const float* a1b   = (const float*)d_in[12];
    const float* a2w   = (const float*)d_in[13];
    const float* a2b   = (const float*)d_in[14];
    const float* Wagg  = (const float*)d_in[15];
    const float* bagg  = (const float*)d_in[16];
    float* out = (float*)d_out;

    cudaFuncSetAttribute(gemm1_kernel, cudaFuncAttributeMaxDynamicSharedMemorySize, GEMM_SMEM_BYTES);
    cudaFuncSetAttribute(gemm2_kernel, cudaFuncAttributeMaxDynamicSharedMemorySize, GEMM_SMEM_BYTES);

    cvt_w_kernel<<<(HEADS * 256 * 128 + HEADS * 512 * 128 + 255) / 256, 256>>>(W1, Wagg);  // + zero cnt
    bucket_kernel<<<(NNZ0 + NNZ1 + NNZ2 + 255) / 256, 256>>>(
        rows0, cols0, rows1, cols1, rows2, cols2);
    cvt_x_kernel<<<(int)((NXH / 4 + 255) / 256), 256>>>(x0, x1, x2);

    {
        dim3 grid(12, (CN1 + 127) / 128);
        gemm1_kernel<<<grid, 256, GEMM_SMEM_BYTES>>>(b1, a1w, a1b, a2w, a2b);
    }
    {
        int warps = 3 * CN0;
        agg_kernel<<<(warps * 32 + 255) / 256, 256>>>();
    }
    gemm2_kernel<<<(CN0 + 127) / 128, 256, GEMM_SMEM_BYTES>>>(bagg, out);
}